// round 2
// baseline (speedup 1.0000x reference)
#include <cuda_runtime.h>
#include <math.h>
#include <stdint.h>

// ---------------- problem constants ----------------
static constexpr int Bq = 2;
static constexpr int Tq = 1024;
static constexpr int Cq = 256;
static constexpr int Fq = 1024;
static constexpr int Eq = 32;
static constexpr int Vq = 50257;
static constexpr int Hq = 8;
static constexpr int Dq = 32;      // Cq / Hq
static constexpr int Nq = Bq * Tq; // 2048 tokens

// ---------------- device scratch (no allocations allowed) ----------------
__device__ float g_hs[Nq * Cq];
__device__ float g_x[Nq * Cq];
__device__ float g_q[Nq * Cq];
__device__ float g_k[Nq * Cq];
__device__ float g_v[Nq * Cq];
__device__ float g_ao[Nq * Cq];
__device__ float g_xt[Nq * Cq];
__device__ float g_sn[Cq * Eq];
__device__ float g_logits[Nq * Eq];
__device__ float g_rw[Nq * Eq];
// fallback outputs in case harness out layout differs
__device__ float g_feo[(size_t)Nq * Eq * Cq];
__device__ float g_pre[Nq * Eq];
__device__ float g_am[Nq * Eq];

// ---------------- embedding ----------------
__global__ void k_embed(const int* __restrict__ ids, const float* __restrict__ emb,
                        float* __restrict__ hs) {
    int t = blockIdx.x, c = threadIdx.x;
    hs[(size_t)t * Cq + c] = emb[(size_t)ids[t] * Cq + c];
}

// ---------------- layernorm (row = block, C=256 threads) ----------------
__global__ void k_layernorm(const float* __restrict__ in, float* __restrict__ out,
                            const float* __restrict__ w, const float* __restrict__ b) {
    int t = blockIdx.x, c = threadIdx.x;
    float x = in[(size_t)t * Cq + c];
    __shared__ float red[8];
    float s = x;
#pragma unroll
    for (int o = 16; o; o >>= 1) s += __shfl_xor_sync(0xffffffffu, s, o);
    if ((c & 31) == 0) red[c >> 5] = s;
    __syncthreads();
    float mu = 0.f;
#pragma unroll
    for (int i = 0; i < 8; i++) mu += red[i];
    mu *= (1.f / Cq);
    float d = x - mu;
    float s2 = d * d;
#pragma unroll
    for (int o = 16; o; o >>= 1) s2 += __shfl_xor_sync(0xffffffffu, s2, o);
    __syncthreads();
    if ((c & 31) == 0) red[c >> 5] = s2;
    __syncthreads();
    float var = 0.f;
#pragma unroll
    for (int i = 0; i < 8; i++) var += red[i];
    var *= (1.f / Cq);
    out[(size_t)t * Cq + c] = d * rsqrtf(var + 1e-5f) * w[c] + b[c];
}

// ---------------- generic SGEMM: C[M,N] = A[M,K] @ B[K,N] (+C if addC) ----------------
// 64x64 tile, BK=16, 256 threads, 4x4 register blocking.
__global__ void __launch_bounds__(256) k_sgemm(const float* __restrict__ A,
                                               const float* __restrict__ B,
                                               float* __restrict__ Cc,
                                               int M, int Nn, int K, int addC) {
    __shared__ float As[16 * 68]; // [kk][row], padded to 68 to avoid bank conflicts
    __shared__ float Bs[16 * 64]; // [kk][col]
    int tid = threadIdx.x;
    int tx = tid & 15, ty = tid >> 4;
    int colbase = blockIdx.x * 64, rowbase = blockIdx.y * 64;
    float acc[16];
#pragma unroll
    for (int i = 0; i < 16; i++) acc[i] = 0.f;

    for (int kc = 0; kc < K; kc += 16) {
#pragma unroll
        for (int i = 0; i < 4; i++) {
            int lin = tid + i * 256;
            int r = lin >> 4, kk = lin & 15;
            int grow = rowbase + r;
            As[kk * 68 + r] = (grow < M) ? A[(size_t)grow * K + kc + kk] : 0.f;
            int kk2 = lin >> 6, cc = lin & 63;
            int gcol = colbase + cc;
            Bs[kk2 * 64 + cc] = (gcol < Nn) ? B[(size_t)(kc + kk2) * Nn + gcol] : 0.f;
        }
        __syncthreads();
#pragma unroll
        for (int kk = 0; kk < 16; kk++) {
            float4 a = *(const float4*)&As[kk * 68 + ty * 4];
            float4 b = *(const float4*)&Bs[kk * 64 + tx * 4];
            acc[0]  += a.x * b.x; acc[1]  += a.x * b.y; acc[2]  += a.x * b.z; acc[3]  += a.x * b.w;
            acc[4]  += a.y * b.x; acc[5]  += a.y * b.y; acc[6]  += a.y * b.z; acc[7]  += a.y * b.w;
            acc[8]  += a.z * b.x; acc[9]  += a.z * b.y; acc[10] += a.z * b.z; acc[11] += a.z * b.w;
            acc[12] += a.w * b.x; acc[13] += a.w * b.y; acc[14] += a.w * b.z; acc[15] += a.w * b.w;
        }
        __syncthreads();
    }
#pragma unroll
    for (int i = 0; i < 4; i++) {
        int r = rowbase + ty * 4 + i;
        if (r >= M) continue;
#pragma unroll
        for (int j = 0; j < 4; j++) {
            int cl = colbase + tx * 4 + j;
            if (cl < Nn) {
                float v = acc[i * 4 + j];
                if (addC) v += Cc[(size_t)r * Nn + cl];
                Cc[(size_t)r * Nn + cl] = v;
            }
        }
    }
}

// ---------------- causal attention, flash-style, 1 thread = 1 query ----------------
__global__ void k_attn(const float* __restrict__ q, const float* __restrict__ k,
                       const float* __restrict__ v, float* __restrict__ o) {
    int b = blockIdx.z, h = blockIdx.y;
    int t0 = blockIdx.x * 64;
    int qi = t0 + threadIdx.x;
    const float scale = 0.17677669529663687f; // 1/sqrt(32)
    float qr[Dq];
    const float* qp = q + ((size_t)(b * Tq + qi)) * Cq + h * Dq;
#pragma unroll
    for (int d = 0; d < Dq; d++) qr[d] = qp[d] * scale;
    float acc[Dq];
#pragma unroll
    for (int d = 0; d < Dq; d++) acc[d] = 0.f;
    float m = -INFINITY, l = 0.f;
    __shared__ float Ks[64 * Dq], Vs[64 * Dq];

    for (int kt = 0; kt < t0 + 64; kt += 64) {
        for (int i = threadIdx.x; i < 64 * Dq; i += 64) {
            int r = i >> 5, d = i & 31;
            size_t gi = ((size_t)(b * Tq + kt + r)) * Cq + h * Dq + d;
            Ks[i] = k[gi];
            Vs[i] = v[gi];
        }
        __syncthreads();
        int jmax = qi - kt + 1;
        if (jmax > 64) jmax = 64;
        for (int j = 0; j < jmax; j++) {
            float s = 0.f;
#pragma unroll
            for (int d = 0; d < Dq; d++) s += qr[d] * Ks[j * Dq + d];
            float nm = fmaxf(m, s);
            float corr = expf(m - nm); // m=-inf on first key -> 0
            float p = expf(s - nm);
            l = l * corr + p;
#pragma unroll
            for (int d = 0; d < Dq; d++) acc[d] = acc[d] * corr + p * Vs[j * Dq + d];
            m = nm;
        }
        __syncthreads();
    }
    float inv = 1.f / l;
    float* op = o + ((size_t)(b * Tq + qi)) * Cq + h * Dq;
#pragma unroll
    for (int d = 0; d < Dq; d++) op[d] = acc[d] * inv;
}

// ---------------- normalize sim_matrix columns ----------------
__global__ void k_simnorm(const float* __restrict__ sim, float* __restrict__ sn) {
    __shared__ float ps[8][32];
    __shared__ float inv[32];
    int tid = threadIdx.x;
    int e = tid & 31, part = tid >> 5;
    float s = 0.f;
    for (int c = part * 32; c < part * 32 + 32; c++) {
        float vv = sim[(size_t)c * Eq + e];
        s += vv * vv;
    }
    ps[part][e] = s;
    __syncthreads();
    if (tid < 32) {
        float tot = 0.f;
#pragma unroll
        for (int p = 0; p < 8; p++) tot += ps[p][tid];
        inv[tid] = 1.f / fmaxf(sqrtf(tot), 1e-12f);
    }
    __syncthreads();
    for (int i = tid; i < Cq * Eq; i += 256) sn[i] = sim[i] * inv[i & 31];
}

// ---------------- gate logits: cosine sims (1 warp per token) ----------------
__global__ void k_gate_logits(const float* __restrict__ xt, const float* __restrict__ sn,
                              float* __restrict__ logits) {
    __shared__ float xs[8 * Cq];
    int tid = threadIdx.x;
    int t0 = blockIdx.x * 8;
    for (int i = tid; i < 8 * Cq; i += 256) xs[i] = xt[(size_t)t0 * Cq + i];
    __syncthreads();
    int w = tid >> 5, lane = tid & 31;
    int t = t0 + w;
    float s = 0.f;
    for (int c = lane; c < Cq; c += 32) {
        float vv = xs[w * Cq + c];
        s += vv * vv;
    }
#pragma unroll
    for (int o = 16; o; o >>= 1) s += __shfl_xor_sync(0xffffffffu, s, o);
    float inv = 1.f / fmaxf(sqrtf(s), 1e-12f);
    float acc = 0.f;
    for (int c = 0; c < Cq; c++) acc += xs[w * Cq + c] * sn[c * Eq + lane];
    logits[(size_t)t * Eq + lane] = acc * inv;
}

// ---------------- gate decision + routing softmax (1 warp per token) ----------------
__global__ void k_gate(const float* __restrict__ logits, const float* __restrict__ gates,
                       float* __restrict__ pre_o, float* __restrict__ am_o,
                       float* __restrict__ rw) {
    int w = threadIdx.x >> 5, lane = threadIdx.x & 31;
    int t = blockIdx.x * 8 + w;
    float lg = logits[(size_t)t * Eq + lane];
    float pre = lg - 1.f / (1.f + expf(-gates[lane]));
    float gated = fmaxf(pre, 0.f);
    unsigned act = __ballot_sync(0xffffffffu, pre > 0.f);
    float am;
    if (act == 0u) {
        // fallback: top-16 of raw logits, stable tie-break by index (jax.lax.top_k)
        int rank = 0;
#pragma unroll
        for (int j = 0; j < 32; j++) {
            float lj = __shfl_sync(0xffffffffu, lg, j);
            rank += (lj > lg) || (lj == lg && j < lane);
        }
        am = (rank < 16) ? 1.f : 0.f;
    } else {
        am = (pre > 0.f) ? 1.f : 0.f;
    }
    float g2 = (am > 0.f) ? gated : -INFINITY;
    float mx = g2;
#pragma unroll
    for (int o = 16; o; o >>= 1) mx = fmaxf(mx, __shfl_xor_sync(0xffffffffu, mx, o));
    float p = (am > 0.f) ? expf(gated - mx) : 0.f;
    float sum = p;
#pragma unroll
    for (int o = 16; o; o >>= 1) sum += __shfl_xor_sync(0xffffffffu, sum, o);
    rw[(size_t)t * Eq + lane] = p / sum;
    pre_o[(size_t)t * Eq + lane] = pre;
    am_o[(size_t)t * Eq + lane] = am;
}

// ---------------- fused MoE FFN: feo[t,e,:] = amask * (gelu(x@W1[e]) @ W2[e]) ----------------
static constexpr int TM = 32;  // tokens per block
static constexpr int FC = 32;  // f-chunk
static constexpr int MOE_SMEM_FLOATS = TM * Cq + Cq * FC + FC * Cq + TM * (FC + 1);
static constexpr int MOE_SMEM_BYTES = MOE_SMEM_FLOATS * 4;

__device__ __forceinline__ float gelu_exact(float x) {
    return 0.5f * x * (1.0f + erff(x * 0.70710678118654752f));
}

__global__ void __launch_bounds__(256) k_moe(const float* __restrict__ xt,
                                             const float* __restrict__ w1,
                                             const float* __restrict__ w2,
                                             const float* __restrict__ amask,
                                             float* __restrict__ feo) {
    extern __shared__ float smem[];
    float* Xs  = smem;                  // [TM][Cq]
    float* W1s = Xs + TM * Cq;          // [Cq][FC]
    float* W2s = W1s + Cq * FC;         // [FC][Cq]
    float* Hs  = W2s + FC * Cq;         // [TM][FC+1]

    int e = blockIdx.y;
    int t0 = blockIdx.x * TM;
    int tid = threadIdx.x;
    int ty = tid >> 5, tx = tid & 31;   // warp ty owns rows ty*4..+3; tx = lane

    for (int i = tid; i < TM * Cq; i += 256) {
        int r = i >> 8, c = i & 255;
        Xs[r * Cq + c] = xt[(size_t)(t0 + r) * Cq + c];
    }

    float acc[4][8];
#pragma unroll
    for (int i = 0; i < 4; i++)
#pragma unroll
        for (int j = 0; j < 8; j++) acc[i][j] = 0.f;

    const float* w1e = w1 + (size_t)e * Cq * Fq;
    const float* w2e = w2 + (size_t)e * Fq * Cq;

    for (int f0 = 0; f0 < Fq; f0 += FC) {
        __syncthreads();
        for (int i = tid; i < Cq * FC; i += 256) {
            int c = i >> 5, f = i & 31;
            W1s[c * FC + f] = w1e[(size_t)c * Fq + f0 + f];
        }
        for (int i = tid; i < FC * Cq; i += 256) {
            int f = i >> 8, c = i & 255;
            W2s[f * Cq + c] = w2e[(size_t)(f0 + f) * Cq + c];
        }
        __syncthreads();
        // up-proj: warp ty computes h[rows ty*4..+3][f=tx]
        {
            int rb = ty * 4;
            float h0 = 0.f, h1 = 0.f, h2 = 0.f, h3 = 0.f;
#pragma unroll 4
            for (int c = 0; c < Cq; c++) {
                float wv = W1s[c * FC + tx];
                h0 += Xs[(rb + 0) * Cq + c] * wv;
                h1 += Xs[(rb + 1) * Cq + c] * wv;
                h2 += Xs[(rb + 2) * Cq + c] * wv;
                h3 += Xs[(rb + 3) * Cq + c] * wv;
            }
            Hs[(rb + 0) * (FC + 1) + tx] = gelu_exact(h0);
            Hs[(rb + 1) * (FC + 1) + tx] = gelu_exact(h1);
            Hs[(rb + 2) * (FC + 1) + tx] = gelu_exact(h2);
            Hs[(rb + 3) * (FC + 1) + tx] = gelu_exact(h3);
        }
        __syncthreads();
        // down-proj: thread (ty,tx) owns rows ty*4..+3, cols tx*8..+7
#pragma unroll 4
        for (int f = 0; f < FC; f++) {
            float a0 = Hs[(ty * 4 + 0) * (FC + 1) + f];
            float a1 = Hs[(ty * 4 + 1) * (FC + 1) + f];
            float a2 = Hs[(ty * 4 + 2) * (FC + 1) + f];
            float a3 = Hs[(ty * 4 + 3) * (FC + 1) + f];
            float4 b0 = *(const float4*)&W2s[f * Cq + tx * 8];
            float4 b1 = *(const float4*)&W2s[f * Cq + tx * 8 + 4];
            acc[0][0] += a0 * b0.x; acc[0][1] += a0 * b0.y; acc[0][2] += a0 * b0.z; acc[0][3] += a0 * b0.w;
            acc[0][4] += a0 * b1.x; acc[0][5] += a0 * b1.y; acc[0][6] += a0 * b1.z; acc[0][7] += a0 * b1.w;
            acc[1][0] += a1 * b0.x; acc[1][1] += a1 * b0.y; acc[1][2] += a1 * b0.z; acc[1][3] += a1 * b0.w;
            acc[1][4] += a1 * b1.x; acc[1][5] += a1 * b1.y; acc[1][6] += a1 * b1.z; acc[1][7] += a1 * b1.w;
            acc[2][0] += a2 * b0.x; acc[2][1] += a2 * b0.y; acc[2][2] += a2 * b0.z; acc[2][3] += a2 * b0.w;
            acc[2][4] += a2 * b1.x; acc[2][5] += a2 * b1.y; acc[2][6] += a2 * b1.z; acc[2][7] += a2 * b1.w;
            acc[3][0] += a3 * b0.x; acc[3][1] += a3 * b0.y; acc[3][2] += a3 * b0.z; acc[3][3] += a3 * b0.w;
            acc[3][4] += a3 * b1.x; acc[3][5] += a3 * b1.y; acc[3][6] += a3 * b1.z; acc[3][7] += a3 * b1.w;
        }
    }
    // masked store: full_expert_outputs = amask * eo (amask is exactly 0.0/1.0)
#pragma unroll
    for (int i = 0; i < 4; i++) {
        int row = t0 + ty * 4 + i;
        float mm = amask[(size_t)row * Eq + e];
        float4 o0 = make_float4(acc[i][0] * mm, acc[i][1] * mm, acc[i][2] * mm, acc[i][3] * mm);
        float4 o1 = make_float4(acc[i][4] * mm, acc[i][5] * mm, acc[i][6] * mm, acc[i][7] * mm);
        float* dst = feo + ((size_t)row * Eq + e) * Cq + tx * 8;
        *(float4*)(dst) = o0;
        *(float4*)(dst + 4) = o1;
    }
}

// ---------------- combine: hs += sum_e rw[t,e] * feo[t,e,:] ----------------
__global__ void k_combine(const float* __restrict__ rw, const float* __restrict__ feo,
                          float* __restrict__ hs) {
    int t = blockIdx.x, c = threadIdx.x;
    float s = hs[(size_t)t * Cq + c];
#pragma unroll
    for (int e = 0; e < Eq; e++)
        s += rw[(size_t)t * Eq + e] * feo[((size_t)t * Eq + e) * Cq + c];
    hs[(size_t)t * Cq + c] = s;
}

// ---------------- host ----------------
extern "C" void kernel_launch(void* const* d_in, const int* in_sizes, int n_in,
                              void* d_out, int out_size) {
    const int*   ids   = (const int*)d_in[0];
    const float* emb   = (const float*)d_in[1];
    const float* wq    = (const float*)d_in[2];
    const float* wk    = (const float*)d_in[3];
    const float* wv    = (const float*)d_in[4];
    const float* wo    = (const float*)d_in[5];
    const float* ln1w  = (const float*)d_in[6];
    const float* ln1b  = (const float*)d_in[7];
    const float* ln2w  = (const float*)d_in[8];
    const float* ln2b  = (const float*)d_in[9];
    const float* sim   = (const float*)d_in[10];
    const float* gates = (const float*)d_in[11];
    const float* w1    = (const float*)d_in[12];
    const float* w2    = (const float*)d_in[13];
    const float* lmh   = (const float*)d_in[14];

    float *hs, *x, *q, *k, *v, *ao, *xt, *sn, *logits, *rw, *feo_s, *pre_s, *am_s;
    cudaGetSymbolAddress((void**)&hs, g_hs);
    cudaGetSymbolAddress((void**)&x, g_x);
    cudaGetSymbolAddress((void**)&q, g_q);
    cudaGetSymbolAddress((void**)&k, g_k);
    cudaGetSymbolAddress((void**)&v, g_v);
    cudaGetSymbolAddress((void**)&ao, g_ao);
    cudaGetSymbolAddress((void**)&xt, g_xt);
    cudaGetSymbolAddress((void**)&sn, g_sn);
    cudaGetSymbolAddress((void**)&logits, g_logits);
    cudaGetSymbolAddress((void**)&rw, g_rw);
    cudaGetSymbolAddress((void**)&feo_s, g_feo);
    cudaGetSymbolAddress((void**)&pre_s, g_pre);
    cudaGetSymbolAddress((void**)&am_s, g_am);

    float* out = (float*)d_out;
    const size_t NV  = (size_t)Nq * Vq;
    const size_t FEO = (size_t)Nq * Eq * Cq;
    const size_t NE  = (size_t)Nq * Eq;
    float *feo, *pre_o, *am_o;
    if ((size_t)out_size >= NV + FEO + 2 * NE) {
        feo = out + NV;
        pre_o = out + NV + FEO;
        am_o = pre_o + NE;
    } else {
        feo = feo_s; pre_o = pre_s; am_o = am_s;
    }

    k_embed<<<Nq, Cq>>>(ids, emb, hs);
    k_layernorm<<<Nq, Cq>>>(hs, x, ln1w, ln1b);

    dim3 gP(Cq / 64, Nq / 64);
    k_sgemm<<<gP, 256>>>(x, wq, q, Nq, Cq, Cq, 0);
    k_sgemm<<<gP, 256>>>(x, wk, k, Nq, Cq, Cq, 0);
    k_sgemm<<<gP, 256>>>(x, wv, v, Nq, Cq, Cq, 0);

    k_attn<<<dim3(Tq / 64, Hq, Bq), 64>>>(q, k, v, ao);
    k_sgemm<<<gP, 256>>>(ao, wo, hs, Nq, Cq, Cq, 1); // residual add

    k_layernorm<<<Nq, Cq>>>(hs, xt, ln2w, ln2b);
    k_simnorm<<<1, 256>>>(sim, sn);
    k_gate_logits<<<Nq / 8, 256>>>(xt, sn, logits);
    k_gate<<<Nq / 8, 256>>>(logits, gates, pre_o, am_o, rw);

    cudaFuncSetAttribute(k_moe, cudaFuncAttributeMaxDynamicSharedMemorySize, MOE_SMEM_BYTES);
    k_moe<<<dim3(Nq / TM, Eq), 256, MOE_SMEM_BYTES>>>(xt, w1, w2, am_o, feo);

    k_combine<<<Nq, Cq>>>(rw, feo, hs);

    k_sgemm<<<dim3((Vq + 63) / 64, Nq / 64), 256>>>(hs, lmh, out, Nq, Vq, Cq, 0);
}

// round 4
// speedup vs baseline: 1.1938x; 1.1938x over previous
#include <cuda_runtime.h>
#include <cuda_bf16.h>
#include <math.h>
#include <stdint.h>

// ---------------- problem constants ----------------
static constexpr int Bq = 2;
static constexpr int Tq = 1024;
static constexpr int Cq = 256;
static constexpr int Fq = 1024;
static constexpr int Eq = 32;
static constexpr int Vq = 50257;
static constexpr int Hq = 8;
static constexpr int Dq = 32;      // Cq / Hq
static constexpr int Nq = Bq * Tq; // 2048 tokens
static constexpr int VP = 50304;   // Vq padded to 128 (393 tiles)

// ---------------- device scratch (no allocations allowed) ----------------
__device__ float g_hs[Nq * Cq];
__device__ float g_x[Nq * Cq];
__device__ float g_q[Nq * Cq];
__device__ float g_k[Nq * Cq];
__device__ float g_v[Nq * Cq];
__device__ float g_ao[Nq * Cq];
__device__ float g_xt[Nq * Cq];
__device__ float g_sn[Cq * Eq];
__device__ float g_logits[Nq * Eq];
__device__ float g_rw[Nq * Eq];
__device__ float g_feo[(size_t)Nq * Eq * Cq];
__device__ float g_pre[Nq * Eq];
__device__ float g_am[Nq * Eq];
// bf16 hi/lo splits for the lm_head HMMA GEMM
__device__ __nv_bfloat16 g_ahi[Nq * Cq];
__device__ __nv_bfloat16 g_alo[Nq * Cq];
__device__ __nv_bfloat16 g_bhi[(size_t)Cq * VP];
__device__ __nv_bfloat16 g_blo[(size_t)Cq * VP];

// ================= helpers =================
__device__ __forceinline__ uint32_t smem_u32(const void* p) {
    uint32_t a;
    asm("{ .reg .u64 t; cvta.to.shared.u64 t, %1; cvt.u32.u64 %0, t; }" : "=r"(a) : "l"(p));
    return a;
}
__device__ __forceinline__ void split_bf16(float f, uint16_t& hi, uint16_t& lo) {
    __nv_bfloat16 h = __float2bfloat16(f);
    hi = __bfloat16_as_ushort(h);
    lo = __bfloat16_as_ushort(__float2bfloat16(f - __bfloat162float(h)));
}
__device__ __forceinline__ void cp16(uint32_t dst, const void* gsrc) {
    uint64_t g = __cvta_generic_to_global(gsrc);
    asm volatile("cp.async.ca.shared.global [%0], [%1], 16;" :: "r"(dst), "l"(g));
}
__device__ __forceinline__ void cp_commit() { asm volatile("cp.async.commit_group;"); }
__device__ __forceinline__ void cp_wait1() { asm volatile("cp.async.wait_group 1;" ::: "memory"); }
__device__ __forceinline__ void cp_wait0() { asm volatile("cp.async.wait_group 0;" ::: "memory"); }
__device__ __forceinline__ void ldsm_x4(uint32_t* r, uint32_t a) {
    asm volatile("ldmatrix.sync.aligned.m8n8.x4.shared.b16 {%0,%1,%2,%3}, [%4];"
                 : "=r"(r[0]), "=r"(r[1]), "=r"(r[2]), "=r"(r[3]) : "r"(a) : "memory");
}
__device__ __forceinline__ void ldsm_x4_t(uint32_t* r, uint32_t a) {
    asm volatile("ldmatrix.sync.aligned.m8n8.x4.trans.shared.b16 {%0,%1,%2,%3}, [%4];"
                 : "=r"(r[0]), "=r"(r[1]), "=r"(r[2]), "=r"(r[3]) : "r"(a) : "memory");
}
__device__ __forceinline__ void mma16816(float* c, const uint32_t* a, uint32_t b0, uint32_t b1) {
    asm volatile(
        "mma.sync.aligned.m16n8k16.row.col.f32.bf16.bf16.f32 "
        "{%0,%1,%2,%3}, {%4,%5,%6,%7}, {%8,%9}, {%0,%1,%2,%3};"
        : "+f"(c[0]), "+f"(c[1]), "+f"(c[2]), "+f"(c[3])
        : "r"(a[0]), "r"(a[1]), "r"(a[2]), "r"(a[3]), "r"(b0), "r"(b1));
}

// ---------------- split kernels (fp32 -> bf16 hi/lo) ----------------
__global__ void k_split_a(const float* __restrict__ src, __nv_bfloat16* __restrict__ hi,
                          __nv_bfloat16* __restrict__ lo) {
    int i = blockIdx.x * 256 + threadIdx.x; // pair index
    float2 v = *(const float2*)&src[i * 2];
    uint16_t h0, l0, h1, l1;
    split_bf16(v.x, h0, l0);
    split_bf16(v.y, h1, l1);
    ((uint32_t*)hi)[i] = (uint32_t)h0 | ((uint32_t)h1 << 16);
    ((uint32_t*)lo)[i] = (uint32_t)l0 | ((uint32_t)l1 << 16);
}
// B: [Cq][Vq] -> padded [Cq][VP], zero-filled tail
__global__ void k_split_b(const float* __restrict__ src, __nv_bfloat16* __restrict__ hi,
                          __nv_bfloat16* __restrict__ lo) {
    int p = blockIdx.x * 256 + threadIdx.x; // pair index in padded layout
    int k = p / (VP / 2);
    int n = (p - k * (VP / 2)) * 2;
    float v0 = (n < Vq) ? src[(size_t)k * Vq + n] : 0.f;
    float v1 = (n + 1 < Vq) ? src[(size_t)k * Vq + n + 1] : 0.f;
    uint16_t h0, l0, h1, l1;
    split_bf16(v0, h0, l0);
    split_bf16(v1, h1, l1);
    ((uint32_t*)hi)[p] = (uint32_t)h0 | ((uint32_t)h1 << 16);
    ((uint32_t*)lo)[p] = (uint32_t)l0 | ((uint32_t)l1 << 16);
}

// ================= lm_head HMMA GEMM =================
// out[2048, Vq] = A[2048, 256] @ B[256, Vq] in fp32 via bf16 3-split.
// One CTA per 128-col strip; B strip (full K) resident in SMEM; CTA loops all
// 16 M-blocks of 128; A streamed in K-chunks of 64 with cp.async double buffer.
static constexpr int SM_B_HI = 0;            // [256 k][128 n] bf16, swizzled, 64KB
static constexpr int SM_B_LO = 65536;
static constexpr int SM_A    = 131072;       // 2 bufs x (hi 16KB + lo 16KB)
static constexpr int LM_SMEM = 196608;

__global__ void __launch_bounds__(256, 1) k_lmhead_mma(const __nv_bfloat16* __restrict__ Ah,
                                                       const __nv_bfloat16* __restrict__ Al,
                                                       const __nv_bfloat16* __restrict__ Bh,
                                                       const __nv_bfloat16* __restrict__ Bl,
                                                       float* __restrict__ out) {
    extern __shared__ char smem[];
    uint32_t sb = smem_u32(smem);
    int tid = threadIdx.x;
    int wid = tid >> 5, lane = tid & 31;
    int wm = wid >> 2, wn = wid & 3;     // warp grid 2(m) x 4(n); warp tile 64m x 32n
    int g = lane >> 3, gr = lane & 7;    // ldmatrix address groups
    int n0 = blockIdx.x * 128;

    // ---- issue B strip copies (one-time) + A chunk 0, as commit group 0 ----
#pragma unroll
    for (int it = 0; it < 32; it++) {
        int lin = tid + it * 256;        // 0..8191
        int half = lin >> 12;            // 0 hi, 1 lo
        int r = lin & 4095;
        int k = r >> 4, n8 = r & 15;
        uint32_t dst = sb + (half ? SM_B_LO : SM_B_HI) + k * 256 + (((n8 ^ (k & 7))) << 4);
        const __nv_bfloat16* srcb = (half ? Bl : Bh) + (size_t)k * VP + n0 + n8 * 8;
        cp16(dst, srcb);
    }
    // A chunk copier (templated by flat chunk step t)
    auto copyA = [&](int t) {
        int mb = t >> 2;
        int kc = (t & 3) * 64;
        uint32_t abase = sb + SM_A + (t & 1) * 32768;
#pragma unroll
        for (int it = 0; it < 8; it++) {
            int lin = tid + it * 256;    // 0..2047
            int half = lin >> 10;
            int r = lin & 1023;
            int m = r >> 3, k8 = r & 7;
            uint32_t dst = abase + half * 16384 + m * 128 + (((k8 ^ (m & 7))) << 4);
            const __nv_bfloat16* srca = (half ? Al : Ah) + (size_t)(mb * 128 + m) * Cq + kc + k8 * 8;
            cp16(dst, srca);
        }
    };
    copyA(0);
    cp_commit();

    float acc[4][4][4];
#pragma unroll
    for (int a = 0; a < 4; a++)
#pragma unroll
        for (int b = 0; b < 4; b++)
#pragma unroll
            for (int c = 0; c < 4; c++) acc[a][b][c] = 0.f;

    const int k_extra = (g & 1) * 8;
    const int n_extra = (g >> 1) * 8;

    for (int t = 0; t < 64; t++) {
        if (t + 1 < 64) { copyA(t + 1); cp_commit(); cp_wait1(); }
        else cp_wait0();
        __syncthreads();

        int kc = (t & 3) * 64;
        uint32_t ah_base = sb + SM_A + (t & 1) * 32768;
        uint32_t al_base = ah_base + 16384;
#pragma unroll
        for (int ks = 0; ks < 4; ks++) {
            uint32_t Bhf[2][4], Blf[2][4];
#pragma unroll
            for (int b = 0; b < 2; b++) {
                int kx = kc + ks * 16 + k_extra + gr;
                int nf = wn * 32 + b * 16 + n_extra;
                uint32_t off = kx * 256 + ((((nf >> 3) ^ (kx & 7))) << 4);
                ldsm_x4_t(Bhf[b], sb + SM_B_HI + off);
                ldsm_x4_t(Blf[b], sb + SM_B_LO + off);
            }
#pragma unroll
            for (int ma = 0; ma < 4; ma++) {
                int rowa = wm * 64 + ma * 16 + (g & 1) * 8 + gr;
                int kkl = ks * 16 + n_extra; // (g>>1)*8 reused as k-half for A
                uint32_t ao = rowa * 128 + ((((kkl >> 3) ^ (rowa & 7))) << 4);
                uint32_t Ahf[4], Alf[4];
                ldsm_x4(Ahf, ah_base + ao);
                ldsm_x4(Alf, al_base + ao);
#pragma unroll
                for (int b = 0; b < 2; b++) {
                    mma16816(acc[ma][2 * b],     Ahf, Bhf[b][0], Bhf[b][1]);
                    mma16816(acc[ma][2 * b],     Ahf, Blf[b][0], Blf[b][1]);
                    mma16816(acc[ma][2 * b],     Alf, Bhf[b][0], Bhf[b][1]);
                    mma16816(acc[ma][2 * b + 1], Ahf, Bhf[b][2], Bhf[b][3]);
                    mma16816(acc[ma][2 * b + 1], Ahf, Blf[b][2], Blf[b][3]);
                    mma16816(acc[ma][2 * b + 1], Alf, Bhf[b][2], Bhf[b][3]);
                }
            }
        }
        if ((t & 3) == 3) {
            // epilogue for m-block mb = t>>2
            int mbase = (t >> 2) * 128 + wm * 64;
#pragma unroll
            for (int ma = 0; ma < 4; ma++) {
#pragma unroll
                for (int na = 0; na < 4; na++) {
                    int gm = mbase + ma * 16 + (lane >> 2);
                    int gn = n0 + wn * 32 + na * 8 + (lane & 3) * 2;
                    float* p0 = out + (size_t)gm * Vq + gn;
                    float* p1 = out + (size_t)(gm + 8) * Vq + gn;
                    if (gn < Vq)     { p0[0] = acc[ma][na][0]; p1[0] = acc[ma][na][2]; }
                    if (gn + 1 < Vq) { p0[1] = acc[ma][na][1]; p1[1] = acc[ma][na][3]; }
                    acc[ma][na][0] = acc[ma][na][1] = acc[ma][na][2] = acc[ma][na][3] = 0.f;
                }
            }
        }
        __syncthreads();
    }
}

// ---------------- embedding ----------------
__global__ void k_embed(const int* __restrict__ ids, const float* __restrict__ emb,
                        float* __restrict__ hs) {
    int t = blockIdx.x, c = threadIdx.x;
    hs[(size_t)t * Cq + c] = emb[(size_t)ids[t] * Cq + c];
}

// ---------------- layernorm ----------------
__global__ void k_layernorm(const float* __restrict__ in, float* __restrict__ out,
                            const float* __restrict__ w, const float* __restrict__ b) {
    int t = blockIdx.x, c = threadIdx.x;
    float x = in[(size_t)t * Cq + c];
    __shared__ float red[8];
    float s = x;
#pragma unroll
    for (int o = 16; o; o >>= 1) s += __shfl_xor_sync(0xffffffffu, s, o);
    if ((c & 31) == 0) red[c >> 5] = s;
    __syncthreads();
    float mu = 0.f;
#pragma unroll
    for (int i = 0; i < 8; i++) mu += red[i];
    mu *= (1.f / Cq);
    float d = x - mu;
    float s2 = d * d;
#pragma unroll
    for (int o = 16; o; o >>= 1) s2 += __shfl_xor_sync(0xffffffffu, s2, o);
    __syncthreads();
    if ((c & 31) == 0) red[c >> 5] = s2;
    __syncthreads();
    float var = 0.f;
#pragma unroll
    for (int i = 0; i < 8; i++) var += red[i];
    var *= (1.f / Cq);
    out[(size_t)t * Cq + c] = d * rsqrtf(var + 1e-5f) * w[c] + b[c];
}

// ---------------- generic SGEMM (small projections) ----------------
__global__ void __launch_bounds__(256) k_sgemm(const float* __restrict__ A,
                                               const float* __restrict__ B,
                                               float* __restrict__ Cc,
                                               int M, int Nn, int K, int addC) {
    __shared__ float As[16 * 68];
    __shared__ float Bs[16 * 64];
    int tid = threadIdx.x;
    int tx = tid & 15, ty = tid >> 4;
    int colbase = blockIdx.x * 64, rowbase = blockIdx.y * 64;
    float acc[16];
#pragma unroll
    for (int i = 0; i < 16; i++) acc[i] = 0.f;

    for (int kc = 0; kc < K; kc += 16) {
#pragma unroll
        for (int i = 0; i < 4; i++) {
            int lin = tid + i * 256;
            int r = lin >> 4, kk = lin & 15;
            int grow = rowbase + r;
            As[kk * 68 + r] = (grow < M) ? A[(size_t)grow * K + kc + kk] : 0.f;
            int kk2 = lin >> 6, cc = lin & 63;
            int gcol = colbase + cc;
            Bs[kk2 * 64 + cc] = (gcol < Nn) ? B[(size_t)(kc + kk2) * Nn + gcol] : 0.f;
        }
        __syncthreads();
#pragma unroll
        for (int kk = 0; kk < 16; kk++) {
            float4 a = *(const float4*)&As[kk * 68 + ty * 4];
            float4 b = *(const float4*)&Bs[kk * 64 + tx * 4];
            acc[0]  += a.x * b.x; acc[1]  += a.x * b.y; acc[2]  += a.x * b.z; acc[3]  += a.x * b.w;
            acc[4]  += a.y * b.x; acc[5]  += a.y * b.y; acc[6]  += a.y * b.z; acc[7]  += a.y * b.w;
            acc[8]  += a.z * b.x; acc[9]  += a.z * b.y; acc[10] += a.z * b.z; acc[11] += a.z * b.w;
            acc[12] += a.w * b.x; acc[13] += a.w * b.y; acc[14] += a.w * b.z; acc[15] += a.w * b.w;
        }
        __syncthreads();
    }
#pragma unroll
    for (int i = 0; i < 4; i++) {
        int r = rowbase + ty * 4 + i;
        if (r >= M) continue;
#pragma unroll
        for (int j = 0; j < 4; j++) {
            int cl = colbase + tx * 4 + j;
            if (cl < Nn) {
                float v = acc[i * 4 + j];
                if (addC) v += Cc[(size_t)r * Nn + cl];
                Cc[(size_t)r * Nn + cl] = v;
            }
        }
    }
}

// ---------------- causal attention ----------------
__global__ void k_attn(const float* __restrict__ q, const float* __restrict__ k,
                       const float* __restrict__ v, float* __restrict__ o) {
    int b = blockIdx.z, h = blockIdx.y;
    int t0 = blockIdx.x * 64;
    int qi = t0 + threadIdx.x;
    const float scale = 0.17677669529663687f;
    float qr[Dq];
    const float* qp = q + ((size_t)(b * Tq + qi)) * Cq + h * Dq;
#pragma unroll
    for (int d = 0; d < Dq; d++) qr[d] = qp[d] * scale;
    float acc[Dq];
#pragma unroll
    for (int d = 0; d < Dq; d++) acc[d] = 0.f;
    float m = -INFINITY, l = 0.f;
    __shared__ float Ks[64 * Dq], Vs[64 * Dq];

    for (int kt = 0; kt < t0 + 64; kt += 64) {
        for (int i = threadIdx.x; i < 64 * Dq; i += 64) {
            int r = i >> 5, d = i & 31;
            size_t gi = ((size_t)(b * Tq + kt + r)) * Cq + h * Dq + d;
            Ks[i] = k[gi];
            Vs[i] = v[gi];
        }
        __syncthreads();
        int jmax = qi - kt + 1;
        if (jmax > 64) jmax = 64;
        for (int j = 0; j < jmax; j++) {
            float s = 0.f;
#pragma unroll
            for (int d = 0; d < Dq; d++) s += qr[d] * Ks[j * Dq + d];
            float nm = fmaxf(m, s);
            float corr = expf(m - nm);
            float p = expf(s - nm);
            l = l * corr + p;
#pragma unroll
            for (int d = 0; d < Dq; d++) acc[d] = acc[d] * corr + p * Vs[j * Dq + d];
            m = nm;
        }
        __syncthreads();
    }
    float inv = 1.f / l;
    float* op = o + ((size_t)(b * Tq + qi)) * Cq + h * Dq;
#pragma unroll
    for (int d = 0; d < Dq; d++) op[d] = acc[d] * inv;
}

// ---------------- normalize sim_matrix columns ----------------
__global__ void k_simnorm(const float* __restrict__ sim, float* __restrict__ sn) {
    __shared__ float ps[8][32];
    __shared__ float inv[32];
    int tid = threadIdx.x;
    int e = tid & 31, part = tid >> 5;
    float s = 0.f;
    for (int c = part * 32; c < part * 32 + 32; c++) {
        float vv = sim[(size_t)c * Eq + e];
        s += vv * vv;
    }
    ps[part][e] = s;
    __syncthreads();
    if (tid < 32) {
        float tot = 0.f;
#pragma unroll
        for (int p = 0; p < 8; p++) tot += ps[p][tid];
        inv[tid] = 1.f / fmaxf(sqrtf(tot), 1e-12f);
    }
    __syncthreads();
    for (int i = tid; i < Cq * Eq; i += 256) sn[i] = sim[i] * inv[i & 31];
}

// ---------------- gate logits ----------------
__global__ void k_gate_logits(const float* __restrict__ xt, const float* __restrict__ sn,
                              float* __restrict__ logits) {
    __shared__ float xs[8 * Cq];
    int tid = threadIdx.x;
    int t0 = blockIdx.x * 8;
    for (int i = tid; i < 8 * Cq; i += 256) xs[i] = xt[(size_t)t0 * Cq + i];
    __syncthreads();
    int w = tid >> 5, lane = tid & 31;
    int t = t0 + w;
    float s = 0.f;
    for (int c = lane; c < Cq; c += 32) {
        float vv = xs[w * Cq + c];
        s += vv * vv;
    }
#pragma unroll
    for (int o = 16; o; o >>= 1) s += __shfl_xor_sync(0xffffffffu, s, o);
    float inv = 1.f / fmaxf(sqrtf(s), 1e-12f);
    float acc = 0.f;
    for (int c = 0; c < Cq; c++) acc += xs[w * Cq + c] * sn[c * Eq + lane];
    logits[(size_t)t * Eq + lane] = acc * inv;
}

// ---------------- gate decision + routing softmax ----------------
__global__ void k_gate(const float* __restrict__ logits, const float* __restrict__ gates,
                       float* __restrict__ pre_o, float* __restrict__ am_o,
                       float* __restrict__ rw) {
    int w = threadIdx.x >> 5, lane = threadIdx.x & 31;
    int t = blockIdx.x * 8 + w;
    float lg = logits[(size_t)t * Eq + lane];
    float pre = lg - 1.f / (1.f + expf(-gates[lane]));
    float gated = fmaxf(pre, 0.f);
    unsigned act = __ballot_sync(0xffffffffu, pre > 0.f);
    float am;
    if (act == 0u) {
        int rank = 0;
#pragma unroll
        for (int j = 0; j < 32; j++) {
            float lj = __shfl_sync(0xffffffffu, lg, j);
            rank += (lj > lg) || (lj == lg && j < lane);
        }
        am = (rank < 16) ? 1.f : 0.f;
    } else {
        am = (pre > 0.f) ? 1.f : 0.f;
    }
    float g2 = (am > 0.f) ? gated : -INFINITY;
    float mx = g2;
#pragma unroll
    for (int o = 16; o; o >>= 1) mx = fmaxf(mx, __shfl_xor_sync(0xffffffffu, mx, o));
    float p = (am > 0.f) ? expf(gated - mx) : 0.f;
    float sum = p;
#pragma unroll
    for (int o = 16; o; o >>= 1) sum += __shfl_xor_sync(0xffffffffu, sum, o);
    rw[(size_t)t * Eq + lane] = p / sum;
    pre_o[(size_t)t * Eq + lane] = pre;
    am_o[(size_t)t * Eq + lane] = am;
}

// ---------------- fused MoE FFN ----------------
static constexpr int TM = 32;
static constexpr int FC = 32;
static constexpr int MOE_SMEM_FLOATS = TM * Cq + Cq * FC + FC * Cq + TM * (FC + 1);
static constexpr int MOE_SMEM_BYTES = MOE_SMEM_FLOATS * 4;

__device__ __forceinline__ float gelu_exact(float x) {
    return 0.5f * x * (1.0f + erff(x * 0.70710678118654752f));
}

__global__ void __launch_bounds__(256) k_moe(const float* __restrict__ xt,
                                             const float* __restrict__ w1,
                                             const float* __restrict__ w2,
                                             const float* __restrict__ amask,
                                             float* __restrict__ feo) {
    extern __shared__ float smemf[];
    float* Xs  = smemf;
    float* W1s = Xs + TM * Cq;
    float* W2s = W1s + Cq * FC;
    float* Hs  = W2s + FC * Cq;

    int e = blockIdx.y;
    int t0 = blockIdx.x * TM;
    int tid = threadIdx.x;
    int ty = tid >> 5, tx = tid & 31;

    for (int i = tid; i < TM * Cq; i += 256) {
        int r = i >> 8, c = i & 255;
        Xs[r * Cq + c] = xt[(size_t)(t0 + r) * Cq + c];
    }

    float acc[4][8];
#pragma unroll
    for (int i = 0; i < 4; i++)
#pragma unroll
        for (int j = 0; j < 8; j++) acc[i][j] = 0.f;

    const float* w1e = w1 + (size_t)e * Cq * Fq;
    const float* w2e = w2 + (size_t)e * Fq * Cq;

    for (int f0 = 0; f0 < Fq; f0 += FC) {
        __syncthreads();
        for (int i = tid; i < Cq * FC; i += 256) {
            int c = i >> 5, f = i & 31;
            W1s[c * FC + f] = w1e[(size_t)c * Fq + f0 + f];
        }
        for (int i = tid; i < FC * Cq; i += 256) {
            int f = i >> 8, c = i & 255;
            W2s[f * Cq + c] = w2e[(size_t)(f0 + f) * Cq + c];
        }
        __syncthreads();
        {
            int rb = ty * 4;
            float h0 = 0.f, h1 = 0.f, h2 = 0.f, h3 = 0.f;
#pragma unroll 4
            for (int c = 0; c < Cq; c++) {
                float wv = W1s[c * FC + tx];
                h0 += Xs[(rb + 0) * Cq + c] * wv;
                h1 += Xs[(rb + 1) * Cq + c] * wv;
                h2 += Xs[(rb + 2) * Cq + c] * wv;
                h3 += Xs[(rb + 3) * Cq + c] * wv;
            }
            Hs[(rb + 0) * (FC + 1) + tx] = gelu_exact(h0);
            Hs[(rb + 1) * (FC + 1) + tx] = gelu_exact(h1);
            Hs[(rb + 2) * (FC + 1) + tx] = gelu_exact(h2);
            Hs[(rb + 3) * (FC + 1) + tx] = gelu_exact(h3);
        }
        __syncthreads();
#pragma unroll 4
        for (int f = 0; f < FC; f++) {
            float a0 = Hs[(ty * 4 + 0) * (FC + 1) + f];
            float a1 = Hs[(ty * 4 + 1) * (FC + 1) + f];
            float a2 = Hs[(ty * 4 + 2) * (FC + 1) + f];
            float a3 = Hs[(ty * 4 + 3) * (FC + 1) + f];
            float4 b0 = *(const float4*)&W2s[f * Cq + tx * 8];
            float4 b1 = *(const float4*)&W2s[f * Cq + tx * 8 + 4];
            acc[0][0] += a0 * b0.x; acc[0][1] += a0 * b0.y; acc[0][2] += a0 * b0.z; acc[0][3] += a0 * b0.w;
            acc[0][4] += a0 * b1.x; acc[0][5] += a0 * b1.y; acc[0][6] += a0 * b1.z; acc[0][7] += a0 * b1.w;
            acc[1][0] += a1 * b0.x; acc[1][1] += a1 * b0.y; acc[1][2] += a1 * b0.z; acc[1][3] += a1 * b0.w;
            acc[1][4] += a1 * b1.x; acc[1][5] += a1 * b1.y; acc[1][6] += a1 * b1.z; acc[1][7] += a1 * b1.w;
            acc[2][0] += a2 * b0.x; acc[2][1] += a2 * b0.y; acc[2][2] += a2 * b0.z; acc[2][3] += a2 * b0.w;
            acc[2][4] += a2 * b1.x; acc[2][5] += a2 * b1.y; acc[2][6] += a2 * b1.z; acc[2][7] += a2 * b1.w;
            acc[3][0] += a3 * b0.x; acc[3][1] += a3 * b0.y; acc[3][2] += a3 * b0.z; acc[3][3] += a3 * b0.w;
            acc[3][4] += a3 * b1.x; acc[3][5] += a3 * b1.y; acc[3][6] += a3 * b1.z; acc[3][7] += a3 * b1.w;
        }
    }
#pragma unroll
    for (int i = 0; i < 4; i++) {
        int row = t0 + ty * 4 + i;
        float mm = amask[(size_t)row * Eq + e];
        float4 o0 = make_float4(acc[i][0] * mm, acc[i][1] * mm, acc[i][2] * mm, acc[i][3] * mm);
        float4 o1 = make_float4(acc[i][4] * mm, acc[i][5] * mm, acc[i][6] * mm, acc[i][7] * mm);
        float* dst = feo + ((size_t)row * Eq + e) * Cq + tx * 8;
        *(float4*)(dst) = o0;
        *(float4*)(dst + 4) = o1;
    }
}

// ---------------- combine ----------------
__global__ void k_combine(const float* __restrict__ rw, const float* __restrict__ feo,
                          float* __restrict__ hs) {
    int t = blockIdx.x, c = threadIdx.x;
    float s = hs[(size_t)t * Cq + c];
#pragma unroll
    for (int e = 0; e < Eq; e++)
        s += rw[(size_t)t * Eq + e] * feo[((size_t)t * Eq + e) * Cq + c];
    hs[(size_t)t * Cq + c] = s;
}

// ---------------- host ----------------
extern "C" void kernel_launch(void* const* d_in, const int* in_sizes, int n_in,
                              void* d_out, int out_size) {
    const int*   ids   = (const int*)d_in[0];
    const float* emb   = (const float*)d_in[1];
    const float* wq    = (const float*)d_in[2];
    const float* wk    = (const float*)d_in[3];
    const float* wv    = (const float*)d_in[4];
    const float* wo    = (const float*)d_in[5];
    const float* ln1w  = (const float*)d_in[6];
    const float* ln1b  = (const float*)d_in[7];
    const float* ln2w  = (const float*)d_in[8];
    const float* ln2b  = (const float*)d_in[9];
    const float* sim   = (const float*)d_in[10];
    const float* gates = (const float*)d_in[11];
    const float* w1    = (const float*)d_in[12];
    const float* w2    = (const float*)d_in[13];
    const float* lmh   = (const float*)d_in[14];

    float *hs, *x, *q, *k, *v, *ao, *xt, *sn, *logits, *rw, *feo_s, *pre_s, *am_s;
    __nv_bfloat16 *ahi, *alo, *bhi, *blo;
    cudaGetSymbolAddress((void**)&hs, g_hs);
    cudaGetSymbolAddress((void**)&x, g_x);
    cudaGetSymbolAddress((void**)&q, g_q);
    cudaGetSymbolAddress((void**)&k, g_k);
    cudaGetSymbolAddress((void**)&v, g_v);
    cudaGetSymbolAddress((void**)&ao, g_ao);
    cudaGetSymbolAddress((void**)&xt, g_xt);
    cudaGetSymbolAddress((void**)&sn, g_sn);
    cudaGetSymbolAddress((void**)&logits, g_logits);
    cudaGetSymbolAddress((void**)&rw, g_rw);
    cudaGetSymbolAddress((void**)&feo_s, g_feo);
    cudaGetSymbolAddress((void**)&pre_s, g_pre);
    cudaGetSymbolAddress((void**)&am_s, g_am);
    cudaGetSymbolAddress((void**)&ahi, g_ahi);
    cudaGetSymbolAddress((void**)&alo, g_alo);
    cudaGetSymbolAddress((void**)&bhi, g_bhi);
    cudaGetSymbolAddress((void**)&blo, g_blo);

    float* out = (float*)d_out;
    const size_t NV  = (size_t)Nq * Vq;
    const size_t FEO = (size_t)Nq * Eq * Cq;
    const size_t NE  = (size_t)Nq * Eq;
    float *feo, *pre_o, *am_o;
    if ((size_t)out_size >= NV + FEO + 2 * NE) {
        feo = out + NV;
        pre_o = out + NV + FEO;
        am_o = pre_o + NE;
    } else {
        feo = feo_s; pre_o = pre_s; am_o = am_s;
    }

    k_embed<<<Nq, Cq>>>(ids, emb, hs);
    // pre-split lm_head weights (constant, but graph replays everything)
    k_split_b<<<(Cq * VP / 2) / 256, 256>>>(lmh, bhi, blo);

    k_layernorm<<<Nq, Cq>>>(hs, x, ln1w, ln1b);

    dim3 gP(Cq / 64, Nq / 64);
    k_sgemm<<<gP, 256>>>(x, wq, q, Nq, Cq, Cq, 0);
    k_sgemm<<<gP, 256>>>(x, wk, k, Nq, Cq, Cq, 0);
    k_sgemm<<<gP, 256>>>(x, wv, v, Nq, Cq, Cq, 0);

    k_attn<<<dim3(Tq / 64, Hq, Bq), 64>>>(q, k, v, ao);
    k_sgemm<<<gP, 256>>>(ao, wo, hs, Nq, Cq, Cq, 1);

    k_layernorm<<<Nq, Cq>>>(hs, xt, ln2w, ln2b);
    k_simnorm<<<1, 256>>>(sim, sn);
    k_gate_logits<<<Nq / 8, 256>>>(xt, sn, logits);
    k_gate<<<Nq / 8, 256>>>(logits, gates, pre_o, am_o, rw);

    cudaFuncSetAttribute(k_moe, cudaFuncAttributeMaxDynamicSharedMemorySize, MOE_SMEM_BYTES);
    k_moe<<<dim3(Nq / TM, Eq), 256, MOE_SMEM_BYTES>>>(xt, w1, w2, am_o, feo);

    k_combine<<<Nq, Cq>>>(rw, feo, hs);

    // lm_head on HMMA tensor cores (bf16 3-split)
    k_split_a<<<(Nq * Cq / 2) / 256, 256>>>(hs, ahi, alo);
    cudaFuncSetAttribute(k_lmhead_mma, cudaFuncAttributeMaxDynamicSharedMemorySize, LM_SMEM);
    k_lmhead_mma<<<VP / 128, 256, LM_SMEM>>>(ahi, alo, bhi, blo, out);
}

// round 5
// speedup vs baseline: 2.1145x; 1.7712x over previous
#include <cuda_runtime.h>
#include <cuda_bf16.h>
#include <math.h>
#include <stdint.h>

// ---------------- problem constants ----------------
static constexpr int Bq = 2;
static constexpr int Tq = 1024;
static constexpr int Cq = 256;
static constexpr int Fq = 1024;
static constexpr int Eq = 32;
static constexpr int Vq = 50257;
static constexpr int Hq = 8;
static constexpr int Dq = 32;      // Cq / Hq
static constexpr int Nq = Bq * Tq; // 2048 tokens
static constexpr int VP = 50304;   // Vq padded to 128 (393 tiles)

// ---------------- device scratch (no allocations allowed) ----------------
__device__ float g_hs[Nq * Cq];
__device__ float g_x[Nq * Cq];
__device__ float g_q[Nq * Cq];
__device__ float g_k[Nq * Cq];
__device__ float g_v[Nq * Cq];
__device__ float g_ao[Nq * Cq];
__device__ float g_xt[Nq * Cq];
__device__ float g_sn[Cq * Eq];
__device__ float g_logits[Nq * Eq];
__device__ float g_rw[Nq * Eq];
__device__ float g_feo[(size_t)Nq * Eq * Cq];
__device__ float g_pre[Nq * Eq];
__device__ float g_am[Nq * Eq];
// bf16 hi/lo splits
__device__ __nv_bfloat16 g_ahi[Nq * Cq];
__device__ __nv_bfloat16 g_alo[Nq * Cq];
__device__ __nv_bfloat16 g_bhi[(size_t)Cq * VP];
__device__ __nv_bfloat16 g_blo[(size_t)Cq * VP];
__device__ __nv_bfloat16 g_xhi[Nq * Cq];
__device__ __nv_bfloat16 g_xlo[Nq * Cq];
__device__ __nv_bfloat16 g_w1h[(size_t)Eq * Cq * Fq];
__device__ __nv_bfloat16 g_w1l[(size_t)Eq * Cq * Fq];
__device__ __nv_bfloat16 g_w2h[(size_t)Eq * Fq * Cq];
__device__ __nv_bfloat16 g_w2l[(size_t)Eq * Fq * Cq];
__device__ __nv_bfloat16 g_hh[(size_t)Eq * Nq * Fq];   // gelu(X@W1) hi
__device__ __nv_bfloat16 g_hl[(size_t)Eq * Nq * Fq];   // gelu(X@W1) lo

// ================= helpers =================
__device__ __forceinline__ uint32_t smem_u32(const void* p) {
    uint32_t a;
    asm("{ .reg .u64 t; cvta.to.shared.u64 t, %1; cvt.u32.u64 %0, t; }" : "=r"(a) : "l"(p));
    return a;
}
__device__ __forceinline__ void split_bf16(float f, uint16_t& hi, uint16_t& lo) {
    __nv_bfloat16 h = __float2bfloat16(f);
    hi = __bfloat16_as_ushort(h);
    lo = __bfloat16_as_ushort(__float2bfloat16(f - __bfloat162float(h)));
}
__device__ __forceinline__ void cp16(uint32_t dst, const void* gsrc) {
    uint64_t g = __cvta_generic_to_global(gsrc);
    asm volatile("cp.async.ca.shared.global [%0], [%1], 16;" :: "r"(dst), "l"(g));
}
__device__ __forceinline__ void cp_commit() { asm volatile("cp.async.commit_group;"); }
__device__ __forceinline__ void cp_wait1() { asm volatile("cp.async.wait_group 1;" ::: "memory"); }
__device__ __forceinline__ void cp_wait0() { asm volatile("cp.async.wait_group 0;" ::: "memory"); }
__device__ __forceinline__ void ldsm_x4(uint32_t* r, uint32_t a) {
    asm volatile("ldmatrix.sync.aligned.m8n8.x4.shared.b16 {%0,%1,%2,%3}, [%4];"
                 : "=r"(r[0]), "=r"(r[1]), "=r"(r[2]), "=r"(r[3]) : "r"(a) : "memory");
}
__device__ __forceinline__ void ldsm_x4_t(uint32_t* r, uint32_t a) {
    asm volatile("ldmatrix.sync.aligned.m8n8.x4.trans.shared.b16 {%0,%1,%2,%3}, [%4];"
                 : "=r"(r[0]), "=r"(r[1]), "=r"(r[2]), "=r"(r[3]) : "r"(a) : "memory");
}
__device__ __forceinline__ void mma16816(float* c, const uint32_t* a, uint32_t b0, uint32_t b1) {
    asm volatile(
        "mma.sync.aligned.m16n8k16.row.col.f32.bf16.bf16.f32 "
        "{%0,%1,%2,%3}, {%4,%5,%6,%7}, {%8,%9}, {%0,%1,%2,%3};"
        : "+f"(c[0]), "+f"(c[1]), "+f"(c[2]), "+f"(c[3])
        : "r"(a[0]), "r"(a[1]), "r"(a[2]), "r"(a[3]), "r"(b0), "r"(b1));
}
__device__ __forceinline__ float gelu_exact(float x) {
    return 0.5f * x * (1.0f + erff(x * 0.70710678118654752f));
}

// ---------------- split kernels (fp32 -> bf16 hi/lo) ----------------
__global__ void k_split_a(const float* __restrict__ src, __nv_bfloat16* __restrict__ hi,
                          __nv_bfloat16* __restrict__ lo) {
    size_t i = (size_t)blockIdx.x * 256 + threadIdx.x; // pair index
    float2 v = *(const float2*)&src[i * 2];
    uint16_t h0, l0, h1, l1;
    split_bf16(v.x, h0, l0);
    split_bf16(v.y, h1, l1);
    ((uint32_t*)hi)[i] = (uint32_t)h0 | ((uint32_t)h1 << 16);
    ((uint32_t*)lo)[i] = (uint32_t)l0 | ((uint32_t)l1 << 16);
}
__global__ void k_split_b(const float* __restrict__ src, __nv_bfloat16* __restrict__ hi,
                          __nv_bfloat16* __restrict__ lo) {
    int p = blockIdx.x * 256 + threadIdx.x;
    int k = p / (VP / 2);
    int n = (p - k * (VP / 2)) * 2;
    float v0 = (n < Vq) ? src[(size_t)k * Vq + n] : 0.f;
    float v1 = (n + 1 < Vq) ? src[(size_t)k * Vq + n + 1] : 0.f;
    uint16_t h0, l0, h1, l1;
    split_bf16(v0, h0, l0);
    split_bf16(v1, h1, l1);
    ((uint32_t*)hi)[p] = (uint32_t)h0 | ((uint32_t)h1 << 16);
    ((uint32_t*)lo)[p] = (uint32_t)l0 | ((uint32_t)l1 << 16);
}

// ================= generic MoE HMMA GEMM (bf16 3-split) =================
// Per CTA: 128m x 128n tile, K chunked by 64, cp.async double buffer.
// epi=0: O = gelu(A@B) -> split bf16 store to Oh/Ol   (up-proj)
// epi=1: feo = amask * (A@B), fp32                    (down-proj)
static constexpr int MM_SMEM = 131072; // 2 bufs x (Ahi16K + Alo16K + Bhi16K + Blo16K)

__global__ void __launch_bounds__(256, 1) k_moe_mma(
    const __nv_bfloat16* __restrict__ Ah, const __nv_bfloat16* __restrict__ Al,
    const __nv_bfloat16* __restrict__ Bh, const __nv_bfloat16* __restrict__ Bl,
    const float* __restrict__ amask,
    __nv_bfloat16* __restrict__ Oh, __nv_bfloat16* __restrict__ Ol,
    float* __restrict__ feo,
    int K, int lda, int ldb, int aExpStride, int epi) {
    extern __shared__ char smem[];
    uint32_t sb = smem_u32(smem);
    int tid = threadIdx.x, wid = tid >> 5, lane = tid & 31;
    int wm = wid >> 2, wn = wid & 3;    // warp grid 2m x 4n, warp tile 64x32
    int g = lane >> 3, gr = lane & 7;
    int n0 = blockIdx.x * 128, m0 = blockIdx.y * 128, e = blockIdx.z;

    const __nv_bfloat16* Abh = Ah + (size_t)e * aExpStride;
    const __nv_bfloat16* Abl = Al + (size_t)e * aExpStride;
    const __nv_bfloat16* Bbh = Bh + (size_t)e * K * ldb + n0;
    const __nv_bfloat16* Bbl = Bl + (size_t)e * K * ldb + n0;

    auto copyChunk = [&](int ch) {
        uint32_t base = sb + (ch & 1) * 65536;
        int kc = ch * 64;
#pragma unroll
        for (int it = 0; it < 8; it++) {         // A: [128m][64k] hi+lo
            int lin = tid + it * 256;
            int half = lin >> 10;
            int r = lin & 1023;
            int m = r >> 3, k8 = r & 7;
            uint32_t dst = base + half * 16384 + m * 128 + (((k8 ^ (m & 7))) << 4);
            cp16(dst, (half ? Abl : Abh) + (size_t)(m0 + m) * lda + kc + k8 * 8);
        }
#pragma unroll
        for (int it = 0; it < 8; it++) {         // B: [64k][128n] hi+lo
            int lin = tid + it * 256;
            int half = lin >> 10;
            int r = lin & 1023;
            int k = r >> 4, n8 = r & 15;
            uint32_t dst = base + 32768 + half * 16384 + k * 256 + (((n8 ^ (k & 7))) << 4);
            cp16(dst, (half ? Bbl : Bbh) + (size_t)(kc + k) * ldb + n8 * 8);
        }
    };

    float acc[4][4][4];
#pragma unroll
    for (int a = 0; a < 4; a++)
#pragma unroll
        for (int b = 0; b < 4; b++)
#pragma unroll
            for (int c = 0; c < 4; c++) acc[a][b][c] = 0.f;

    const int k_extra = (g & 1) * 8;
    const int n_extra = (g >> 1) * 8;
    const int nch = K / 64;

    copyChunk(0);
    cp_commit();
    for (int t = 0; t < nch; t++) {
        if (t + 1 < nch) { copyChunk(t + 1); cp_commit(); cp_wait1(); }
        else cp_wait0();
        __syncthreads();
        uint32_t ab = sb + (t & 1) * 65536;
        uint32_t bb = ab + 32768;
#pragma unroll
        for (int ks = 0; ks < 4; ks++) {
            uint32_t Bhf[2][4], Blf[2][4];
#pragma unroll
            for (int b = 0; b < 2; b++) {
                int kx = ks * 16 + k_extra + gr;
                int nf = wn * 32 + b * 16 + n_extra;
                uint32_t off = kx * 256 + ((((nf >> 3) ^ (kx & 7))) << 4);
                ldsm_x4_t(Bhf[b], bb + off);
                ldsm_x4_t(Blf[b], bb + 16384 + off);
            }
#pragma unroll
            for (int ma = 0; ma < 4; ma++) {
                int rowa = wm * 64 + ma * 16 + (g & 1) * 8 + gr;
                int kk = ks * 16 + n_extra;
                uint32_t ao = rowa * 128 + ((((kk >> 3) ^ (rowa & 7))) << 4);
                uint32_t Ahf[4], Alf[4];
                ldsm_x4(Ahf, ab + ao);
                ldsm_x4(Alf, ab + 16384 + ao);
#pragma unroll
                for (int b = 0; b < 2; b++) {
                    mma16816(acc[ma][2 * b],     Ahf, Bhf[b][0], Bhf[b][1]);
                    mma16816(acc[ma][2 * b],     Ahf, Blf[b][0], Blf[b][1]);
                    mma16816(acc[ma][2 * b],     Alf, Bhf[b][0], Bhf[b][1]);
                    mma16816(acc[ma][2 * b + 1], Ahf, Bhf[b][2], Bhf[b][3]);
                    mma16816(acc[ma][2 * b + 1], Ahf, Blf[b][2], Blf[b][3]);
                    mma16816(acc[ma][2 * b + 1], Alf, Bhf[b][2], Bhf[b][3]);
                }
            }
        }
        __syncthreads();
    }

    if (epi == 0) {
        // gelu -> split bf16 hi/lo, O layout [e][Nq][Fq]
#pragma unroll
        for (int ma = 0; ma < 4; ma++) {
            int gm = m0 + wm * 64 + ma * 16 + (lane >> 2);
#pragma unroll
            for (int na = 0; na < 4; na++) {
                int gn = n0 + wn * 32 + na * 8 + (lane & 3) * 2;
                float v0 = gelu_exact(acc[ma][na][0]);
                float v1 = gelu_exact(acc[ma][na][1]);
                float v2 = gelu_exact(acc[ma][na][2]);
                float v3 = gelu_exact(acc[ma][na][3]);
                uint16_t h0, l0, h1, l1, h2, l2, h3, l3;
                split_bf16(v0, h0, l0); split_bf16(v1, h1, l1);
                split_bf16(v2, h2, l2); split_bf16(v3, h3, l3);
                size_t o0 = ((size_t)e * Nq + gm) * Fq + gn;
                size_t o1 = ((size_t)e * Nq + gm + 8) * Fq + gn;
                *(uint32_t*)(Oh + o0) = (uint32_t)h0 | ((uint32_t)h1 << 16);
                *(uint32_t*)(Ol + o0) = (uint32_t)l0 | ((uint32_t)l1 << 16);
                *(uint32_t*)(Oh + o1) = (uint32_t)h2 | ((uint32_t)h3 << 16);
                *(uint32_t*)(Ol + o1) = (uint32_t)l2 | ((uint32_t)l3 << 16);
            }
        }
    } else {
#pragma unroll
        for (int ma = 0; ma < 4; ma++) {
            int gm = m0 + wm * 64 + ma * 16 + (lane >> 2);
            float mm0 = amask[(size_t)gm * Eq + e];
            float mm8 = amask[(size_t)(gm + 8) * Eq + e];
#pragma unroll
            for (int na = 0; na < 4; na++) {
                int gn = n0 + wn * 32 + na * 8 + (lane & 3) * 2;
                float* p0 = feo + ((size_t)gm * Eq + e) * Cq + gn;
                float* p1 = feo + ((size_t)(gm + 8) * Eq + e) * Cq + gn;
                p0[0] = acc[ma][na][0] * mm0;
                p0[1] = acc[ma][na][1] * mm0;
                p1[0] = acc[ma][na][2] * mm8;
                p1[1] = acc[ma][na][3] * mm8;
            }
        }
    }
}

// ================= lm_head HMMA GEMM =================
static constexpr int SM_B_HI = 0;
static constexpr int SM_B_LO = 65536;
static constexpr int SM_A    = 131072;
static constexpr int LM_SMEM = 196608;

__global__ void __launch_bounds__(256, 1) k_lmhead_mma(const __nv_bfloat16* __restrict__ Ah,
                                                       const __nv_bfloat16* __restrict__ Al,
                                                       const __nv_bfloat16* __restrict__ Bh,
                                                       const __nv_bfloat16* __restrict__ Bl,
                                                       float* __restrict__ out) {
    extern __shared__ char smem[];
    uint32_t sb = smem_u32(smem);
    int tid = threadIdx.x;
    int wid = tid >> 5, lane = tid & 31;
    int wm = wid >> 2, wn = wid & 3;
    int g = lane >> 3, gr = lane & 7;
    int n0 = blockIdx.x * 128;

#pragma unroll
    for (int it = 0; it < 32; it++) {
        int lin = tid + it * 256;
        int half = lin >> 12;
        int r = lin & 4095;
        int k = r >> 4, n8 = r & 15;
        uint32_t dst = sb + (half ? SM_B_LO : SM_B_HI) + k * 256 + (((n8 ^ (k & 7))) << 4);
        const __nv_bfloat16* srcb = (half ? Bl : Bh) + (size_t)k * VP + n0 + n8 * 8;
        cp16(dst, srcb);
    }
    auto copyA = [&](int t) {
        int mb = t >> 2;
        int kc = (t & 3) * 64;
        uint32_t abase = sb + SM_A + (t & 1) * 32768;
#pragma unroll
        for (int it = 0; it < 8; it++) {
            int lin = tid + it * 256;
            int half = lin >> 10;
            int r = lin & 1023;
            int m = r >> 3, k8 = r & 7;
            uint32_t dst = abase + half * 16384 + m * 128 + (((k8 ^ (m & 7))) << 4);
            const __nv_bfloat16* srca = (half ? Al : Ah) + (size_t)(mb * 128 + m) * Cq + kc + k8 * 8;
            cp16(dst, srca);
        }
    };
    copyA(0);
    cp_commit();

    float acc[4][4][4];
#pragma unroll
    for (int a = 0; a < 4; a++)
#pragma unroll
        for (int b = 0; b < 4; b++)
#pragma unroll
            for (int c = 0; c < 4; c++) acc[a][b][c] = 0.f;

    const int k_extra = (g & 1) * 8;
    const int n_extra = (g >> 1) * 8;

    for (int t = 0; t < 64; t++) {
        if (t + 1 < 64) { copyA(t + 1); cp_commit(); cp_wait1(); }
        else cp_wait0();
        __syncthreads();

        int kc = (t & 3) * 64;
        uint32_t ah_base = sb + SM_A + (t & 1) * 32768;
        uint32_t al_base = ah_base + 16384;
#pragma unroll
        for (int ks = 0; ks < 4; ks++) {
            uint32_t Bhf[2][4], Blf[2][4];
#pragma unroll
            for (int b = 0; b < 2; b++) {
                int kx = kc + ks * 16 + k_extra + gr;
                int nf = wn * 32 + b * 16 + n_extra;
                uint32_t off = kx * 256 + ((((nf >> 3) ^ (kx & 7))) << 4);
                ldsm_x4_t(Bhf[b], sb + SM_B_HI + off);
                ldsm_x4_t(Blf[b], sb + SM_B_LO + off);
            }
#pragma unroll
            for (int ma = 0; ma < 4; ma++) {
                int rowa = wm * 64 + ma * 16 + (g & 1) * 8 + gr;
                int kkl = ks * 16 + n_extra;
                uint32_t ao = rowa * 128 + ((((kkl >> 3) ^ (rowa & 7))) << 4);
                uint32_t Ahf[4], Alf[4];
                ldsm_x4(Ahf, ah_base + ao);
                ldsm_x4(Alf, al_base + ao);
#pragma unroll
                for (int b = 0; b < 2; b++) {
                    mma16816(acc[ma][2 * b],     Ahf, Bhf[b][0], Bhf[b][1]);
                    mma16816(acc[ma][2 * b],     Ahf, Blf[b][0], Blf[b][1]);
                    mma16816(acc[ma][2 * b],     Alf, Bhf[b][0], Bhf[b][1]);
                    mma16816(acc[ma][2 * b + 1], Ahf, Bhf[b][2], Bhf[b][3]);
                    mma16816(acc[ma][2 * b + 1], Ahf, Blf[b][2], Blf[b][3]);
                    mma16816(acc[ma][2 * b + 1], Alf, Bhf[b][2], Bhf[b][3]);
                }
            }
        }
        if ((t & 3) == 3) {
            int mbase = (t >> 2) * 128 + wm * 64;
#pragma unroll
            for (int ma = 0; ma < 4; ma++) {
#pragma unroll
                for (int na = 0; na < 4; na++) {
                    int gm = mbase + ma * 16 + (lane >> 2);
                    int gn = n0 + wn * 32 + na * 8 + (lane & 3) * 2;
                    float* p0 = out + (size_t)gm * Vq + gn;
                    float* p1 = out + (size_t)(gm + 8) * Vq + gn;
                    if (gn < Vq)     { p0[0] = acc[ma][na][0]; p1[0] = acc[ma][na][2]; }
                    if (gn + 1 < Vq) { p0[1] = acc[ma][na][1]; p1[1] = acc[ma][na][3]; }
                    acc[ma][na][0] = acc[ma][na][1] = acc[ma][na][2] = acc[ma][na][3] = 0.f;
                }
            }
        }
        __syncthreads();
    }
}

// ---------------- embedding ----------------
__global__ void k_embed(const int* __restrict__ ids, const float* __restrict__ emb,
                        float* __restrict__ hs) {
    int t = blockIdx.x, c = threadIdx.x;
    hs[(size_t)t * Cq + c] = emb[(size_t)ids[t] * Cq + c];
}

// ---------------- layernorm ----------------
__global__ void k_layernorm(const float* __restrict__ in, float* __restrict__ out,
                            const float* __restrict__ w, const float* __restrict__ b) {
    int t = blockIdx.x, c = threadIdx.x;
    float x = in[(size_t)t * Cq + c];
    __shared__ float red[8];
    float s = x;
#pragma unroll
    for (int o = 16; o; o >>= 1) s += __shfl_xor_sync(0xffffffffu, s, o);
    if ((c & 31) == 0) red[c >> 5] = s;
    __syncthreads();
    float mu = 0.f;
#pragma unroll
    for (int i = 0; i < 8; i++) mu += red[i];
    mu *= (1.f / Cq);
    float d = x - mu;
    float s2 = d * d;
#pragma unroll
    for (int o = 16; o; o >>= 1) s2 += __shfl_xor_sync(0xffffffffu, s2, o);
    __syncthreads();
    if ((c & 31) == 0) red[c >> 5] = s2;
    __syncthreads();
    float var = 0.f;
#pragma unroll
    for (int i = 0; i < 8; i++) var += red[i];
    var *= (1.f / Cq);
    out[(size_t)t * Cq + c] = d * rsqrtf(var + 1e-5f) * w[c] + b[c];
}

// ---------------- generic SGEMM (small projections) ----------------
__global__ void __launch_bounds__(256) k_sgemm(const float* __restrict__ A,
                                               const float* __restrict__ B,
                                               float* __restrict__ Cc,
                                               int M, int Nn, int K, int addC) {
    __shared__ float As[16 * 68];
    __shared__ float Bs[16 * 64];
    int tid = threadIdx.x;
    int tx = tid & 15, ty = tid >> 4;
    int colbase = blockIdx.x * 64, rowbase = blockIdx.y * 64;
    float acc[16];
#pragma unroll
    for (int i = 0; i < 16; i++) acc[i] = 0.f;

    for (int kc = 0; kc < K; kc += 16) {
#pragma unroll
        for (int i = 0; i < 4; i++) {
            int lin = tid + i * 256;
            int r = lin >> 4, kk = lin & 15;
            int grow = rowbase + r;
            As[kk * 68 + r] = (grow < M) ? A[(size_t)grow * K + kc + kk] : 0.f;
            int kk2 = lin >> 6, cc = lin & 63;
            int gcol = colbase + cc;
            Bs[kk2 * 64 + cc] = (gcol < Nn) ? B[(size_t)(kc + kk2) * Nn + gcol] : 0.f;
        }
        __syncthreads();
#pragma unroll
        for (int kk = 0; kk < 16; kk++) {
            float4 a = *(const float4*)&As[kk * 68 + ty * 4];
            float4 b = *(const float4*)&Bs[kk * 64 + tx * 4];
            acc[0]  += a.x * b.x; acc[1]  += a.x * b.y; acc[2]  += a.x * b.z; acc[3]  += a.x * b.w;
            acc[4]  += a.y * b.x; acc[5]  += a.y * b.y; acc[6]  += a.y * b.z; acc[7]  += a.y * b.w;
            acc[8]  += a.z * b.x; acc[9]  += a.z * b.y; acc[10] += a.z * b.z; acc[11] += a.z * b.w;
            acc[12] += a.w * b.x; acc[13] += a.w * b.y; acc[14] += a.w * b.z; acc[15] += a.w * b.w;
        }
        __syncthreads();
    }
#pragma unroll
    for (int i = 0; i < 4; i++) {
        int r = rowbase + ty * 4 + i;
        if (r >= M) continue;
#pragma unroll
        for (int j = 0; j < 4; j++) {
            int cl = colbase + tx * 4 + j;
            if (cl < Nn) {
                float v = acc[i * 4 + j];
                if (addC) v += Cc[(size_t)r * Nn + cl];
                Cc[(size_t)r * Nn + cl] = v;
            }
        }
    }
}

// ---------------- causal attention ----------------
__global__ void k_attn(const float* __restrict__ q, const float* __restrict__ k,
                       const float* __restrict__ v, float* __restrict__ o) {
    int b = blockIdx.z, h = blockIdx.y;
    int t0 = blockIdx.x * 64;
    int qi = t0 + threadIdx.x;
    const float scale = 0.17677669529663687f;
    float qr[Dq];
    const float* qp = q + ((size_t)(b * Tq + qi)) * Cq + h * Dq;
#pragma unroll
    for (int d = 0; d < Dq; d++) qr[d] = qp[d] * scale;
    float acc[Dq];
#pragma unroll
    for (int d = 0; d < Dq; d++) acc[d] = 0.f;
    float m = -INFINITY, l = 0.f;
    __shared__ float Ks[64 * Dq], Vs[64 * Dq];

    for (int kt = 0; kt < t0 + 64; kt += 64) {
        for (int i = threadIdx.x; i < 64 * Dq; i += 64) {
            int r = i >> 5, d = i & 31;
            size_t gi = ((size_t)(b * Tq + kt + r)) * Cq + h * Dq + d;
            Ks[i] = k[gi];
            Vs[i] = v[gi];
        }
        __syncthreads();
        int jmax = qi - kt + 1;
        if (jmax > 64) jmax = 64;
        for (int j = 0; j < jmax; j++) {
            float s = 0.f;
#pragma unroll
            for (int d = 0; d < Dq; d++) s += qr[d] * Ks[j * Dq + d];
            float nm = fmaxf(m, s);
            float corr = expf(m - nm);
            float p = expf(s - nm);
            l = l * corr + p;
#pragma unroll
            for (int d = 0; d < Dq; d++) acc[d] = acc[d] * corr + p * Vs[j * Dq + d];
            m = nm;
        }
        __syncthreads();
    }
    float inv = 1.f / l;
    float* op = o + ((size_t)(b * Tq + qi)) * Cq + h * Dq;
#pragma unroll
    for (int d = 0; d < Dq; d++) op[d] = acc[d] * inv;
}

// ---------------- normalize sim_matrix columns ----------------
__global__ void k_simnorm(const float* __restrict__ sim, float* __restrict__ sn) {
    __shared__ float ps[8][32];
    __shared__ float inv[32];
    int tid = threadIdx.x;
    int e = tid & 31, part = tid >> 5;
    float s = 0.f;
    for (int c = part * 32; c < part * 32 + 32; c++) {
        float vv = sim[(size_t)c * Eq + e];
        s += vv * vv;
    }
    ps[part][e] = s;
    __syncthreads();
    if (tid < 32) {
        float tot = 0.f;
#pragma unroll
        for (int p = 0; p < 8; p++) tot += ps[p][tid];
        inv[tid] = 1.f / fmaxf(sqrtf(tot), 1e-12f);
    }
    __syncthreads();
    for (int i = tid; i < Cq * Eq; i += 256) sn[i] = sim[i] * inv[i & 31];
}

// ---------------- gate logits ----------------
__global__ void k_gate_logits(const float* __restrict__ xt, const float* __restrict__ sn,
                              float* __restrict__ logits) {
    __shared__ float xs[8 * Cq];
    int tid = threadIdx.x;
    int t0 = blockIdx.x * 8;
    for (int i = tid; i < 8 * Cq; i += 256) xs[i] = xt[(size_t)t0 * Cq + i];
    __syncthreads();
    int w = tid >> 5, lane = tid & 31;
    int t = t0 + w;
    float s = 0.f;
    for (int c = lane; c < Cq; c += 32) {
        float vv = xs[w * Cq + c];
        s += vv * vv;
    }
#pragma unroll
    for (int o = 16; o; o >>= 1) s += __shfl_xor_sync(0xffffffffu, s, o);
    float inv = 1.f / fmaxf(sqrtf(s), 1e-12f);
    float acc = 0.f;
    for (int c = 0; c < Cq; c++) acc += xs[w * Cq + c] * sn[c * Eq + lane];
    logits[(size_t)t * Eq + lane] = acc * inv;
}

// ---------------- gate decision + routing softmax ----------------
__global__ void k_gate(const float* __restrict__ logits, const float* __restrict__ gates,
                       float* __restrict__ pre_o, float* __restrict__ am_o,
                       float* __restrict__ rw) {
    int w = threadIdx.x >> 5, lane = threadIdx.x & 31;
    int t = blockIdx.x * 8 + w;
    float lg = logits[(size_t)t * Eq + lane];
    float pre = lg - 1.f / (1.f + expf(-gates[lane]));
    float gated = fmaxf(pre, 0.f);
    unsigned act = __ballot_sync(0xffffffffu, pre > 0.f);
    float am;
    if (act == 0u) {
        int rank = 0;
#pragma unroll
        for (int j = 0; j < 32; j++) {
            float lj = __shfl_sync(0xffffffffu, lg, j);
            rank += (lj > lg) || (lj == lg && j < lane);
        }
        am = (rank < 16) ? 1.f : 0.f;
    } else {
        am = (pre > 0.f) ? 1.f : 0.f;
    }
    float g2 = (am > 0.f) ? gated : -INFINITY;
    float mx = g2;
#pragma unroll
    for (int o = 16; o; o >>= 1) mx = fmaxf(mx, __shfl_xor_sync(0xffffffffu, mx, o));
    float p = (am > 0.f) ? expf(gated - mx) : 0.f;
    float sum = p;
#pragma unroll
    for (int o = 16; o; o >>= 1) sum += __shfl_xor_sync(0xffffffffu, sum, o);
    rw[(size_t)t * Eq + lane] = p / sum;
    pre_o[(size_t)t * Eq + lane] = pre;
    am_o[(size_t)t * Eq + lane] = am;
}

// ---------------- combine ----------------
__global__ void k_combine(const float* __restrict__ rw, const float* __restrict__ feo,
                          float* __restrict__ hs) {
    int t = blockIdx.x, c = threadIdx.x;
    float s = hs[(size_t)t * Cq + c];
#pragma unroll
    for (int e = 0; e < Eq; e++)
        s += rw[(size_t)t * Eq + e] * feo[((size_t)t * Eq + e) * Cq + c];
    hs[(size_t)t * Cq + c] = s;
}

// ---------------- host ----------------
extern "C" void kernel_launch(void* const* d_in, const int* in_sizes, int n_in,
                              void* d_out, int out_size) {
    const int*   ids   = (const int*)d_in[0];
    const float* emb   = (const float*)d_in[1];
    const float* wq    = (const float*)d_in[2];
    const float* wk    = (const float*)d_in[3];
    const float* wv    = (const float*)d_in[4];
    const float* wo    = (const float*)d_in[5];
    const float* ln1w  = (const float*)d_in[6];
    const float* ln1b  = (const float*)d_in[7];
    const float* ln2w  = (const float*)d_in[8];
    const float* ln2b  = (const float*)d_in[9];
    const float* sim   = (const float*)d_in[10];
    const float* gates = (const float*)d_in[11];
    const float* w1    = (const float*)d_in[12];
    const float* w2    = (const float*)d_in[13];
    const float* lmh   = (const float*)d_in[14];

    float *hs, *x, *q, *k, *v, *ao, *xt, *sn, *logits, *rw, *feo_s, *pre_s, *am_s;
    __nv_bfloat16 *ahi, *alo, *bhi, *blo, *xhi, *xlo, *w1h, *w1l, *w2h, *w2l, *hh, *hl;
    cudaGetSymbolAddress((void**)&hs, g_hs);
    cudaGetSymbolAddress((void**)&x, g_x);
    cudaGetSymbolAddress((void**)&q, g_q);
    cudaGetSymbolAddress((void**)&k, g_k);
    cudaGetSymbolAddress((void**)&v, g_v);
    cudaGetSymbolAddress((void**)&ao, g_ao);
    cudaGetSymbolAddress((void**)&xt, g_xt);
    cudaGetSymbolAddress((void**)&sn, g_sn);
    cudaGetSymbolAddress((void**)&logits, g_logits);
    cudaGetSymbolAddress((void**)&rw, g_rw);
    cudaGetSymbolAddress((void**)&feo_s, g_feo);
    cudaGetSymbolAddress((void**)&pre_s, g_pre);
    cudaGetSymbolAddress((void**)&am_s, g_am);
    cudaGetSymbolAddress((void**)&ahi, g_ahi);
    cudaGetSymbolAddress((void**)&alo, g_alo);
    cudaGetSymbolAddress((void**)&bhi, g_bhi);
    cudaGetSymbolAddress((void**)&blo, g_blo);
    cudaGetSymbolAddress((void**)&xhi, g_xhi);
    cudaGetSymbolAddress((void**)&xlo, g_xlo);
    cudaGetSymbolAddress((void**)&w1h, g_w1h);
    cudaGetSymbolAddress((void**)&w1l, g_w1l);
    cudaGetSymbolAddress((void**)&w2h, g_w2h);
    cudaGetSymbolAddress((void**)&w2l, g_w2l);
    cudaGetSymbolAddress((void**)&hh, g_hh);
    cudaGetSymbolAddress((void**)&hl, g_hl);

    float* out = (float*)d_out;
    const size_t NV  = (size_t)Nq * Vq;
    const size_t FEO = (size_t)Nq * Eq * Cq;
    const size_t NE  = (size_t)Nq * Eq;
    float *feo, *pre_o, *am_o;
    if ((size_t)out_size >= NV + FEO + 2 * NE) {
        feo = out + NV;
        pre_o = out + NV + FEO;
        am_o = pre_o + NE;
    } else {
        feo = feo_s; pre_o = pre_s; am_o = am_s;
    }

    k_embed<<<Nq, Cq>>>(ids, emb, hs);
    // pre-split constant weights
    k_split_b<<<(Cq * VP / 2) / 256, 256>>>(lmh, bhi, blo);
    k_split_a<<<((size_t)Eq * Cq * Fq / 2) / 256, 256>>>(w1, w1h, w1l);
    k_split_a<<<((size_t)Eq * Fq * Cq / 2) / 256, 256>>>(w2, w2h, w2l);

    k_layernorm<<<Nq, Cq>>>(hs, x, ln1w, ln1b);

    dim3 gP(Cq / 64, Nq / 64);
    k_sgemm<<<gP, 256>>>(x, wq, q, Nq, Cq, Cq, 0);
    k_sgemm<<<gP, 256>>>(x, wk, k, Nq, Cq, Cq, 0);
    k_sgemm<<<gP, 256>>>(x, wv, v, Nq, Cq, Cq, 0);

    k_attn<<<dim3(Tq / 64, Hq, Bq), 64>>>(q, k, v, ao);
    k_sgemm<<<gP, 256>>>(ao, wo, hs, Nq, Cq, Cq, 1);

    k_layernorm<<<Nq, Cq>>>(hs, xt, ln2w, ln2b);
    k_simnorm<<<1, 256>>>(sim, sn);
    k_gate_logits<<<Nq / 8, 256>>>(xt, sn, logits);
    k_gate<<<Nq / 8, 256>>>(logits, gates, pre_o, am_o, rw);

    // MoE on HMMA tensor cores (bf16 3-split)
    k_split_a<<<(Nq * Cq / 2) / 256, 256>>>(xt, xhi, xlo);
    cudaFuncSetAttribute(k_moe_mma, cudaFuncAttributeMaxDynamicSharedMemorySize, MM_SMEM);
    // up-proj: H = gelu(X @ W1e)  [grid: 8 n-tiles, 16 m-tiles, 32 experts]
    k_moe_mma<<<dim3(Fq / 128, Nq / 128, Eq), 256, MM_SMEM>>>(
        xhi, xlo, w1h, w1l, nullptr, hh, hl, nullptr, Cq, Cq, Fq, 0, 0);
    // down-proj: feo = mask * (H @ W2e)  [grid: 2 n-tiles, 16 m-tiles, 32 experts]
    k_moe_mma<<<dim3(Cq / 128, Nq / 128, Eq), 256, MM_SMEM>>>(
        hh, hl, w2h, w2l, am_o, nullptr, nullptr, feo, Fq, Fq, Cq, Nq * Fq, 1);

    k_combine<<<Nq, Cq>>>(rw, feo, hs);

    // lm_head on HMMA tensor cores (bf16 3-split)
    k_split_a<<<(Nq * Cq / 2) / 256, 256>>>(hs, ahi, alo);
    cudaFuncSetAttribute(k_lmhead_mma, cudaFuncAttributeMaxDynamicSharedMemorySize, LM_SMEM);
    k_lmhead_mma<<<VP / 128, 256, LM_SMEM>>>(ahi, alo, bhi, blo, out);
}

// round 7
// speedup vs baseline: 3.4063x; 1.6109x over previous
#include <cuda_runtime.h>
#include <cuda_bf16.h>
#include <math.h>
#include <stdint.h>

// ---------------- problem constants ----------------
static constexpr int Bq = 2;
static constexpr int Tq = 1024;
static constexpr int Cq = 256;
static constexpr int Fq = 1024;
static constexpr int Eq = 32;
static constexpr int Vq = 50257;
static constexpr int Hq = 8;
static constexpr int Dq = 32;      // Cq / Hq
static constexpr int Nq = Bq * Tq; // 2048 tokens
static constexpr int VP = 50304;   // Vq padded to 128 (393 tiles)

// ---------------- device scratch (no allocations allowed) ----------------
__device__ float g_hs[Nq * Cq];
__device__ float g_x[Nq * Cq];
__device__ float g_q[Nq * Cq];
__device__ float g_k[Nq * Cq];
__device__ float g_v[Nq * Cq];
__device__ float g_ao[Nq * Cq];
__device__ float g_xt[Nq * Cq];
__device__ float g_sn[Cq * Eq];
__device__ float g_logits[Nq * Eq];
__device__ float g_rw[Nq * Eq];
__device__ float g_feo[(size_t)Nq * Eq * Cq];
__device__ float g_pre[Nq * Eq];
__device__ float g_am[Nq * Eq];
// bf16 hi/lo splits
__device__ __nv_bfloat16 g_ahi[Nq * Cq];           // x -> ao -> hs (sequential reuse)
__device__ __nv_bfloat16 g_alo[Nq * Cq];
__device__ __nv_bfloat16 g_bhi[(size_t)Cq * VP];   // lm_head
__device__ __nv_bfloat16 g_blo[(size_t)Cq * VP];
__device__ __nv_bfloat16 g_xhi[Nq * Cq];           // xt (MoE)
__device__ __nv_bfloat16 g_xlo[Nq * Cq];
__device__ __nv_bfloat16 g_w1h[(size_t)Eq * Cq * Fq];
__device__ __nv_bfloat16 g_w1l[(size_t)Eq * Cq * Fq];
__device__ __nv_bfloat16 g_w2h[(size_t)Eq * Fq * Cq];
__device__ __nv_bfloat16 g_w2l[(size_t)Eq * Fq * Cq];
__device__ __nv_bfloat16 g_wph[4 * Cq * Cq];       // wq|wk|wv|wo hi
__device__ __nv_bfloat16 g_wpl[4 * Cq * Cq];       // wq|wk|wv|wo lo
__device__ __nv_bfloat16 g_hh[(size_t)Eq * Nq * Fq];
__device__ __nv_bfloat16 g_hl[(size_t)Eq * Nq * Fq];

// ================= helpers =================
__device__ __forceinline__ uint32_t smem_u32(const void* p) {
    uint32_t a;
    asm("{ .reg .u64 t; cvta.to.shared.u64 t, %1; cvt.u32.u64 %0, t; }" : "=r"(a) : "l"(p));
    return a;
}
__device__ __forceinline__ void split_bf16(float f, uint16_t& hi, uint16_t& lo) {
    __nv_bfloat16 h = __float2bfloat16(f);
    hi = __bfloat16_as_ushort(h);
    lo = __bfloat16_as_ushort(__float2bfloat16(f - __bfloat162float(h)));
}
__device__ __forceinline__ void cp16(uint32_t dst, const void* gsrc) {
    uint64_t g = __cvta_generic_to_global(gsrc);
    asm volatile("cp.async.ca.shared.global [%0], [%1], 16;" :: "r"(dst), "l"(g));
}
__device__ __forceinline__ void cp_commit() { asm volatile("cp.async.commit_group;"); }
__device__ __forceinline__ void cp_wait1() { asm volatile("cp.async.wait_group 1;" ::: "memory"); }
__device__ __forceinline__ void cp_wait0() { asm volatile("cp.async.wait_group 0;" ::: "memory"); }
__device__ __forceinline__ void ldsm_x4(uint32_t* r, uint32_t a) {
    asm volatile("ldmatrix.sync.aligned.m8n8.x4.shared.b16 {%0,%1,%2,%3}, [%4];"
                 : "=r"(r[0]), "=r"(r[1]), "=r"(r[2]), "=r"(r[3]) : "r"(a) : "memory");
}
__device__ __forceinline__ void ldsm_x4_t(uint32_t* r, uint32_t a) {
    asm volatile("ldmatrix.sync.aligned.m8n8.x4.trans.shared.b16 {%0,%1,%2,%3}, [%4];"
                 : "=r"(r[0]), "=r"(r[1]), "=r"(r[2]), "=r"(r[3]) : "r"(a) : "memory");
}
__device__ __forceinline__ void mma16816(float* c, const uint32_t* a, uint32_t b0, uint32_t b1) {
    asm volatile(
        "mma.sync.aligned.m16n8k16.row.col.f32.bf16.bf16.f32 "
        "{%0,%1,%2,%3}, {%4,%5,%6,%7}, {%8,%9}, {%0,%1,%2,%3};"
        : "+f"(c[0]), "+f"(c[1]), "+f"(c[2]), "+f"(c[3])
        : "r"(a[0]), "r"(a[1]), "r"(a[2]), "r"(a[3]), "r"(b0), "r"(b1));
}
__device__ __forceinline__ float gelu_exact(float x) {
    return 0.5f * x * (1.0f + erff(x * 0.70710678118654752f));
}

// ---------------- split kernels (fp32 -> bf16 hi/lo) ----------------
__global__ void k_split_a(const float* __restrict__ src, __nv_bfloat16* __restrict__ hi,
                          __nv_bfloat16* __restrict__ lo) {
    size_t i = (size_t)blockIdx.x * 256 + threadIdx.x; // pair index
    float2 v = *(const float2*)&src[i * 2];
    uint16_t h0, l0, h1, l1;
    split_bf16(v.x, h0, l0);
    split_bf16(v.y, h1, l1);
    ((uint32_t*)hi)[i] = (uint32_t)h0 | ((uint32_t)h1 << 16);
    ((uint32_t*)lo)[i] = (uint32_t)l0 | ((uint32_t)l1 << 16);
}
__global__ void k_split_b(const float* __restrict__ src, __nv_bfloat16* __restrict__ hi,
                          __nv_bfloat16* __restrict__ lo) {
    int p = blockIdx.x * 256 + threadIdx.x;
    int k = p / (VP / 2);
    int n = (p - k * (VP / 2)) * 2;
    float v0 = (n < Vq) ? src[(size_t)k * Vq + n] : 0.f;
    float v1 = (n + 1 < Vq) ? src[(size_t)k * Vq + n + 1] : 0.f;
    uint16_t h0, l0, h1, l1;
    split_bf16(v0, h0, l0);
    split_bf16(v1, h1, l1);
    ((uint32_t*)hi)[p] = (uint32_t)h0 | ((uint32_t)h1 << 16);
    ((uint32_t*)lo)[p] = (uint32_t)l0 | ((uint32_t)l1 << 16);
}

// ================= generic HMMA GEMM (bf16 3-split) =================
// Per CTA: 128m x 128n tile, K chunked by 64, cp.async double buffer.
// epi=0: O = gelu(A@B) -> split bf16 -> Oh/Ol, layout [e][Nq][Fq]
// epi=1: feo[(t*Eq+e)*Cq] = amask * (A@B), fp32 coalesced
// epi=2: out[m*ldo+n] = A@B (+ res[m*ldo+n] if res)
static constexpr int MM_SMEM = 131072;

__global__ void __launch_bounds__(256, 1) k_gemm_mma(
    const __nv_bfloat16* __restrict__ Ah, const __nv_bfloat16* __restrict__ Al,
    const __nv_bfloat16* __restrict__ Bh, const __nv_bfloat16* __restrict__ Bl,
    const float* __restrict__ amask,
    __nv_bfloat16* __restrict__ Oh, __nv_bfloat16* __restrict__ Ol,
    float* __restrict__ fout, const float* __restrict__ res,
    int K, int lda, int ldb, int ldo, int aExpStride, int epi) {
    extern __shared__ char smem[];
    uint32_t sb = smem_u32(smem);
    int tid = threadIdx.x, wid = tid >> 5, lane = tid & 31;
    int wm = wid >> 2, wn = wid & 3;    // warp grid 2m x 4n, warp tile 64x32
    int g = lane >> 3, gr = lane & 7;
    int n0 = blockIdx.x * 128, m0 = blockIdx.y * 128, e = blockIdx.z;

    const __nv_bfloat16* Abh = Ah + (size_t)e * aExpStride;
    const __nv_bfloat16* Abl = Al + (size_t)e * aExpStride;
    const __nv_bfloat16* Bbh = Bh + (size_t)e * K * ldb + n0;
    const __nv_bfloat16* Bbl = Bl + (size_t)e * K * ldb + n0;

    auto copyChunk = [&](int ch) {
        uint32_t base = sb + (ch & 1) * 65536;
        int kc = ch * 64;
#pragma unroll
        for (int it = 0; it < 8; it++) {         // A: [128m][64k] hi+lo
            int lin = tid + it * 256;
            int half = lin >> 10;
            int r = lin & 1023;
            int m = r >> 3, k8 = r & 7;
            uint32_t dst = base + half * 16384 + m * 128 + (((k8 ^ (m & 7))) << 4);
            cp16(dst, (half ? Abl : Abh) + (size_t)(m0 + m) * lda + kc + k8 * 8);
        }
#pragma unroll
        for (int it = 0; it < 8; it++) {         // B: [64k][128n] hi+lo
            int lin = tid + it * 256;
            int half = lin >> 10;
            int r = lin & 1023;
            int k = r >> 4, n8 = r & 15;
            uint32_t dst = base + 32768 + half * 16384 + k * 256 + (((n8 ^ (k & 7))) << 4);
            cp16(dst, (half ? Bbl : Bbh) + (size_t)(kc + k) * ldb + n8 * 8);
        }
    };

    float acc[4][4][4];
#pragma unroll
    for (int a = 0; a < 4; a++)
#pragma unroll
        for (int b = 0; b < 4; b++)
#pragma unroll
            for (int c = 0; c < 4; c++) acc[a][b][c] = 0.f;

    const int k_extra = (g & 1) * 8;
    const int n_extra = (g >> 1) * 8;
    const int nch = K / 64;

    copyChunk(0);
    cp_commit();
    for (int t = 0; t < nch; t++) {
        if (t + 1 < nch) { copyChunk(t + 1); cp_commit(); cp_wait1(); }
        else cp_wait0();
        __syncthreads();
        uint32_t ab = sb + (t & 1) * 65536;
        uint32_t bb = ab + 32768;
#pragma unroll
        for (int ks = 0; ks < 4; ks++) {
            uint32_t Bhf[2][4], Blf[2][4];
#pragma unroll
            for (int b = 0; b < 2; b++) {
                int kx = ks * 16 + k_extra + gr;
                int nf = wn * 32 + b * 16 + n_extra;
                uint32_t off = kx * 256 + ((((nf >> 3) ^ (kx & 7))) << 4);
                ldsm_x4_t(Bhf[b], bb + off);
                ldsm_x4_t(Blf[b], bb + 16384 + off);
            }
#pragma unroll
            for (int ma = 0; ma < 4; ma++) {
                int rowa = wm * 64 + ma * 16 + (g & 1) * 8 + gr;
                int kk = ks * 16 + n_extra;
                uint32_t ao = rowa * 128 + ((((kk >> 3) ^ (rowa & 7))) << 4);
                uint32_t Ahf[4], Alf[4];
                ldsm_x4(Ahf, ab + ao);
                ldsm_x4(Alf, ab + 16384 + ao);
#pragma unroll
                for (int b = 0; b < 2; b++) {
                    mma16816(acc[ma][2 * b],     Ahf, Bhf[b][0], Bhf[b][1]);
                    mma16816(acc[ma][2 * b],     Ahf, Blf[b][0], Blf[b][1]);
                    mma16816(acc[ma][2 * b],     Alf, Bhf[b][0], Bhf[b][1]);
                    mma16816(acc[ma][2 * b + 1], Ahf, Bhf[b][2], Bhf[b][3]);
                    mma16816(acc[ma][2 * b + 1], Ahf, Blf[b][2], Blf[b][3]);
                    mma16816(acc[ma][2 * b + 1], Alf, Bhf[b][2], Bhf[b][3]);
                }
            }
        }
        __syncthreads();
    }

    // ---- SMEM-staged epilogue: stage [128][132] fp32, then coalesced stores ----
    float* stage = (float*)smem;
#pragma unroll
    for (int ma = 0; ma < 4; ma++) {
        int lr = wm * 64 + ma * 16 + (lane >> 2);
#pragma unroll
        for (int na = 0; na < 4; na++) {
            int lc = wn * 32 + na * 8 + (lane & 3) * 2;
            float v0 = acc[ma][na][0], v1 = acc[ma][na][1];
            float v2 = acc[ma][na][2], v3 = acc[ma][na][3];
            if (epi == 0) { v0 = gelu_exact(v0); v1 = gelu_exact(v1);
                            v2 = gelu_exact(v2); v3 = gelu_exact(v3); }
            stage[lr * 132 + lc] = v0;
            stage[lr * 132 + lc + 1] = v1;
            stage[(lr + 8) * 132 + lc] = v2;
            stage[(lr + 8) * 132 + lc + 1] = v3;
        }
    }
    __syncthreads();

    if (epi == 0) {
        // pack to bf16 hi/lo, 16B stores
#pragma unroll
        for (int it = 0; it < 8; it++) {
            int idx = tid + it * 256;       // 0..2047 (128 rows x 16 col8-groups)
            int r = idx >> 4, c8 = (idx & 15) * 8;
            float4 a = *(float4*)&stage[r * 132 + c8];
            float4 b = *(float4*)&stage[r * 132 + c8 + 4];
            uint16_t h[8], l[8];
            split_bf16(a.x, h[0], l[0]); split_bf16(a.y, h[1], l[1]);
            split_bf16(a.z, h[2], l[2]); split_bf16(a.w, h[3], l[3]);
            split_bf16(b.x, h[4], l[4]); split_bf16(b.y, h[5], l[5]);
            split_bf16(b.z, h[6], l[6]); split_bf16(b.w, h[7], l[7]);
            size_t o = ((size_t)e * Nq + m0 + r) * Fq + n0 + c8;
            *(uint4*)(Oh + o) = make_uint4(
                (uint32_t)h[0] | ((uint32_t)h[1] << 16), (uint32_t)h[2] | ((uint32_t)h[3] << 16),
                (uint32_t)h[4] | ((uint32_t)h[5] << 16), (uint32_t)h[6] | ((uint32_t)h[7] << 16));
            *(uint4*)(Ol + o) = make_uint4(
                (uint32_t)l[0] | ((uint32_t)l[1] << 16), (uint32_t)l[2] | ((uint32_t)l[3] << 16),
                (uint32_t)l[4] | ((uint32_t)l[5] << 16), (uint32_t)l[6] | ((uint32_t)l[7] << 16));
        }
    } else if (epi == 1) {
#pragma unroll
        for (int it = 0; it < 16; it++) {
            int idx = tid + it * 256;       // 0..4095 (128 rows x 32 float4)
            int r = idx >> 5, c4 = (idx & 31) * 4;
            float mm = amask[(size_t)(m0 + r) * Eq + e];
            float4 v = *(float4*)&stage[r * 132 + c4];
            v.x *= mm; v.y *= mm; v.z *= mm; v.w *= mm;
            *(float4*)&fout[((size_t)(m0 + r) * Eq + e) * Cq + n0 + c4] = v;
        }
    } else {
#pragma unroll
        for (int it = 0; it < 16; it++) {
            int idx = tid + it * 256;
            int r = idx >> 5, c4 = (idx & 31) * 4;
            float4 v = *(float4*)&stage[r * 132 + c4];
            size_t o = (size_t)(m0 + r) * ldo + n0 + c4;
            if (res) {
                float4 rr = *(const float4*)&res[o];
                v.x += rr.x; v.y += rr.y; v.z += rr.z; v.w += rr.w;
            }
            *(float4*)&fout[o] = v;
        }
    }
}

// ================= lm_head HMMA GEMM =================
static constexpr int SM_B_HI = 0;
static constexpr int SM_B_LO = 65536;
static constexpr int SM_A    = 131072;
static constexpr int LM_SMEM = 196608;

__global__ void __launch_bounds__(256, 1) k_lmhead_mma(const __nv_bfloat16* __restrict__ Ah,
                                                       const __nv_bfloat16* __restrict__ Al,
                                                       const __nv_bfloat16* __restrict__ Bh,
                                                       const __nv_bfloat16* __restrict__ Bl,
                                                       float* __restrict__ out) {
    extern __shared__ char smem[];
    uint32_t sb = smem_u32(smem);
    int tid = threadIdx.x;
    int wid = tid >> 5, lane = tid & 31;
    int wm = wid >> 2, wn = wid & 3;
    int g = lane >> 3, gr = lane & 7;
    int n0 = blockIdx.x * 128;

#pragma unroll
    for (int it = 0; it < 32; it++) {
        int lin = tid + it * 256;
        int half = lin >> 12;
        int r = lin & 4095;
        int k = r >> 4, n8 = r & 15;
        uint32_t dst = sb + (half ? SM_B_LO : SM_B_HI) + k * 256 + (((n8 ^ (k & 7))) << 4);
        const __nv_bfloat16* srcb = (half ? Bl : Bh) + (size_t)k * VP + n0 + n8 * 8;
        cp16(dst, srcb);
    }
    auto copyA = [&](int t) {
        int mb = t >> 2;
        int kc = (t & 3) * 64;
        uint32_t abase = sb + SM_A + (t & 1) * 32768;
#pragma unroll
        for (int it = 0; it < 8; it++) {
            int lin = tid + it * 256;
            int half = lin >> 10;
            int r = lin & 1023;
            int m = r >> 3, k8 = r & 7;
            uint32_t dst = abase + half * 16384 + m * 128 + (((k8 ^ (m & 7))) << 4);
            const __nv_bfloat16* srca = (half ? Al : Ah) + (size_t)(mb * 128 + m) * Cq + kc + k8 * 8;
            cp16(dst, srca);
        }
    };
    copyA(0);
    cp_commit();

    float acc[4][4][4];
#pragma unroll
    for (int a = 0; a < 4; a++)
#pragma unroll
        for (int b = 0; b < 4; b++)
#pragma unroll
            for (int c = 0; c < 4; c++) acc[a][b][c] = 0.f;

    const int k_extra = (g & 1) * 8;
    const int n_extra = (g >> 1) * 8;

    for (int t = 0; t < 64; t++) {
        if (t + 1 < 64) { copyA(t + 1); cp_commit(); cp_wait1(); }
        else cp_wait0();
        __syncthreads();

        int kc = (t & 3) * 64;
        uint32_t ah_base = sb + SM_A + (t & 1) * 32768;
        uint32_t al_base = ah_base + 16384;
#pragma unroll
        for (int ks = 0; ks < 4; ks++) {
            uint32_t Bhf[2][4], Blf[2][4];
#pragma unroll
            for (int b = 0; b < 2; b++) {
                int kx = kc + ks * 16 + k_extra + gr;
                int nf = wn * 32 + b * 16 + n_extra;
                uint32_t off = kx * 256 + ((((nf >> 3) ^ (kx & 7))) << 4);
                ldsm_x4_t(Bhf[b], sb + SM_B_HI + off);
                ldsm_x4_t(Blf[b], sb + SM_B_LO + off);
            }
#pragma unroll
            for (int ma = 0; ma < 4; ma++) {
                int rowa = wm * 64 + ma * 16 + (g & 1) * 8 + gr;
                int kkl = ks * 16 + n_extra;
                uint32_t ao = rowa * 128 + ((((kkl >> 3) ^ (rowa & 7))) << 4);
                uint32_t Ahf[4], Alf[4];
                ldsm_x4(Ahf, ah_base + ao);
                ldsm_x4(Alf, al_base + ao);
#pragma unroll
                for (int b = 0; b < 2; b++) {
                    mma16816(acc[ma][2 * b],     Ahf, Bhf[b][0], Bhf[b][1]);
                    mma16816(acc[ma][2 * b],     Ahf, Blf[b][0], Blf[b][1]);
                    mma16816(acc[ma][2 * b],     Alf, Bhf[b][0], Bhf[b][1]);
                    mma16816(acc[ma][2 * b + 1], Ahf, Bhf[b][2], Bhf[b][3]);
                    mma16816(acc[ma][2 * b + 1], Ahf, Blf[b][2], Blf[b][3]);
                    mma16816(acc[ma][2 * b + 1], Alf, Bhf[b][2], Bhf[b][3]);
                }
            }
        }
        if ((t & 3) == 3) {
            // scalar stores: out row stride Vq=50257 is ODD -> float2 would be
            // misaligned on odd rows. Keep 4B stores.
            int mbase = (t >> 2) * 128 + wm * 64;
#pragma unroll
            for (int ma = 0; ma < 4; ma++) {
#pragma unroll
                for (int na = 0; na < 4; na++) {
                    int gm = mbase + ma * 16 + (lane >> 2);
                    int gn = n0 + wn * 32 + na * 8 + (lane & 3) * 2;
                    float* p0 = out + (size_t)gm * Vq + gn;
                    float* p1 = out + (size_t)(gm + 8) * Vq + gn;
                    if (gn < Vq)     { p0[0] = acc[ma][na][0]; p1[0] = acc[ma][na][2]; }
                    if (gn + 1 < Vq) { p0[1] = acc[ma][na][1]; p1[1] = acc[ma][na][3]; }
                    acc[ma][na][0] = acc[ma][na][1] = acc[ma][na][2] = acc[ma][na][3] = 0.f;
                }
            }
        }
        __syncthreads();
    }
}

// ---------------- embedding ----------------
__global__ void k_embed(const int* __restrict__ ids, const float* __restrict__ emb,
                        float* __restrict__ hs) {
    int t = blockIdx.x, c = threadIdx.x;
    hs[(size_t)t * Cq + c] = emb[(size_t)ids[t] * Cq + c];
}

// ---------------- layernorm ----------------
__global__ void k_layernorm(const float* __restrict__ in, float* __restrict__ out,
                            const float* __restrict__ w, const float* __restrict__ b) {
    int t = blockIdx.x, c = threadIdx.x;
    float x = in[(size_t)t * Cq + c];
    __shared__ float red[8];
    float s = x;
#pragma unroll
    for (int o = 16; o; o >>= 1) s += __shfl_xor_sync(0xffffffffu, s, o);
    if ((c & 31) == 0) red[c >> 5] = s;
    __syncthreads();
    float mu = 0.f;
#pragma unroll
    for (int i = 0; i < 8; i++) mu += red[i];
    mu *= (1.f / Cq);
    float d = x - mu;
    float s2 = d * d;
#pragma unroll
    for (int o = 16; o; o >>= 1) s2 += __shfl_xor_sync(0xffffffffu, s2, o);
    __syncthreads();
    if ((c & 31) == 0) red[c >> 5] = s2;
    __syncthreads();
    float var = 0.f;
#pragma unroll
    for (int i = 0; i < 8; i++) var += red[i];
    var *= (1.f / Cq);
    out[(size_t)t * Cq + c] = d * rsqrtf(var + 1e-5f) * w[c] + b[c];
}

// ---------------- causal attention ----------------
__global__ void k_attn(const float* __restrict__ q, const float* __restrict__ k,
                       const float* __restrict__ v, float* __restrict__ o) {
    int b = blockIdx.z, h = blockIdx.y;
    int t0 = blockIdx.x * 64;
    int qi = t0 + threadIdx.x;
    const float scale = 0.17677669529663687f;
    float qr[Dq];
    const float* qp = q + ((size_t)(b * Tq + qi)) * Cq + h * Dq;
#pragma unroll
    for (int d = 0; d < Dq; d++) qr[d] = qp[d] * scale;
    float acc[Dq];
#pragma unroll
    for (int d = 0; d < Dq; d++) acc[d] = 0.f;
    float m = -INFINITY, l = 0.f;
    __shared__ float Ks[64 * Dq], Vs[64 * Dq];

    for (int kt = 0; kt < t0 + 64; kt += 64) {
        for (int i = threadIdx.x; i < 64 * Dq; i += 64) {
            int r = i >> 5, d = i & 31;
            size_t gi = ((size_t)(b * Tq + kt + r)) * Cq + h * Dq + d;
            Ks[i] = k[gi];
            Vs[i] = v[gi];
        }
        __syncthreads();
        int jmax = qi - kt + 1;
        if (jmax > 64) jmax = 64;
        for (int j = 0; j < jmax; j++) {
            float s = 0.f;
#pragma unroll
            for (int d = 0; d < Dq; d++) s += qr[d] * Ks[j * Dq + d];
            float nm = fmaxf(m, s);
            float corr = expf(m - nm);
            float p = expf(s - nm);
            l = l * corr + p;
#pragma unroll
            for (int d = 0; d < Dq; d++) acc[d] = acc[d] * corr + p * Vs[j * Dq + d];
            m = nm;
        }
        __syncthreads();
    }
    float inv = 1.f / l;
    float* op = o + ((size_t)(b * Tq + qi)) * Cq + h * Dq;
#pragma unroll
    for (int d = 0; d < Dq; d++) op[d] = acc[d] * inv;
}

// ---------------- normalize sim_matrix columns ----------------
__global__ void k_simnorm(const float* __restrict__ sim, float* __restrict__ sn) {
    __shared__ float ps[8][32];
    __shared__ float inv[32];
    int tid = threadIdx.x;
    int e = tid & 31, part = tid >> 5;
    float s = 0.f;
    for (int c = part * 32; c < part * 32 + 32; c++) {
        float vv = sim[(size_t)c * Eq + e];
        s += vv * vv;
    }
    ps[part][e] = s;
    __syncthreads();
    if (tid < 32) {
        float tot = 0.f;
#pragma unroll
        for (int p = 0; p < 8; p++) tot += ps[p][tid];
        inv[tid] = 1.f / fmaxf(sqrtf(tot), 1e-12f);
    }
    __syncthreads();
    for (int i = tid; i < Cq * Eq; i += 256) sn[i] = sim[i] * inv[i & 31];
}

// ---------------- gate logits ----------------
__global__ void k_gate_logits(const float* __restrict__ xt, const float* __restrict__ sn,
                              float* __restrict__ logits) {
    __shared__ float xs[8 * Cq];
    int tid = threadIdx.x;
    int t0 = blockIdx.x * 8;
    for (int i = tid; i < 8 * Cq; i += 256) xs[i] = xt[(size_t)t0 * Cq + i];
    __syncthreads();
    int w = tid >> 5, lane = tid & 31;
    int t = t0 + w;
    float s = 0.f;
    for (int c = lane; c < Cq; c += 32) {
        float vv = xs[w * Cq + c];
        s += vv * vv;
    }
#pragma unroll
    for (int o = 16; o; o >>= 1) s += __shfl_xor_sync(0xffffffffu, s, o);
    float inv = 1.f / fmaxf(sqrtf(s), 1e-12f);
    float acc = 0.f;
    for (int c = 0; c < Cq; c++) acc += xs[w * Cq + c] * sn[c * Eq + lane];
    logits[(size_t)t * Eq + lane] = acc * inv;
}

// ---------------- gate decision + routing softmax ----------------
__global__ void k_gate(const float* __restrict__ logits, const float* __restrict__ gates,
                       float* __restrict__ pre_o, float* __restrict__ am_o,
                       float* __restrict__ rw) {
    int w = threadIdx.x >> 5, lane = threadIdx.x & 31;
    int t = blockIdx.x * 8 + w;
    float lg = logits[(size_t)t * Eq + lane];
    float pre = lg - 1.f / (1.f + expf(-gates[lane]));
    float gated = fmaxf(pre, 0.f);
    unsigned act = __ballot_sync(0xffffffffu, pre > 0.f);
    float am;
    if (act == 0u) {
        int rank = 0;
#pragma unroll
        for (int j = 0; j < 32; j++) {
            float lj = __shfl_sync(0xffffffffu, lg, j);
            rank += (lj > lg) || (lj == lg && j < lane);
        }
        am = (rank < 16) ? 1.f : 0.f;
    } else {
        am = (pre > 0.f) ? 1.f : 0.f;
    }
    float g2 = (am > 0.f) ? gated : -INFINITY;
    float mx = g2;
#pragma unroll
    for (int o = 16; o; o >>= 1) mx = fmaxf(mx, __shfl_xor_sync(0xffffffffu, mx, o));
    float p = (am > 0.f) ? expf(gated - mx) : 0.f;
    float sum = p;
#pragma unroll
    for (int o = 16; o; o >>= 1) sum += __shfl_xor_sync(0xffffffffu, sum, o);
    rw[(size_t)t * Eq + lane] = p / sum;
    pre_o[(size_t)t * Eq + lane] = pre;
    am_o[(size_t)t * Eq + lane] = am;
}

// ---------------- combine ----------------
__global__ void k_combine(const float* __restrict__ rw, const float* __restrict__ feo,
                          float* __restrict__ hs) {
    int t = blockIdx.x, c = threadIdx.x;
    float s = hs[(size_t)t * Cq + c];
#pragma unroll
    for (int e = 0; e < Eq; e++)
        s += rw[(size_t)t * Eq + e] * feo[((size_t)t * Eq + e) * Cq + c];
    hs[(size_t)t * Cq + c] = s;
}

// ---------------- host ----------------
extern "C" void kernel_launch(void* const* d_in, const int* in_sizes, int n_in,
                              void* d_out, int out_size) {
    const int*   ids   = (const int*)d_in[0];
    const float* emb   = (const float*)d_in[1];
    const float* wq    = (const float*)d_in[2];
    const float* wk    = (const float*)d_in[3];
    const float* wv    = (const float*)d_in[4];
    const float* wo    = (const float*)d_in[5];
    const float* ln1w  = (const float*)d_in[6];
    const float* ln1b  = (const float*)d_in[7];
    const float* ln2w  = (const float*)d_in[8];
    const float* ln2b  = (const float*)d_in[9];
    const float* sim   = (const float*)d_in[10];
    const float* gates = (const float*)d_in[11];
    const float* w1    = (const float*)d_in[12];
    const float* w2    = (const float*)d_in[13];
    const float* lmh   = (const float*)d_in[14];

    float *hs, *x, *q, *k, *v, *ao, *xt, *sn, *logits, *rw, *feo_s, *pre_s, *am_s;
    __nv_bfloat16 *ahi, *alo, *bhi, *blo, *xhi, *xlo, *w1h, *w1l, *w2h, *w2l, *wph, *wpl, *hh, *hl;
    cudaGetSymbolAddress((void**)&hs, g_hs);
    cudaGetSymbolAddress((void**)&x, g_x);
    cudaGetSymbolAddress((void**)&q, g_q);
    cudaGetSymbolAddress((void**)&k, g_k);
    cudaGetSymbolAddress((void**)&v, g_v);
    cudaGetSymbolAddress((void**)&ao, g_ao);
    cudaGetSymbolAddress((void**)&xt, g_xt);
    cudaGetSymbolAddress((void**)&sn, g_sn);
    cudaGetSymbolAddress((void**)&logits, g_logits);
    cudaGetSymbolAddress((void**)&rw, g_rw);
    cudaGetSymbolAddress((void**)&feo_s, g_feo);
    cudaGetSymbolAddress((void**)&pre_s, g_pre);
    cudaGetSymbolAddress((void**)&am_s, g_am);
    cudaGetSymbolAddress((void**)&ahi, g_ahi);
    cudaGetSymbolAddress((void**)&alo, g_alo);
    cudaGetSymbolAddress((void**)&bhi, g_bhi);
    cudaGetSymbolAddress((void**)&blo, g_blo);
    cudaGetSymbolAddress((void**)&xhi, g_xhi);
    cudaGetSymbolAddress((void**)&xlo, g_xlo);
    cudaGetSymbolAddress((void**)&w1h, g_w1h);
    cudaGetSymbolAddress((void**)&w1l, g_w1l);
    cudaGetSymbolAddress((void**)&w2h, g_w2h);
    cudaGetSymbolAddress((void**)&w2l, g_w2l);
    cudaGetSymbolAddress((void**)&wph, g_wph);
    cudaGetSymbolAddress((void**)&wpl, g_wpl);
    cudaGetSymbolAddress((void**)&hh, g_hh);
    cudaGetSymbolAddress((void**)&hl, g_hl);

    float* out = (float*)d_out;
    const size_t NV  = (size_t)Nq * Vq;
    const size_t FEO = (size_t)Nq * Eq * Cq;
    const size_t NE  = (size_t)Nq * Eq;
    float *feo, *pre_o, *am_o;
    if ((size_t)out_size >= NV + FEO + 2 * NE) {
        feo = out + NV;
        pre_o = out + NV + FEO;
        am_o = pre_o + NE;
    } else {
        feo = feo_s; pre_o = pre_s; am_o = am_s;
    }

    cudaFuncSetAttribute(k_gemm_mma, cudaFuncAttributeMaxDynamicSharedMemorySize, MM_SMEM);
    cudaFuncSetAttribute(k_lmhead_mma, cudaFuncAttributeMaxDynamicSharedMemorySize, LM_SMEM);

    k_embed<<<Nq, Cq>>>(ids, emb, hs);
    // pre-split constant weights
    k_split_b<<<(Cq * VP / 2) / 256, 256>>>(lmh, bhi, blo);
    k_split_a<<<((size_t)Eq * Cq * Fq / 2) / 256, 256>>>(w1, w1h, w1l);
    k_split_a<<<((size_t)Eq * Fq * Cq / 2) / 256, 256>>>(w2, w2h, w2l);
    k_split_a<<<(Cq * Cq / 2) / 256, 256>>>(wq, wph, wpl);
    k_split_a<<<(Cq * Cq / 2) / 256, 256>>>(wk, wph + Cq * Cq, wpl + Cq * Cq);
    k_split_a<<<(Cq * Cq / 2) / 256, 256>>>(wv, wph + 2 * Cq * Cq, wpl + 2 * Cq * Cq);
    k_split_a<<<(Cq * Cq / 2) / 256, 256>>>(wo, wph + 3 * Cq * Cq, wpl + 3 * Cq * Cq);

    k_layernorm<<<Nq, Cq>>>(hs, x, ln1w, ln1b);
    k_split_a<<<(Nq * Cq / 2) / 256, 256>>>(x, ahi, alo);

    // QKV on HMMA (epi=2)
    dim3 gQ(Cq / 128, Nq / 128);
    k_gemm_mma<<<gQ, 256, MM_SMEM>>>(ahi, alo, wph, wpl, nullptr, nullptr, nullptr,
                                     q, nullptr, Cq, Cq, Cq, Cq, 0, 2);
    k_gemm_mma<<<gQ, 256, MM_SMEM>>>(ahi, alo, wph + Cq * Cq, wpl + Cq * Cq, nullptr,
                                     nullptr, nullptr, k, nullptr, Cq, Cq, Cq, Cq, 0, 2);
    k_gemm_mma<<<gQ, 256, MM_SMEM>>>(ahi, alo, wph + 2 * Cq * Cq, wpl + 2 * Cq * Cq, nullptr,
                                     nullptr, nullptr, v, nullptr, Cq, Cq, Cq, Cq, 0, 2);

    k_attn<<<dim3(Tq / 64, Hq, Bq), 64>>>(q, k, v, ao);

    // hs = hs + ao @ wo  (epi=2 with residual)
    k_split_a<<<(Nq * Cq / 2) / 256, 256>>>(ao, ahi, alo);
    k_gemm_mma<<<gQ, 256, MM_SMEM>>>(ahi, alo, wph + 3 * Cq * Cq, wpl + 3 * Cq * Cq, nullptr,
                                     nullptr, nullptr, hs, hs, Cq, Cq, Cq, Cq, 0, 2);

    k_layernorm<<<Nq, Cq>>>(hs, xt, ln2w, ln2b);
    k_simnorm<<<1, 256>>>(sim, sn);
    k_gate_logits<<<Nq / 8, 256>>>(xt, sn, logits);
    k_gate<<<Nq / 8, 256>>>(logits, gates, pre_o, am_o, rw);

    // MoE on HMMA (bf16 3-split)
    k_split_a<<<(Nq * Cq / 2) / 256, 256>>>(xt, xhi, xlo);
    k_gemm_mma<<<dim3(Fq / 128, Nq / 128, Eq), 256, MM_SMEM>>>(
        xhi, xlo, w1h, w1l, nullptr, hh, hl, nullptr, nullptr, Cq, Cq, Fq, 0, 0, 0);
    k_gemm_mma<<<dim3(Cq / 128, Nq / 128, Eq), 256, MM_SMEM>>>(
        hh, hl, w2h, w2l, am_o, nullptr, nullptr, feo, nullptr, Fq, Fq, Cq, 0, Nq * Fq, 1);

    k_combine<<<Nq, Cq>>>(rw, feo, hs);

    // lm_head on HMMA
    k_split_a<<<(Nq * Cq / 2) / 256, 256>>>(hs, ahi, alo);
    k_lmhead_mma<<<VP / 128, 256, LM_SMEM>>>(ahi, alo, bhi, blo, out);
}

// round 8
// speedup vs baseline: 4.1362x; 1.2143x over previous
#include <cuda_runtime.h>
#include <cuda_bf16.h>
#include <math.h>
#include <stdint.h>

// ---------------- problem constants ----------------
static constexpr int Bq = 2;
static constexpr int Tq = 1024;
static constexpr int Cq = 256;
static constexpr int Fq = 1024;
static constexpr int Eq = 32;
static constexpr int Vq = 50257;
static constexpr int Hq = 8;
static constexpr int Dq = 32;      // Cq / Hq
static constexpr int Nq = Bq * Tq; // 2048 tokens
static constexpr int VP = 50304;   // Vq padded to 128 (393 tiles)
static constexpr int C3 = 3 * Cq;  // 768, packed QKV width

// ---------------- device scratch (no allocations allowed) ----------------
__device__ float g_hs[Nq * Cq];
__device__ float g_qkv[Nq * C3];
__device__ float g_xt[Nq * Cq];
__device__ float g_sn[Cq * Eq];
__device__ float g_logits[Nq * Eq];
__device__ float g_rw[Nq * Eq];
__device__ float g_feo[(size_t)Nq * Eq * Cq];
__device__ float g_pre[Nq * Eq];
__device__ float g_am[Nq * Eq];
// MoE dispatch
__device__ int g_cnt[Eq];
__device__ int g_tok[Eq * Nq];
// bf16 hi/lo splits
__device__ __nv_bfloat16 g_ahi[Nq * Cq];           // x -> attn-out -> combine-out
__device__ __nv_bfloat16 g_alo[Nq * Cq];
__device__ __nv_bfloat16 g_bhi[(size_t)Cq * VP];   // lm_head
__device__ __nv_bfloat16 g_blo[(size_t)Cq * VP];
__device__ __nv_bfloat16 g_xhi[Nq * Cq];           // xt (MoE)
__device__ __nv_bfloat16 g_xlo[Nq * Cq];
__device__ __nv_bfloat16 g_w1h[(size_t)Eq * Cq * Fq];
__device__ __nv_bfloat16 g_w1l[(size_t)Eq * Cq * Fq];
__device__ __nv_bfloat16 g_w2h[(size_t)Eq * Fq * Cq];
__device__ __nv_bfloat16 g_w2l[(size_t)Eq * Fq * Cq];
__device__ __nv_bfloat16 g_w3h[Cq * C3];           // packed wq|wk|wv
__device__ __nv_bfloat16 g_w3l[Cq * C3];
__device__ __nv_bfloat16 g_wph[Cq * Cq];           // wo
__device__ __nv_bfloat16 g_wpl[Cq * Cq];
__device__ __nv_bfloat16 g_hh[(size_t)Eq * Nq * Fq];  // compact gelu(X@W1) hi
__device__ __nv_bfloat16 g_hl[(size_t)Eq * Nq * Fq];

// ================= helpers =================
__device__ __forceinline__ uint32_t smem_u32(const void* p) {
    uint32_t a;
    asm("{ .reg .u64 t; cvta.to.shared.u64 t, %1; cvt.u32.u64 %0, t; }" : "=r"(a) : "l"(p));
    return a;
}
__device__ __forceinline__ void split_bf16(float f, uint16_t& hi, uint16_t& lo) {
    __nv_bfloat16 h = __float2bfloat16(f);
    hi = __bfloat16_as_ushort(h);
    lo = __bfloat16_as_ushort(__float2bfloat16(f - __bfloat162float(h)));
}
__device__ __forceinline__ void cp16(uint32_t dst, const void* gsrc) {
    uint64_t g = __cvta_generic_to_global(gsrc);
    asm volatile("cp.async.ca.shared.global [%0], [%1], 16;" :: "r"(dst), "l"(g));
}
__device__ __forceinline__ void cp_commit() { asm volatile("cp.async.commit_group;"); }
__device__ __forceinline__ void cp_wait1() { asm volatile("cp.async.wait_group 1;" ::: "memory"); }
__device__ __forceinline__ void cp_wait0() { asm volatile("cp.async.wait_group 0;" ::: "memory"); }
__device__ __forceinline__ void ldsm_x4(uint32_t* r, uint32_t a) {
    asm volatile("ldmatrix.sync.aligned.m8n8.x4.shared.b16 {%0,%1,%2,%3}, [%4];"
                 : "=r"(r[0]), "=r"(r[1]), "=r"(r[2]), "=r"(r[3]) : "r"(a) : "memory");
}
__device__ __forceinline__ void ldsm_x4_t(uint32_t* r, uint32_t a) {
    asm volatile("ldmatrix.sync.aligned.m8n8.x4.trans.shared.b16 {%0,%1,%2,%3}, [%4];"
                 : "=r"(r[0]), "=r"(r[1]), "=r"(r[2]), "=r"(r[3]) : "r"(a) : "memory");
}
__device__ __forceinline__ void mma16816(float* c, const uint32_t* a, uint32_t b0, uint32_t b1) {
    asm volatile(
        "mma.sync.aligned.m16n8k16.row.col.f32.bf16.bf16.f32 "
        "{%0,%1,%2,%3}, {%4,%5,%6,%7}, {%8,%9}, {%0,%1,%2,%3};"
        : "+f"(c[0]), "+f"(c[1]), "+f"(c[2]), "+f"(c[3])
        : "r"(a[0]), "r"(a[1]), "r"(a[2]), "r"(a[3]), "r"(b0), "r"(b1));
}
__device__ __forceinline__ float gelu_exact(float x) {
    return 0.5f * x * (1.0f + erff(x * 0.70710678118654752f));
}

// ---------------- split kernels (fp32 -> bf16 hi/lo) ----------------
__global__ void k_split_a(const float* __restrict__ src, __nv_bfloat16* __restrict__ hi,
                          __nv_bfloat16* __restrict__ lo) {
    size_t i = (size_t)blockIdx.x * 256 + threadIdx.x;
    float2 v = *(const float2*)&src[i * 2];
    uint16_t h0, l0, h1, l1;
    split_bf16(v.x, h0, l0);
    split_bf16(v.y, h1, l1);
    ((uint32_t*)hi)[i] = (uint32_t)h0 | ((uint32_t)h1 << 16);
    ((uint32_t*)lo)[i] = (uint32_t)l0 | ((uint32_t)l1 << 16);
}
__global__ void k_split_b(const float* __restrict__ src, __nv_bfloat16* __restrict__ hi,
                          __nv_bfloat16* __restrict__ lo) {
    int p = blockIdx.x * 256 + threadIdx.x;
    int k = p / (VP / 2);
    int n = (p - k * (VP / 2)) * 2;
    float v0 = (n < Vq) ? src[(size_t)k * Vq + n] : 0.f;
    float v1 = (n + 1 < Vq) ? src[(size_t)k * Vq + n + 1] : 0.f;
    uint16_t h0, l0, h1, l1;
    split_bf16(v0, h0, l0);
    split_bf16(v1, h1, l1);
    ((uint32_t*)hi)[p] = (uint32_t)h0 | ((uint32_t)h1 << 16);
    ((uint32_t*)lo)[p] = (uint32_t)l0 | ((uint32_t)l1 << 16);
}
// packed wq|wk|wv -> [Cq][768]
__global__ void k_split_w3(const float* __restrict__ wq, const float* __restrict__ wk,
                           const float* __restrict__ wv, __nv_bfloat16* __restrict__ hi,
                           __nv_bfloat16* __restrict__ lo) {
    int i = blockIdx.x * 256 + threadIdx.x;    // pair index over Cq*C3/2
    int k = i / (C3 / 2);
    int n = (i - k * (C3 / 2)) * 2;
    const float* src = (n < Cq) ? wq : ((n < 2 * Cq) ? wk : wv);
    int nn = n & (Cq - 1);
    float v0 = src[k * Cq + nn], v1 = src[k * Cq + nn + 1];
    uint16_t h0, l0, h1, l1;
    split_bf16(v0, h0, l0);
    split_bf16(v1, h1, l1);
    ((uint32_t*)hi)[i] = (uint32_t)h0 | ((uint32_t)h1 << 16);
    ((uint32_t*)lo)[i] = (uint32_t)l0 | ((uint32_t)l1 << 16);
}

// ================= generic HMMA GEMM (bf16 3-split) =================
// epi=0: O = gelu(A@B) -> split bf16 -> Oh/Ol [e][slot][Fq]; A gathered by toks
// epi=1: feo scatter: slot -> token via toks; skip slot >= cnt
// epi=2: out[m*ldo+n] = A@B (+res)
static constexpr int MM_SMEM = 131072;

__global__ void __launch_bounds__(256, 1) k_gemm_mma(
    const __nv_bfloat16* __restrict__ Ah, const __nv_bfloat16* __restrict__ Al,
    const __nv_bfloat16* __restrict__ Bh, const __nv_bfloat16* __restrict__ Bl,
    __nv_bfloat16* __restrict__ Oh, __nv_bfloat16* __restrict__ Ol,
    float* __restrict__ fout, const float* __restrict__ res,
    const int* __restrict__ toks, const int* __restrict__ cnts,
    int K, int lda, int ldb, int ldo, int aExpStride, int epi) {
    extern __shared__ char smem[];
    uint32_t sb = smem_u32(smem);
    int tid = threadIdx.x, wid = tid >> 5, lane = tid & 31;
    int wm = wid >> 2, wn = wid & 3;
    int g = lane >> 3, gr = lane & 7;
    int n0 = blockIdx.x * 128, m0 = blockIdx.y * 128, e = blockIdx.z;

    int ce = cnts ? cnts[e] : 0x7fffffff;
    if (cnts) {
        int lim = (epi == 0) ? ((ce + 127) & ~127) : ce;
        if (m0 >= lim) return;
    }
    const int* tokE = toks ? toks + (size_t)e * Nq : nullptr;

    const __nv_bfloat16* Abh = Ah + (size_t)e * aExpStride;
    const __nv_bfloat16* Abl = Al + (size_t)e * aExpStride;
    const __nv_bfloat16* Bbh = Bh + (size_t)e * K * ldb + n0;
    const __nv_bfloat16* Bbl = Bl + (size_t)e * K * ldb + n0;

    auto copyChunk = [&](int ch) {
        uint32_t base = sb + (ch & 1) * 65536;
        int kc = ch * 64;
#pragma unroll
        for (int it = 0; it < 8; it++) {         // A: [128m][64k] hi+lo
            int lin = tid + it * 256;
            int half = lin >> 10;
            int r = lin & 1023;
            int m = r >> 3, k8 = r & 7;
            int row = m0 + m;
            if (epi == 0 && tokE) row = tokE[row];   // token gather (up-proj)
            uint32_t dst = base + half * 16384 + m * 128 + (((k8 ^ (m & 7))) << 4);
            cp16(dst, (half ? Abl : Abh) + (size_t)row * lda + kc + k8 * 8);
        }
#pragma unroll
        for (int it = 0; it < 8; it++) {         // B: [64k][128n] hi+lo
            int lin = tid + it * 256;
            int half = lin >> 10;
            int r = lin & 1023;
            int k = r >> 4, n8 = r & 15;
            uint32_t dst = base + 32768 + half * 16384 + k * 256 + (((n8 ^ (k & 7))) << 4);
            cp16(dst, (half ? Bbl : Bbh) + (size_t)(kc + k) * ldb + n8 * 8);
        }
    };

    float acc[4][4][4];
#pragma unroll
    for (int a = 0; a < 4; a++)
#pragma unroll
        for (int b = 0; b < 4; b++)
#pragma unroll
            for (int c = 0; c < 4; c++) acc[a][b][c] = 0.f;

    const int k_extra = (g & 1) * 8;
    const int n_extra = (g >> 1) * 8;
    const int nch = K / 64;

    copyChunk(0);
    cp_commit();
    for (int t = 0; t < nch; t++) {
        if (t + 1 < nch) { copyChunk(t + 1); cp_commit(); cp_wait1(); }
        else cp_wait0();
        __syncthreads();
        uint32_t ab = sb + (t & 1) * 65536;
        uint32_t bb = ab + 32768;
#pragma unroll
        for (int ks = 0; ks < 4; ks++) {
            uint32_t Bhf[2][4], Blf[2][4];
#pragma unroll
            for (int b = 0; b < 2; b++) {
                int kx = ks * 16 + k_extra + gr;
                int nf = wn * 32 + b * 16 + n_extra;
                uint32_t off = kx * 256 + ((((nf >> 3) ^ (kx & 7))) << 4);
                ldsm_x4_t(Bhf[b], bb + off);
                ldsm_x4_t(Blf[b], bb + 16384 + off);
            }
#pragma unroll
            for (int ma = 0; ma < 4; ma++) {
                int rowa = wm * 64 + ma * 16 + (g & 1) * 8 + gr;
                int kk = ks * 16 + n_extra;
                uint32_t ao = rowa * 128 + ((((kk >> 3) ^ (rowa & 7))) << 4);
                uint32_t Ahf[4], Alf[4];
                ldsm_x4(Ahf, ab + ao);
                ldsm_x4(Alf, ab + 16384 + ao);
#pragma unroll
                for (int b = 0; b < 2; b++) {
                    mma16816(acc[ma][2 * b],     Ahf, Bhf[b][0], Bhf[b][1]);
                    mma16816(acc[ma][2 * b],     Ahf, Blf[b][0], Blf[b][1]);
                    mma16816(acc[ma][2 * b],     Alf, Bhf[b][0], Bhf[b][1]);
                    mma16816(acc[ma][2 * b + 1], Ahf, Bhf[b][2], Bhf[b][3]);
                    mma16816(acc[ma][2 * b + 1], Ahf, Blf[b][2], Blf[b][3]);
                    mma16816(acc[ma][2 * b + 1], Alf, Bhf[b][2], Bhf[b][3]);
                }
            }
        }
        __syncthreads();
    }

    // ---- SMEM-staged epilogue ----
    float* stage = (float*)smem;
#pragma unroll
    for (int ma = 0; ma < 4; ma++) {
        int lr = wm * 64 + ma * 16 + (lane >> 2);
#pragma unroll
        for (int na = 0; na < 4; na++) {
            int lc = wn * 32 + na * 8 + (lane & 3) * 2;
            float v0 = acc[ma][na][0], v1 = acc[ma][na][1];
            float v2 = acc[ma][na][2], v3 = acc[ma][na][3];
            if (epi == 0) { v0 = gelu_exact(v0); v1 = gelu_exact(v1);
                            v2 = gelu_exact(v2); v3 = gelu_exact(v3); }
            stage[lr * 132 + lc] = v0;
            stage[lr * 132 + lc + 1] = v1;
            stage[(lr + 8) * 132 + lc] = v2;
            stage[(lr + 8) * 132 + lc + 1] = v3;
        }
    }
    __syncthreads();

    if (epi == 0) {
#pragma unroll
        for (int it = 0; it < 8; it++) {
            int idx = tid + it * 256;
            int r = idx >> 4, c8 = (idx & 15) * 8;
            float4 a = *(float4*)&stage[r * 132 + c8];
            float4 b = *(float4*)&stage[r * 132 + c8 + 4];
            uint16_t h[8], l[8];
            split_bf16(a.x, h[0], l[0]); split_bf16(a.y, h[1], l[1]);
            split_bf16(a.z, h[2], l[2]); split_bf16(a.w, h[3], l[3]);
            split_bf16(b.x, h[4], l[4]); split_bf16(b.y, h[5], l[5]);
            split_bf16(b.z, h[6], l[6]); split_bf16(b.w, h[7], l[7]);
            size_t o = ((size_t)e * Nq + m0 + r) * Fq + n0 + c8;
            *(uint4*)(Oh + o) = make_uint4(
                (uint32_t)h[0] | ((uint32_t)h[1] << 16), (uint32_t)h[2] | ((uint32_t)h[3] << 16),
                (uint32_t)h[4] | ((uint32_t)h[5] << 16), (uint32_t)h[6] | ((uint32_t)h[7] << 16));
            *(uint4*)(Ol + o) = make_uint4(
                (uint32_t)l[0] | ((uint32_t)l[1] << 16), (uint32_t)l[2] | ((uint32_t)l[3] << 16),
                (uint32_t)l[4] | ((uint32_t)l[5] << 16), (uint32_t)l[6] | ((uint32_t)l[7] << 16));
        }
    } else if (epi == 1) {
#pragma unroll
        for (int it = 0; it < 16; it++) {
            int idx = tid + it * 256;
            int r = idx >> 5, c4 = (idx & 31) * 4;
            int slot = m0 + r;
            if (slot >= ce) continue;                 // padded rows: don't store
            int t = tokE ? tokE[slot] : slot;
            float4 v = *(float4*)&stage[r * 132 + c4];
            *(float4*)&fout[((size_t)t * Eq + e) * Cq + n0 + c4] = v;
        }
    } else {
#pragma unroll
        for (int it = 0; it < 16; it++) {
            int idx = tid + it * 256;
            int r = idx >> 5, c4 = (idx & 31) * 4;
            float4 v = *(float4*)&stage[r * 132 + c4];
            size_t o = (size_t)(m0 + r) * ldo + n0 + c4;
            if (res) {
                float4 rr = *(const float4*)&res[o];
                v.x += rr.x; v.y += rr.y; v.z += rr.z; v.w += rr.w;
            }
            *(float4*)&fout[o] = v;
        }
    }
}

// ================= lm_head HMMA GEMM =================
static constexpr int SM_B_HI = 0;
static constexpr int SM_B_LO = 65536;
static constexpr int SM_A    = 131072;
static constexpr int LM_SMEM = 196608;

__global__ void __launch_bounds__(256, 1) k_lmhead_mma(const __nv_bfloat16* __restrict__ Ah,
                                                       const __nv_bfloat16* __restrict__ Al,
                                                       const __nv_bfloat16* __restrict__ Bh,
                                                       const __nv_bfloat16* __restrict__ Bl,
                                                       float* __restrict__ out) {
    extern __shared__ char smem[];
    uint32_t sb = smem_u32(smem);
    int tid = threadIdx.x;
    int wid = tid >> 5, lane = tid & 31;
    int wm = wid >> 2, wn = wid & 3;
    int g = lane >> 3, gr = lane & 7;
    int n0 = blockIdx.x * 128;

#pragma unroll
    for (int it = 0; it < 32; it++) {
        int lin = tid + it * 256;
        int half = lin >> 12;
        int r = lin & 4095;
        int k = r >> 4, n8 = r & 15;
        uint32_t dst = sb + (half ? SM_B_LO : SM_B_HI) + k * 256 + (((n8 ^ (k & 7))) << 4);
        const __nv_bfloat16* srcb = (half ? Bl : Bh) + (size_t)k * VP + n0 + n8 * 8;
        cp16(dst, srcb);
    }
    auto copyA = [&](int t) {
        int mb = t >> 2;
        int kc = (t & 3) * 64;
        uint32_t abase = sb + SM_A + (t & 1) * 32768;
#pragma unroll
        for (int it = 0; it < 8; it++) {
            int lin = tid + it * 256;
            int half = lin >> 10;
            int r = lin & 1023;
            int m = r >> 3, k8 = r & 7;
            uint32_t dst = abase + half * 16384 + m * 128 + (((k8 ^ (m & 7))) << 4);
            const __nv_bfloat16* srca = (half ? Al : Ah) + (size_t)(mb * 128 + m) * Cq + kc + k8 * 8;
            cp16(dst, srca);
        }
    };
    copyA(0);
    cp_commit();

    float acc[4][4][4];
#pragma unroll
    for (int a = 0; a < 4; a++)
#pragma unroll
        for (int b = 0; b < 4; b++)
#pragma unroll
            for (int c = 0; c < 4; c++) acc[a][b][c] = 0.f;

    const int k_extra = (g & 1) * 8;
    const int n_extra = (g >> 1) * 8;

    for (int t = 0; t < 64; t++) {
        if (t + 1 < 64) { copyA(t + 1); cp_commit(); cp_wait1(); }
        else cp_wait0();
        __syncthreads();

        int kc = (t & 3) * 64;
        uint32_t ah_base = sb + SM_A + (t & 1) * 32768;
        uint32_t al_base = ah_base + 16384;
#pragma unroll
        for (int ks = 0; ks < 4; ks++) {
            uint32_t Bhf[2][4], Blf[2][4];
#pragma unroll
            for (int b = 0; b < 2; b++) {
                int kx = kc + ks * 16 + k_extra + gr;
                int nf = wn * 32 + b * 16 + n_extra;
                uint32_t off = kx * 256 + ((((nf >> 3) ^ (kx & 7))) << 4);
                ldsm_x4_t(Bhf[b], sb + SM_B_HI + off);
                ldsm_x4_t(Blf[b], sb + SM_B_LO + off);
            }
#pragma unroll
            for (int ma = 0; ma < 4; ma++) {
                int rowa = wm * 64 + ma * 16 + (g & 1) * 8 + gr;
                int kkl = ks * 16 + n_extra;
                uint32_t ao = rowa * 128 + ((((kkl >> 3) ^ (rowa & 7))) << 4);
                uint32_t Ahf[4], Alf[4];
                ldsm_x4(Ahf, ah_base + ao);
                ldsm_x4(Alf, al_base + ao);
#pragma unroll
                for (int b = 0; b < 2; b++) {
                    mma16816(acc[ma][2 * b],     Ahf, Bhf[b][0], Bhf[b][1]);
                    mma16816(acc[ma][2 * b],     Ahf, Blf[b][0], Blf[b][1]);
                    mma16816(acc[ma][2 * b],     Alf, Bhf[b][0], Bhf[b][1]);
                    mma16816(acc[ma][2 * b + 1], Ahf, Bhf[b][2], Bhf[b][3]);
                    mma16816(acc[ma][2 * b + 1], Ahf, Blf[b][2], Blf[b][3]);
                    mma16816(acc[ma][2 * b + 1], Alf, Bhf[b][2], Bhf[b][3]);
                }
            }
        }
        if ((t & 3) == 3) {
            // scalar stores: Vq odd -> wider stores misalign on odd rows
            int mbase = (t >> 2) * 128 + wm * 64;
#pragma unroll
            for (int ma = 0; ma < 4; ma++) {
#pragma unroll
                for (int na = 0; na < 4; na++) {
                    int gm = mbase + ma * 16 + (lane >> 2);
                    int gn = n0 + wn * 32 + na * 8 + (lane & 3) * 2;
                    float* p0 = out + (size_t)gm * Vq + gn;
                    float* p1 = out + (size_t)(gm + 8) * Vq + gn;
                    if (gn < Vq)     { p0[0] = acc[ma][na][0]; p1[0] = acc[ma][na][2]; }
                    if (gn + 1 < Vq) { p0[1] = acc[ma][na][1]; p1[1] = acc[ma][na][3]; }
                    acc[ma][na][0] = acc[ma][na][1] = acc[ma][na][2] = acc[ma][na][3] = 0.f;
                }
            }
        }
        __syncthreads();
    }
}

// ---------------- embedding ----------------
__global__ void k_embed(const int* __restrict__ ids, const float* __restrict__ emb,
                        float* __restrict__ hs) {
    int t = blockIdx.x, c = threadIdx.x;
    hs[(size_t)t * Cq + c] = emb[(size_t)ids[t] * Cq + c];
}

// ---------------- layernorm fused with bf16 split ----------------
__global__ void k_layernorm_split(const float* __restrict__ in, const float* __restrict__ w,
                                  const float* __restrict__ b, float* __restrict__ fp32out,
                                  __nv_bfloat16* __restrict__ hi, __nv_bfloat16* __restrict__ lo) {
    int t = blockIdx.x, c = threadIdx.x;
    float x = in[(size_t)t * Cq + c];
    __shared__ float red[8];
    float s = x;
#pragma unroll
    for (int o = 16; o; o >>= 1) s += __shfl_xor_sync(0xffffffffu, s, o);
    if ((c & 31) == 0) red[c >> 5] = s;
    __syncthreads();
    float mu = 0.f;
#pragma unroll
    for (int i = 0; i < 8; i++) mu += red[i];
    mu *= (1.f / Cq);
    float d = x - mu;
    float s2 = d * d;
#pragma unroll
    for (int o = 16; o; o >>= 1) s2 += __shfl_xor_sync(0xffffffffu, s2, o);
    __syncthreads();
    if ((c & 31) == 0) red[c >> 5] = s2;
    __syncthreads();
    float var = 0.f;
#pragma unroll
    for (int i = 0; i < 8; i++) var += red[i];
    var *= (1.f / Cq);
    float y = d * rsqrtf(var + 1e-5f) * w[c] + b[c];
    if (fp32out) fp32out[(size_t)t * Cq + c] = y;
    uint16_t h, l;
    split_bf16(y, h, l);
    ((uint16_t*)hi)[(size_t)t * Cq + c] = h;
    ((uint16_t*)lo)[(size_t)t * Cq + c] = l;
}

// ---------------- causal attention (reads packed qkv, writes bf16 split) ----------------
__global__ void k_attn(const float* __restrict__ qkv, __nv_bfloat16* __restrict__ ohi,
                       __nv_bfloat16* __restrict__ olo) {
    int b = blockIdx.z, h = blockIdx.y;
    int t0 = blockIdx.x * 64;
    int qi = t0 + threadIdx.x;
    const float scale = 0.17677669529663687f;
    float qr[Dq];
    const float* qp = qkv + ((size_t)(b * Tq + qi)) * C3 + h * Dq;
#pragma unroll
    for (int d = 0; d < Dq; d++) qr[d] = qp[d] * scale;
    float acc[Dq];
#pragma unroll
    for (int d = 0; d < Dq; d++) acc[d] = 0.f;
    float m = -INFINITY, l = 0.f;
    __shared__ float Ks[64 * Dq], Vs[64 * Dq];

    for (int kt = 0; kt < t0 + 64; kt += 64) {
        for (int i = threadIdx.x; i < 64 * Dq; i += 64) {
            int r = i >> 5, d = i & 31;
            size_t gi = ((size_t)(b * Tq + kt + r)) * C3 + h * Dq + d;
            Ks[i] = qkv[gi + Cq];       // K at offset 256
            Vs[i] = qkv[gi + 2 * Cq];   // V at offset 512
        }
        __syncthreads();
        int jmax = qi - kt + 1;
        if (jmax > 64) jmax = 64;
        for (int j = 0; j < jmax; j++) {
            float s = 0.f;
#pragma unroll
            for (int d = 0; d < Dq; d++) s += qr[d] * Ks[j * Dq + d];
            float nm = fmaxf(m, s);
            float corr = expf(m - nm);
            float p = expf(s - nm);
            l = l * corr + p;
#pragma unroll
            for (int d = 0; d < Dq; d++) acc[d] = acc[d] * corr + p * Vs[j * Dq + d];
            m = nm;
        }
        __syncthreads();
    }
    float inv = 1.f / l;
    size_t ob = ((size_t)(b * Tq + qi)) * Cq + h * Dq;
#pragma unroll
    for (int d = 0; d < Dq; d++) {
        uint16_t hh, ll;
        split_bf16(acc[d] * inv, hh, ll);
        ((uint16_t*)ohi)[ob + d] = hh;
        ((uint16_t*)olo)[ob + d] = ll;
    }
}

// ---------------- normalize sim_matrix columns ----------------
__global__ void k_simnorm(const float* __restrict__ sim, float* __restrict__ sn) {
    __shared__ float ps[8][32];
    __shared__ float inv[32];
    int tid = threadIdx.x;
    int e = tid & 31, part = tid >> 5;
    float s = 0.f;
    for (int c = part * 32; c < part * 32 + 32; c++) {
        float vv = sim[(size_t)c * Eq + e];
        s += vv * vv;
    }
    ps[part][e] = s;
    __syncthreads();
    if (tid < 32) {
        float tot = 0.f;
#pragma unroll
        for (int p = 0; p < 8; p++) tot += ps[p][tid];
        inv[tid] = 1.f / fmaxf(sqrtf(tot), 1e-12f);
    }
    __syncthreads();
    for (int i = tid; i < Cq * Eq; i += 256) sn[i] = sim[i] * inv[i & 31];
}

// ---------------- gate logits ----------------
__global__ void k_gate_logits(const float* __restrict__ xt, const float* __restrict__ sn,
                              float* __restrict__ logits) {
    __shared__ float xs[8 * Cq];
    int tid = threadIdx.x;
    int t0 = blockIdx.x * 8;
    for (int i = tid; i < 8 * Cq; i += 256) xs[i] = xt[(size_t)t0 * Cq + i];
    __syncthreads();
    int w = tid >> 5, lane = tid & 31;
    int t = t0 + w;
    float s = 0.f;
    for (int c = lane; c < Cq; c += 32) {
        float vv = xs[w * Cq + c];
        s += vv * vv;
    }
#pragma unroll
    for (int o = 16; o; o >>= 1) s += __shfl_xor_sync(0xffffffffu, s, o);
    float inv = 1.f / fmaxf(sqrtf(s), 1e-12f);
    float acc = 0.f;
    for (int c = 0; c < Cq; c++) acc += xs[w * Cq + c] * sn[c * Eq + lane];
    logits[(size_t)t * Eq + lane] = acc * inv;
}

// ---------------- gate decision + routing softmax + dispatch lists ----------------
__global__ void k_gate(const float* __restrict__ logits, const float* __restrict__ gates,
                       float* __restrict__ pre_o, float* __restrict__ am_o,
                       float* __restrict__ rw) {
    int w = threadIdx.x >> 5, lane = threadIdx.x & 31;
    int t = blockIdx.x * 8 + w;
    float lg = logits[(size_t)t * Eq + lane];
    float pre = lg - 1.f / (1.f + expf(-gates[lane]));
    float gated = fmaxf(pre, 0.f);
    unsigned act = __ballot_sync(0xffffffffu, pre > 0.f);
    float am;
    if (act == 0u) {
        int rank = 0;
#pragma unroll
        for (int j = 0; j < 32; j++) {
            float lj = __shfl_sync(0xffffffffu, lg, j);
            rank += (lj > lg) || (lj == lg && j < lane);
        }
        am = (rank < 16) ? 1.f : 0.f;
    } else {
        am = (pre > 0.f) ? 1.f : 0.f;
    }
    float g2 = (am > 0.f) ? gated : -INFINITY;
    float mx = g2;
#pragma unroll
    for (int o = 16; o; o >>= 1) mx = fmaxf(mx, __shfl_xor_sync(0xffffffffu, mx, o));
    float p = (am > 0.f) ? expf(gated - mx) : 0.f;
    float sum = p;
#pragma unroll
    for (int o = 16; o; o >>= 1) sum += __shfl_xor_sync(0xffffffffu, sum, o);
    rw[(size_t)t * Eq + lane] = p / sum;
    pre_o[(size_t)t * Eq + lane] = pre;
    am_o[(size_t)t * Eq + lane] = am;
    if (am > 0.f) {
        int slot = atomicAdd(&g_cnt[lane], 1);
        g_tok[lane * Nq + slot] = t;
    }
}

// ---------------- pad token lists to 128 ----------------
__global__ void k_pad() {
    int e = blockIdx.x;
    int c = g_cnt[e];
    int cap = (c + 127) & ~127;
    int t0v = (c > 0) ? g_tok[e * Nq] : 0;
    for (int i = c + threadIdx.x; i < cap; i += blockDim.x) g_tok[e * Nq + i] = t0v;
}

// ---------------- zero feo at inactive (t,e) ----------------
__global__ void k_zero_feo(const float* __restrict__ am, float* __restrict__ feo) {
    int t = blockIdx.x, tid = threadIdx.x;
    __shared__ float ams[Eq];
    if (tid < Eq) ams[tid] = am[(size_t)t * Eq + tid];
    __syncthreads();
    for (int idx = tid; idx < Eq * 64; idx += 256) {
        int e = idx >> 6, c4 = (idx & 63) * 4;
        if (ams[e] == 0.f)
            *(float4*)&feo[((size_t)t * Eq + e) * Cq + c4] = make_float4(0.f, 0.f, 0.f, 0.f);
    }
}

// ---------------- combine fused with bf16 split (skips rw==0 experts) ----------------
__global__ void k_combine_split(const float* __restrict__ rw, const float* __restrict__ feo,
                                const float* __restrict__ hs, __nv_bfloat16* __restrict__ hi,
                                __nv_bfloat16* __restrict__ lo) {
    int t = blockIdx.x, c = threadIdx.x;
    __shared__ float rws[Eq];
    if (c < Eq) rws[c] = rw[(size_t)t * Eq + c];
    __syncthreads();
    float s = hs[(size_t)t * Cq + c];
#pragma unroll
    for (int e = 0; e < Eq; e++) {
        float r = rws[e];
        if (r != 0.f) s += r * feo[((size_t)t * Eq + e) * Cq + c];
    }
    uint16_t h, l;
    split_bf16(s, h, l);
    ((uint16_t*)hi)[(size_t)t * Cq + c] = h;
    ((uint16_t*)lo)[(size_t)t * Cq + c] = l;
}

// ---------------- host ----------------
extern "C" void kernel_launch(void* const* d_in, const int* in_sizes, int n_in,
                              void* d_out, int out_size) {
    const int*   ids   = (const int*)d_in[0];
    const float* emb   = (const float*)d_in[1];
    const float* wq    = (const float*)d_in[2];
    const float* wk    = (const float*)d_in[3];
    const float* wv    = (const float*)d_in[4];
    const float* wo    = (const float*)d_in[5];
    const float* ln1w  = (const float*)d_in[6];
    const float* ln1b  = (const float*)d_in[7];
    const float* ln2w  = (const float*)d_in[8];
    const float* ln2b  = (const float*)d_in[9];
    const float* sim   = (const float*)d_in[10];
    const float* gates = (const float*)d_in[11];
    const float* w1    = (const float*)d_in[12];
    const float* w2    = (const float*)d_in[13];
    const float* lmh   = (const float*)d_in[14];

    float *hs, *qkv, *xt, *sn, *logits, *rw, *feo_s, *pre_s, *am_s;
    int *cnt, *tok;
    __nv_bfloat16 *ahi, *alo, *bhi, *blo, *xhi, *xlo, *w1h, *w1l, *w2h, *w2l;
    __nv_bfloat16 *w3h, *w3l, *wph, *wpl, *hh, *hl;
    cudaGetSymbolAddress((void**)&hs, g_hs);
    cudaGetSymbolAddress((void**)&qkv, g_qkv);
    cudaGetSymbolAddress((void**)&xt, g_xt);
    cudaGetSymbolAddress((void**)&sn, g_sn);
    cudaGetSymbolAddress((void**)&logits, g_logits);
    cudaGetSymbolAddress((void**)&rw, g_rw);
    cudaGetSymbolAddress((void**)&feo_s, g_feo);
    cudaGetSymbolAddress((void**)&pre_s, g_pre);
    cudaGetSymbolAddress((void**)&am_s, g_am);
    cudaGetSymbolAddress((void**)&cnt, g_cnt);
    cudaGetSymbolAddress((void**)&tok, g_tok);
    cudaGetSymbolAddress((void**)&ahi, g_ahi);
    cudaGetSymbolAddress((void**)&alo, g_alo);
    cudaGetSymbolAddress((void**)&bhi, g_bhi);
    cudaGetSymbolAddress((void**)&blo, g_blo);
    cudaGetSymbolAddress((void**)&xhi, g_xhi);
    cudaGetSymbolAddress((void**)&xlo, g_xlo);
    cudaGetSymbolAddress((void**)&w1h, g_w1h);
    cudaGetSymbolAddress((void**)&w1l, g_w1l);
    cudaGetSymbolAddress((void**)&w2h, g_w2h);
    cudaGetSymbolAddress((void**)&w2l, g_w2l);
    cudaGetSymbolAddress((void**)&w3h, g_w3h);
    cudaGetSymbolAddress((void**)&w3l, g_w3l);
    cudaGetSymbolAddress((void**)&wph, g_wph);
    cudaGetSymbolAddress((void**)&wpl, g_wpl);
    cudaGetSymbolAddress((void**)&hh, g_hh);
    cudaGetSymbolAddress((void**)&hl, g_hl);

    float* out = (float*)d_out;
    const size_t NV  = (size_t)Nq * Vq;
    const size_t FEO = (size_t)Nq * Eq * Cq;
    const size_t NE  = (size_t)Nq * Eq;
    float *feo, *pre_o, *am_o;
    if ((size_t)out_size >= NV + FEO + 2 * NE) {
        feo = out + NV;
        pre_o = out + NV + FEO;
        am_o = pre_o + NE;
    } else {
        feo = feo_s; pre_o = pre_s; am_o = am_s;
    }

    cudaFuncSetAttribute(k_gemm_mma, cudaFuncAttributeMaxDynamicSharedMemorySize, MM_SMEM);
    cudaFuncSetAttribute(k_lmhead_mma, cudaFuncAttributeMaxDynamicSharedMemorySize, LM_SMEM);

    cudaMemsetAsync(cnt, 0, Eq * sizeof(int));
    k_embed<<<Nq, Cq>>>(ids, emb, hs);
    // pre-split constant weights
    k_split_b<<<(Cq * VP / 2) / 256, 256>>>(lmh, bhi, blo);
    k_split_a<<<((size_t)Eq * Cq * Fq / 2) / 256, 256>>>(w1, w1h, w1l);
    k_split_a<<<((size_t)Eq * Fq * Cq / 2) / 256, 256>>>(w2, w2h, w2l);
    k_split_w3<<<(Cq * C3 / 2) / 256, 256>>>(wq, wk, wv, w3h, w3l);
    k_split_a<<<(Cq * Cq / 2) / 256, 256>>>(wo, wph, wpl);

    // ln1 -> bf16 split (no fp32 copy needed)
    k_layernorm_split<<<Nq, Cq>>>(hs, ln1w, ln1b, nullptr, ahi, alo);

    // fused QKV GEMM -> packed qkv [t][768]
    k_gemm_mma<<<dim3(C3 / 128, Nq / 128), 256, MM_SMEM>>>(
        ahi, alo, w3h, w3l, nullptr, nullptr, qkv, nullptr, nullptr, nullptr,
        Cq, Cq, C3, C3, 0, 2);

    // attention -> bf16 split output (reuses ahi/alo)
    k_attn<<<dim3(Tq / 64, Hq, Bq), 64>>>(qkv, ahi, alo);

    // hs = hs + attn_out @ wo
    k_gemm_mma<<<dim3(Cq / 128, Nq / 128), 256, MM_SMEM>>>(
        ahi, alo, wph, wpl, nullptr, nullptr, hs, hs, nullptr, nullptr,
        Cq, Cq, Cq, Cq, 0, 2);

    // ln2 -> fp32 xt (for gating) + bf16 split (for MoE)
    k_layernorm_split<<<Nq, Cq>>>(hs, ln2w, ln2b, xt, xhi, xlo);
    k_simnorm<<<1, 256>>>(sim, sn);
    k_gate_logits<<<Nq / 8, 256>>>(xt, sn, logits);
    k_gate<<<Nq / 8, 256>>>(logits, gates, pre_o, am_o, rw);
    k_pad<<<Eq, 128>>>();
    k_zero_feo<<<Nq, 256>>>(am_o, feo);

    // sparse MoE: up-proj gathers active tokens per expert, down-proj scatters
    k_gemm_mma<<<dim3(Fq / 128, Nq / 128, Eq), 256, MM_SMEM>>>(
        xhi, xlo, w1h, w1l, hh, hl, nullptr, nullptr, tok, cnt,
        Cq, Cq, Fq, 0, 0, 0);
    k_gemm_mma<<<dim3(Cq / 128, Nq / 128, Eq), 256, MM_SMEM>>>(
        hh, hl, w2h, w2l, nullptr, nullptr, feo, nullptr, tok, cnt,
        Fq, Fq, Cq, 0, Nq * Fq, 1);

    // combine + split for lm_head input
    k_combine_split<<<Nq, Cq>>>(rw, feo, hs, ahi, alo);

    // lm_head
    k_lmhead_mma<<<VP / 128, 256, LM_SMEM>>>(ahi, alo, bhi, blo, out);
}

// round 11
// speedup vs baseline: 4.2341x; 1.0237x over previous
#include <cuda_runtime.h>
#include <cuda_bf16.h>
#include <math.h>
#include <stdint.h>

// ---------------- problem constants ----------------
static constexpr int Bq = 2;
static constexpr int Tq = 1024;
static constexpr int Cq = 256;
static constexpr int Fq = 1024;
static constexpr int Eq = 32;
static constexpr int Vq = 50257;
static constexpr int Hq = 8;
static constexpr int Dq = 32;      // Cq / Hq
static constexpr int Nq = Bq * Tq; // 2048 tokens
static constexpr int VP = 50304;   // Vq padded to 128 (393 tiles)
static constexpr int C3 = 3 * Cq;  // 768, packed QKV width

// ---------------- device scratch (no allocations allowed) ----------------
__device__ float g_hs[Nq * Cq];
__device__ float g_qkv[Nq * C3];
__device__ float g_xt[Nq * Cq];
__device__ float g_sn[Cq * Eq];
__device__ float g_rw[Nq * Eq];
__device__ float g_feo[(size_t)Nq * Eq * Cq];
__device__ float g_pre[Nq * Eq];
__device__ float g_am[Nq * Eq];
// MoE dispatch
__device__ int g_cnt[Eq];
__device__ int g_tok[Eq * Nq];
// bf16 hi/lo splits
__device__ __nv_bfloat16 g_ahi[Nq * Cq];           // x -> attn-out -> combine-out
__device__ __nv_bfloat16 g_alo[Nq * Cq];
__device__ __nv_bfloat16 g_bhi[(size_t)Cq * VP];   // lm_head
__device__ __nv_bfloat16 g_blo[(size_t)Cq * VP];
__device__ __nv_bfloat16 g_xhi[Nq * Cq];           // xt (MoE)
__device__ __nv_bfloat16 g_xlo[Nq * Cq];
__device__ __nv_bfloat16 g_w1h[(size_t)Eq * Cq * Fq];
__device__ __nv_bfloat16 g_w1l[(size_t)Eq * Cq * Fq];
__device__ __nv_bfloat16 g_w2h[(size_t)Eq * Fq * Cq];
__device__ __nv_bfloat16 g_w2l[(size_t)Eq * Fq * Cq];
__device__ __nv_bfloat16 g_w3h[Cq * C3];           // packed wq|wk|wv
__device__ __nv_bfloat16 g_w3l[Cq * C3];
__device__ __nv_bfloat16 g_wph[Cq * Cq];           // wo
__device__ __nv_bfloat16 g_wpl[Cq * Cq];
__device__ __nv_bfloat16 g_hh[(size_t)Eq * Nq * Fq];  // compact gelu(X@W1) hi
__device__ __nv_bfloat16 g_hl[(size_t)Eq * Nq * Fq];

// ================= helpers =================
__device__ __forceinline__ uint32_t smem_u32(const void* p) {
    uint32_t a;
    asm("{ .reg .u64 t; cvta.to.shared.u64 t, %1; cvt.u32.u64 %0, t; }" : "=r"(a) : "l"(p));
    return a;
}
__device__ __forceinline__ void split_bf16(float f, uint16_t& hi, uint16_t& lo) {
    __nv_bfloat16 h = __float2bfloat16(f);
    hi = __bfloat16_as_ushort(h);
    lo = __bfloat16_as_ushort(__float2bfloat16(f - __bfloat162float(h)));
}
__device__ __forceinline__ void cp16(uint32_t dst, const void* gsrc) {
    uint64_t g = __cvta_generic_to_global(gsrc);
    asm volatile("cp.async.ca.shared.global [%0], [%1], 16;" :: "r"(dst), "l"(g));
}
__device__ __forceinline__ void cp_commit() { asm volatile("cp.async.commit_group;"); }
__device__ __forceinline__ void cp_wait1() { asm volatile("cp.async.wait_group 1;" ::: "memory"); }
__device__ __forceinline__ void cp_wait0() { asm volatile("cp.async.wait_group 0;" ::: "memory"); }
__device__ __forceinline__ void ldsm_x4(uint32_t* r, uint32_t a) {
    asm volatile("ldmatrix.sync.aligned.m8n8.x4.shared.b16 {%0,%1,%2,%3}, [%4];"
                 : "=r"(r[0]), "=r"(r[1]), "=r"(r[2]), "=r"(r[3]) : "r"(a) : "memory");
}
__device__ __forceinline__ void ldsm_x4_t(uint32_t* r, uint32_t a) {
    asm volatile("ldmatrix.sync.aligned.m8n8.x4.trans.shared.b16 {%0,%1,%2,%3}, [%4];"
                 : "=r"(r[0]), "=r"(r[1]), "=r"(r[2]), "=r"(r[3]) : "r"(a) : "memory");
}
__device__ __forceinline__ void mma16816(float* c, const uint32_t* a, uint32_t b0, uint32_t b1) {
    asm volatile(
        "mma.sync.aligned.m16n8k16.row.col.f32.bf16.bf16.f32 "
        "{%0,%1,%2,%3}, {%4,%5,%6,%7}, {%8,%9}, {%0,%1,%2,%3};"
        : "+f"(c[0]), "+f"(c[1]), "+f"(c[2]), "+f"(c[3])
        : "r"(a[0]), "r"(a[1]), "r"(a[2]), "r"(a[3]), "r"(b0), "r"(b1));
}
__device__ __forceinline__ float gelu_exact(float x) {
    return 0.5f * x * (1.0f + erff(x * 0.70710678118654752f));
}

// ---------------- split kernels (fp32 -> bf16 hi/lo) ----------------
__global__ void k_split_a(const float* __restrict__ src, __nv_bfloat16* __restrict__ hi,
                          __nv_bfloat16* __restrict__ lo) {
    size_t i = (size_t)blockIdx.x * 256 + threadIdx.x;
    float2 v = *(const float2*)&src[i * 2];
    uint16_t h0, l0, h1, l1;
    split_bf16(v.x, h0, l0);
    split_bf16(v.y, h1, l1);
    ((uint32_t*)hi)[i] = (uint32_t)h0 | ((uint32_t)h1 << 16);
    ((uint32_t*)lo)[i] = (uint32_t)l0 | ((uint32_t)l1 << 16);
}
__global__ void k_split_b(const float* __restrict__ src, __nv_bfloat16* __restrict__ hi,
                          __nv_bfloat16* __restrict__ lo) {
    int p = blockIdx.x * 256 + threadIdx.x;
    int k = p / (VP / 2);
    int n = (p - k * (VP / 2)) * 2;
    float v0 = (n < Vq) ? src[(size_t)k * Vq + n] : 0.f;
    float v1 = (n + 1 < Vq) ? src[(size_t)k * Vq + n + 1] : 0.f;
    uint16_t h0, l0, h1, l1;
    split_bf16(v0, h0, l0);
    split_bf16(v1, h1, l1);
    ((uint32_t*)hi)[p] = (uint32_t)h0 | ((uint32_t)h1 << 16);
    ((uint32_t*)lo)[p] = (uint32_t)l0 | ((uint32_t)l1 << 16);
}
// packed wq|wk|wv -> [Cq][768]
__global__ void k_split_w3(const float* __restrict__ wq, const float* __restrict__ wk,
                           const float* __restrict__ wv, __nv_bfloat16* __restrict__ hi,
                           __nv_bfloat16* __restrict__ lo) {
    int i = blockIdx.x * 256 + threadIdx.x;
    int k = i / (C3 / 2);
    int n = (i - k * (C3 / 2)) * 2;
    const float* src = (n < Cq) ? wq : ((n < 2 * Cq) ? wk : wv);
    int nn = n & (Cq - 1);
    float v0 = src[k * Cq + nn], v1 = src[k * Cq + nn + 1];
    uint16_t h0, l0, h1, l1;
    split_bf16(v0, h0, l0);
    split_bf16(v1, h1, l1);
    ((uint32_t*)hi)[i] = (uint32_t)h0 | ((uint32_t)h1 << 16);
    ((uint32_t*)lo)[i] = (uint32_t)l0 | ((uint32_t)l1 << 16);
}

// ================= generic HMMA GEMM (bf16 3-split) =================
static constexpr int MM_SMEM = 131072;

__global__ void __launch_bounds__(256, 1) k_gemm_mma(
    const __nv_bfloat16* __restrict__ Ah, const __nv_bfloat16* __restrict__ Al,
    const __nv_bfloat16* __restrict__ Bh, const __nv_bfloat16* __restrict__ Bl,
    __nv_bfloat16* __restrict__ Oh, __nv_bfloat16* __restrict__ Ol,
    float* __restrict__ fout, const float* __restrict__ res,
    const int* __restrict__ toks, const int* __restrict__ cnts,
    int K, int lda, int ldb, int ldo, int aExpStride, int epi) {
    extern __shared__ char smem[];
    uint32_t sb = smem_u32(smem);
    int tid = threadIdx.x, wid = tid >> 5, lane = tid & 31;
    int wm = wid >> 2, wn = wid & 3;
    int g = lane >> 3, gr = lane & 7;
    int n0 = blockIdx.x * 128, m0 = blockIdx.y * 128, e = blockIdx.z;

    int ce = cnts ? cnts[e] : 0x7fffffff;
    if (cnts) {
        int lim = (epi == 0) ? ((ce + 127) & ~127) : ce;
        if (m0 >= lim) return;
    }
    const int* tokE = toks ? toks + (size_t)e * Nq : nullptr;

    const __nv_bfloat16* Abh = Ah + (size_t)e * aExpStride;
    const __nv_bfloat16* Abl = Al + (size_t)e * aExpStride;
    const __nv_bfloat16* Bbh = Bh + (size_t)e * K * ldb + n0;
    const __nv_bfloat16* Bbl = Bl + (size_t)e * K * ldb + n0;

    auto copyChunk = [&](int ch) {
        uint32_t base = sb + (ch & 1) * 65536;
        int kc = ch * 64;
#pragma unroll
        for (int it = 0; it < 8; it++) {         // A: [128m][64k] hi+lo
            int lin = tid + it * 256;
            int half = lin >> 10;
            int r = lin & 1023;
            int m = r >> 3, k8 = r & 7;
            int row = m0 + m;
            if (epi == 0 && tokE) {              // token gather (up-proj), clamp pad
                int slot = row;
                if (slot >= ce) slot = ce - 1;
                row = tokE[slot];
            }
            uint32_t dst = base + half * 16384 + m * 128 + (((k8 ^ (m & 7))) << 4);
            cp16(dst, (half ? Abl : Abh) + (size_t)row * lda + kc + k8 * 8);
        }
#pragma unroll
        for (int it = 0; it < 8; it++) {         // B: [64k][128n] hi+lo
            int lin = tid + it * 256;
            int half = lin >> 10;
            int r = lin & 1023;
            int k = r >> 4, n8 = r & 15;
            uint32_t dst = base + 32768 + half * 16384 + k * 256 + (((n8 ^ (k & 7))) << 4);
            cp16(dst, (half ? Bbl : Bbh) + (size_t)(kc + k) * ldb + n8 * 8);
        }
    };

    float acc[4][4][4];
#pragma unroll
    for (int a = 0; a < 4; a++)
#pragma unroll
        for (int b = 0; b < 4; b++)
#pragma unroll
            for (int c = 0; c < 4; c++) acc[a][b][c] = 0.f;

    const int k_extra = (g & 1) * 8;
    const int n_extra = (g >> 1) * 8;
    const int nch = K / 64;

    copyChunk(0);
    cp_commit();
    for (int t = 0; t < nch; t++) {
        if (t + 1 < nch) { copyChunk(t + 1); cp_commit(); cp_wait1(); }
        else cp_wait0();
        __syncthreads();
        uint32_t ab = sb + (t & 1) * 65536;
        uint32_t bb = ab + 32768;
#pragma unroll
        for (int ks = 0; ks < 4; ks++) {
            uint32_t Bhf[2][4], Blf[2][4];
#pragma unroll
            for (int b = 0; b < 2; b++) {
                int kx = ks * 16 + k_extra + gr;
                int nf = wn * 32 + b * 16 + n_extra;
                uint32_t off = kx * 256 + ((((nf >> 3) ^ (kx & 7))) << 4);
                ldsm_x4_t(Bhf[b], bb + off);
                ldsm_x4_t(Blf[b], bb + 16384 + off);
            }
#pragma unroll
            for (int ma = 0; ma < 4; ma++) {
                int rowa = wm * 64 + ma * 16 + (g & 1) * 8 + gr;
                int kk = ks * 16 + n_extra;
                uint32_t ao = rowa * 128 + ((((kk >> 3) ^ (rowa & 7))) << 4);
                uint32_t Ahf[4], Alf[4];
                ldsm_x4(Ahf, ab + ao);
                ldsm_x4(Alf, ab + 16384 + ao);
#pragma unroll
                for (int b = 0; b < 2; b++) {
                    mma16816(acc[ma][2 * b],     Ahf, Bhf[b][0], Bhf[b][1]);
                    mma16816(acc[ma][2 * b],     Ahf, Blf[b][0], Blf[b][1]);
                    mma16816(acc[ma][2 * b],     Alf, Bhf[b][0], Bhf[b][1]);
                    mma16816(acc[ma][2 * b + 1], Ahf, Bhf[b][2], Bhf[b][3]);
                    mma16816(acc[ma][2 * b + 1], Ahf, Blf[b][2], Blf[b][3]);
                    mma16816(acc[ma][2 * b + 1], Alf, Bhf[b][2], Bhf[b][3]);
                }
            }
        }
        __syncthreads();
    }

    // ---- SMEM-staged epilogue ----
    float* stage = (float*)smem;
#pragma unroll
    for (int ma = 0; ma < 4; ma++) {
        int lr = wm * 64 + ma * 16 + (lane >> 2);
#pragma unroll
        for (int na = 0; na < 4; na++) {
            int lc = wn * 32 + na * 8 + (lane & 3) * 2;
            float v0 = acc[ma][na][0], v1 = acc[ma][na][1];
            float v2 = acc[ma][na][2], v3 = acc[ma][na][3];
            if (epi == 0) { v0 = gelu_exact(v0); v1 = gelu_exact(v1);
                            v2 = gelu_exact(v2); v3 = gelu_exact(v3); }
            stage[lr * 132 + lc] = v0;
            stage[lr * 132 + lc + 1] = v1;
            stage[(lr + 8) * 132 + lc] = v2;
            stage[(lr + 8) * 132 + lc + 1] = v3;
        }
    }
    __syncthreads();

    if (epi == 0) {
#pragma unroll
        for (int it = 0; it < 8; it++) {
            int idx = tid + it * 256;
            int r = idx >> 4, c8 = (idx & 15) * 8;
            float4 a = *(float4*)&stage[r * 132 + c8];
            float4 b = *(float4*)&stage[r * 132 + c8 + 4];
            uint16_t h[8], l[8];
            split_bf16(a.x, h[0], l[0]); split_bf16(a.y, h[1], l[1]);
            split_bf16(a.z, h[2], l[2]); split_bf16(a.w, h[3], l[3]);
            split_bf16(b.x, h[4], l[4]); split_bf16(b.y, h[5], l[5]);
            split_bf16(b.z, h[6], l[6]); split_bf16(b.w, h[7], l[7]);
            size_t o = ((size_t)e * Nq + m0 + r) * Fq + n0 + c8;
            *(uint4*)(Oh + o) = make_uint4(
                (uint32_t)h[0] | ((uint32_t)h[1] << 16), (uint32_t)h[2] | ((uint32_t)h[3] << 16),
                (uint32_t)h[4] | ((uint32_t)h[5] << 16), (uint32_t)h[6] | ((uint32_t)h[7] << 16));
            *(uint4*)(Ol + o) = make_uint4(
                (uint32_t)l[0] | ((uint32_t)l[1] << 16), (uint32_t)l[2] | ((uint32_t)l[3] << 16),
                (uint32_t)l[4] | ((uint32_t)l[5] << 16), (uint32_t)l[6] | ((uint32_t)l[7] << 16));
        }
    } else if (epi == 1) {
#pragma unroll
        for (int it = 0; it < 16; it++) {
            int idx = tid + it * 256;
            int r = idx >> 5, c4 = (idx & 31) * 4;
            int slot = m0 + r;
            if (slot >= ce) continue;
            int t = tokE ? tokE[slot] : slot;
            float4 v = *(float4*)&stage[r * 132 + c4];
            *(float4*)&fout[((size_t)t * Eq + e) * Cq + n0 + c4] = v;
        }
    } else {
#pragma unroll
        for (int it = 0; it < 16; it++) {
            int idx = tid + it * 256;
            int r = idx >> 5, c4 = (idx & 31) * 4;
            float4 v = *(float4*)&stage[r * 132 + c4];
            size_t o = (size_t)(m0 + r) * ldo + n0 + c4;
            if (res) {
                float4 rr = *(const float4*)&res[o];
                v.x += rr.x; v.y += rr.y; v.z += rr.z; v.w += rr.w;
            }
            *(float4*)&fout[o] = v;
        }
    }
}

// ================= lm_head HMMA GEMM (R8-passing version) =================
static constexpr int SM_B_HI = 0;
static constexpr int SM_B_LO = 65536;
static constexpr int SM_A    = 131072;
static constexpr int LM_SMEM = 196608;

__global__ void __launch_bounds__(256, 1) k_lmhead_mma(const __nv_bfloat16* __restrict__ Ah,
                                                       const __nv_bfloat16* __restrict__ Al,
                                                       const __nv_bfloat16* __restrict__ Bh,
                                                       const __nv_bfloat16* __restrict__ Bl,
                                                       float* __restrict__ out) {
    extern __shared__ char smem[];
    uint32_t sb = smem_u32(smem);
    int tid = threadIdx.x;
    int wid = tid >> 5, lane = tid & 31;
    int wm = wid >> 2, wn = wid & 3;
    int g = lane >> 3, gr = lane & 7;
    int n0 = blockIdx.x * 128;

#pragma unroll
    for (int it = 0; it < 32; it++) {
        int lin = tid + it * 256;
        int half = lin >> 12;
        int r = lin & 4095;
        int k = r >> 4, n8 = r & 15;
        uint32_t dst = sb + (half ? SM_B_LO : SM_B_HI) + k * 256 + (((n8 ^ (k & 7))) << 4);
        const __nv_bfloat16* srcb = (half ? Bl : Bh) + (size_t)k * VP + n0 + n8 * 8;
        cp16(dst, srcb);
    }
    auto copyA = [&](int t) {
        int mb = t >> 2;
        int kc = (t & 3) * 64;
        uint32_t abase = sb + SM_A + (t & 1) * 32768;
#pragma unroll
        for (int it = 0; it < 8; it++) {
            int lin = tid + it * 256;
            int half = lin >> 10;
            int r = lin & 1023;
            int m = r >> 3, k8 = r & 7;
            uint32_t dst = abase + half * 16384 + m * 128 + (((k8 ^ (m & 7))) << 4);
            const __nv_bfloat16* srca = (half ? Al : Ah) + (size_t)(mb * 128 + m) * Cq + kc + k8 * 8;
            cp16(dst, srca);
        }
    };
    copyA(0);
    cp_commit();

    float acc[4][4][4];
#pragma unroll
    for (int a = 0; a < 4; a++)
#pragma unroll
        for (int b = 0; b < 4; b++)
#pragma unroll
            for (int c = 0; c < 4; c++) acc[a][b][c] = 0.f;

    const int k_extra = (g & 1) * 8;
    const int n_extra = (g >> 1) * 8;

    for (int t = 0; t < 64; t++) {
        if (t + 1 < 64) { copyA(t + 1); cp_commit(); cp_wait1(); }
        else cp_wait0();
        __syncthreads();

        int kc = (t & 3) * 64;
        uint32_t ah_base = sb + SM_A + (t & 1) * 32768;
        uint32_t al_base = ah_base + 16384;
#pragma unroll
        for (int ks = 0; ks < 4; ks++) {
            uint32_t Bhf[2][4], Blf[2][4];
#pragma unroll
            for (int b = 0; b < 2; b++) {
                int kx = kc + ks * 16 + k_extra + gr;
                int nf = wn * 32 + b * 16 + n_extra;
                uint32_t off = kx * 256 + ((((nf >> 3) ^ (kx & 7))) << 4);
                ldsm_x4_t(Bhf[b], sb + SM_B_HI + off);
                ldsm_x4_t(Blf[b], sb + SM_B_LO + off);
            }
#pragma unroll
            for (int ma = 0; ma < 4; ma++) {
                int rowa = wm * 64 + ma * 16 + (g & 1) * 8 + gr;
                int kkl = ks * 16 + n_extra;
                uint32_t ao = rowa * 128 + ((((kkl >> 3) ^ (rowa & 7))) << 4);
                uint32_t Ahf[4], Alf[4];
                ldsm_x4(Ahf, ah_base + ao);
                ldsm_x4(Alf, al_base + ao);
#pragma unroll
                for (int b = 0; b < 2; b++) {
                    mma16816(acc[ma][2 * b],     Ahf, Bhf[b][0], Bhf[b][1]);
                    mma16816(acc[ma][2 * b],     Ahf, Blf[b][0], Blf[b][1]);
                    mma16816(acc[ma][2 * b],     Alf, Bhf[b][0], Bhf[b][1]);
                    mma16816(acc[ma][2 * b + 1], Ahf, Bhf[b][2], Bhf[b][3]);
                    mma16816(acc[ma][2 * b + 1], Ahf, Blf[b][2], Blf[b][3]);
                    mma16816(acc[ma][2 * b + 1], Alf, Bhf[b][2], Bhf[b][3]);
                }
            }
        }
        if ((t & 3) == 3) {
            // scalar stores: Vq odd -> wider stores misalign on odd rows
            int mbase = (t >> 2) * 128 + wm * 64;
#pragma unroll
            for (int ma = 0; ma < 4; ma++) {
#pragma unroll
                for (int na = 0; na < 4; na++) {
                    int gm = mbase + ma * 16 + (lane >> 2);
                    int gn = n0 + wn * 32 + na * 8 + (lane & 3) * 2;
                    float* p0 = out + (size_t)gm * Vq + gn;
                    float* p1 = out + (size_t)(gm + 8) * Vq + gn;
                    if (gn < Vq)     { p0[0] = acc[ma][na][0]; p1[0] = acc[ma][na][2]; }
                    if (gn + 1 < Vq) { p0[1] = acc[ma][na][1]; p1[1] = acc[ma][na][3]; }
                    acc[ma][na][0] = acc[ma][na][1] = acc[ma][na][2] = acc[ma][na][3] = 0.f;
                }
            }
        }
        __syncthreads();
    }
}

// ---------------- fused embed + LN1 + bf16 split ----------------
__global__ void k_embed_ln(const int* __restrict__ ids, const float* __restrict__ emb,
                           const float* __restrict__ w, const float* __restrict__ b,
                           float* __restrict__ hs,
                           __nv_bfloat16* __restrict__ hi, __nv_bfloat16* __restrict__ lo) {
    int t = blockIdx.x, c = threadIdx.x;
    float x = emb[(size_t)ids[t] * Cq + c];
    hs[(size_t)t * Cq + c] = x;
    __shared__ float red[8];
    float s = x;
#pragma unroll
    for (int o = 16; o; o >>= 1) s += __shfl_xor_sync(0xffffffffu, s, o);
    if ((c & 31) == 0) red[c >> 5] = s;
    __syncthreads();
    float mu = 0.f;
#pragma unroll
    for (int i = 0; i < 8; i++) mu += red[i];
    mu *= (1.f / Cq);
    float d = x - mu;
    float s2 = d * d;
#pragma unroll
    for (int o = 16; o; o >>= 1) s2 += __shfl_xor_sync(0xffffffffu, s2, o);
    __syncthreads();
    if ((c & 31) == 0) red[c >> 5] = s2;
    __syncthreads();
    float var = 0.f;
#pragma unroll
    for (int i = 0; i < 8; i++) var += red[i];
    var *= (1.f / Cq);
    float y = d * rsqrtf(var + 1e-5f) * w[c] + b[c];
    uint16_t h, l;
    split_bf16(y, h, l);
    ((uint16_t*)hi)[(size_t)t * Cq + c] = h;
    ((uint16_t*)lo)[(size_t)t * Cq + c] = l;
}

// ---------------- layernorm fused with bf16 split ----------------
__global__ void k_layernorm_split(const float* __restrict__ in, const float* __restrict__ w,
                                  const float* __restrict__ b, float* __restrict__ fp32out,
                                  __nv_bfloat16* __restrict__ hi, __nv_bfloat16* __restrict__ lo) {
    int t = blockIdx.x, c = threadIdx.x;
    float x = in[(size_t)t * Cq + c];
    __shared__ float red[8];
    float s = x;
#pragma unroll
    for (int o = 16; o; o >>= 1) s += __shfl_xor_sync(0xffffffffu, s, o);
    if ((c & 31) == 0) red[c >> 5] = s;
    __syncthreads();
    float mu = 0.f;
#pragma unroll
    for (int i = 0; i < 8; i++) mu += red[i];
    mu *= (1.f / Cq);
    float d = x - mu;
    float s2 = d * d;
#pragma unroll
    for (int o = 16; o; o >>= 1) s2 += __shfl_xor_sync(0xffffffffu, s2, o);
    __syncthreads();
    if ((c & 31) == 0) red[c >> 5] = s2;
    __syncthreads();
    float var = 0.f;
#pragma unroll
    for (int i = 0; i < 8; i++) var += red[i];
    var *= (1.f / Cq);
    float y = d * rsqrtf(var + 1e-5f) * w[c] + b[c];
    if (fp32out) fp32out[(size_t)t * Cq + c] = y;
    uint16_t h, l;
    split_bf16(y, h, l);
    ((uint16_t*)hi)[(size_t)t * Cq + c] = h;
    ((uint16_t*)lo)[(size_t)t * Cq + c] = l;
}

// ---------------- causal attention: 4-key unroll, __expf ----------------
__global__ void k_attn(const float* __restrict__ qkv, __nv_bfloat16* __restrict__ ohi,
                       __nv_bfloat16* __restrict__ olo) {
    int b = blockIdx.z, h = blockIdx.y;
    int t0 = blockIdx.x * 64;
    int qi = t0 + threadIdx.x;
    const float scale = 0.17677669529663687f;
    float qr[Dq];
    const float* qp = qkv + ((size_t)(b * Tq + qi)) * C3 + h * Dq;
#pragma unroll
    for (int d = 0; d < Dq; d++) qr[d] = qp[d] * scale;
    float acc[Dq];
#pragma unroll
    for (int d = 0; d < Dq; d++) acc[d] = 0.f;
    float m = -INFINITY, l = 0.f;
    __shared__ float Ks[64 * Dq], Vs[64 * Dq];

    for (int kt = 0; kt < t0 + 64; kt += 64) {
#pragma unroll
        for (int i = threadIdx.x; i < 512; i += 64) {
            int r = i >> 3, d4 = (i & 7) * 4;
            size_t gi = ((size_t)(b * Tq + kt + r)) * C3 + h * Dq + d4;
            *(float4*)&Ks[r * Dq + d4] = *(const float4*)&qkv[gi + Cq];
            *(float4*)&Vs[r * Dq + d4] = *(const float4*)&qkv[gi + 2 * Cq];
        }
        __syncthreads();
        int jmax = qi - kt + 1;
        if (jmax > 64) jmax = 64;
        int j = 0;
        for (; j + 3 < jmax; j += 4) {
            float s0 = 0.f, s1 = 0.f, s2 = 0.f, s3 = 0.f;
#pragma unroll
            for (int d = 0; d < Dq; d++) {
                float qv = qr[d];
                s0 += qv * Ks[(j + 0) * Dq + d];
                s1 += qv * Ks[(j + 1) * Dq + d];
                s2 += qv * Ks[(j + 2) * Dq + d];
                s3 += qv * Ks[(j + 3) * Dq + d];
            }
            float mx = fmaxf(fmaxf(s0, s1), fmaxf(s2, s3));
            float nm = fmaxf(m, mx);
            float corr = __expf(m - nm);
            float p0 = __expf(s0 - nm), p1 = __expf(s1 - nm);
            float p2 = __expf(s2 - nm), p3 = __expf(s3 - nm);
            l = l * corr + p0 + p1 + p2 + p3;
#pragma unroll
            for (int d = 0; d < Dq; d++)
                acc[d] = acc[d] * corr + p0 * Vs[(j + 0) * Dq + d] + p1 * Vs[(j + 1) * Dq + d]
                                       + p2 * Vs[(j + 2) * Dq + d] + p3 * Vs[(j + 3) * Dq + d];
            m = nm;
        }
        for (; j < jmax; j++) {
            float s = 0.f;
#pragma unroll
            for (int d = 0; d < Dq; d++) s += qr[d] * Ks[j * Dq + d];
            float nm = fmaxf(m, s);
            float corr = __expf(m - nm);
            float p = __expf(s - nm);
            l = l * corr + p;
#pragma unroll
            for (int d = 0; d < Dq; d++) acc[d] = acc[d] * corr + p * Vs[j * Dq + d];
            m = nm;
        }
        __syncthreads();
    }
    float inv = 1.f / l;
    size_t ob = ((size_t)(b * Tq + qi)) * Cq + h * Dq;
#pragma unroll
    for (int d = 0; d < Dq; d++) {
        uint16_t hh, ll;
        split_bf16(acc[d] * inv, hh, ll);
        ((uint16_t*)ohi)[ob + d] = hh;
        ((uint16_t*)olo)[ob + d] = ll;
    }
}

// ---------------- normalize sim_matrix columns ----------------
__global__ void k_simnorm(const float* __restrict__ sim, float* __restrict__ sn) {
    __shared__ float ps[8][32];
    __shared__ float inv[32];
    int tid = threadIdx.x;
    int e = tid & 31, part = tid >> 5;
    float s = 0.f;
    for (int c = part * 32; c < part * 32 + 32; c++) {
        float vv = sim[(size_t)c * Eq + e];
        s += vv * vv;
    }
    ps[part][e] = s;
    __syncthreads();
    if (tid < 32) {
        float tot = 0.f;
#pragma unroll
        for (int p = 0; p < 8; p++) tot += ps[p][tid];
        inv[tid] = 1.f / fmaxf(sqrtf(tot), 1e-12f);
    }
    __syncthreads();
    for (int i = tid; i < Cq * Eq; i += 256) sn[i] = sim[i] * inv[i & 31];
}

// ---------------- fused gate: logits + decision + softmax + dispatch ----------------
__global__ void k_gate_fused(const float* __restrict__ xt, const float* __restrict__ sn,
                             const float* __restrict__ gates,
                             float* __restrict__ pre_o, float* __restrict__ am_o,
                             float* __restrict__ rw) {
    __shared__ float xs[8 * Cq];
    int tid = threadIdx.x;
    int t0 = blockIdx.x * 8;
    for (int i = tid; i < 8 * Cq; i += 256) xs[i] = xt[(size_t)t0 * Cq + i];
    __syncthreads();
    int w = tid >> 5, lane = tid & 31;
    int t = t0 + w;
    float s = 0.f;
    for (int c = lane; c < Cq; c += 32) {
        float vv = xs[w * Cq + c];
        s += vv * vv;
    }
#pragma unroll
    for (int o = 16; o; o >>= 1) s += __shfl_xor_sync(0xffffffffu, s, o);
    float inv = 1.f / fmaxf(sqrtf(s), 1e-12f);
    float acc = 0.f;
    for (int c = 0; c < Cq; c++) acc += xs[w * Cq + c] * sn[c * Eq + lane];
    float lg = acc * inv;

    float pre = lg - 1.f / (1.f + __expf(-gates[lane]));
    float gated = fmaxf(pre, 0.f);
    unsigned act = __ballot_sync(0xffffffffu, pre > 0.f);
    float am;
    if (act == 0u) {
        int rank = 0;
#pragma unroll
        for (int j = 0; j < 32; j++) {
            float lj = __shfl_sync(0xffffffffu, lg, j);
            rank += (lj > lg) || (lj == lg && j < lane);
        }
        am = (rank < 16) ? 1.f : 0.f;
    } else {
        am = (pre > 0.f) ? 1.f : 0.f;
    }
    float g2 = (am > 0.f) ? gated : -INFINITY;
    float mx = g2;
#pragma unroll
    for (int o = 16; o; o >>= 1) mx = fmaxf(mx, __shfl_xor_sync(0xffffffffu, mx, o));
    float p = (am > 0.f) ? __expf(gated - mx) : 0.f;
    float sum = p;
#pragma unroll
    for (int o = 16; o; o >>= 1) sum += __shfl_xor_sync(0xffffffffu, sum, o);
    rw[(size_t)t * Eq + lane] = p / sum;
    pre_o[(size_t)t * Eq + lane] = pre;
    am_o[(size_t)t * Eq + lane] = am;
    if (am > 0.f) {
        int slot = atomicAdd(&g_cnt[lane], 1);
        g_tok[lane * Nq + slot] = t;
    }
}

// ---------------- combine + zero-inactive-feo + bf16 split ----------------
__global__ void k_combine_zero(const float* __restrict__ rw, const float* __restrict__ am,
                               float* __restrict__ feo, const float* __restrict__ hs,
                               __nv_bfloat16* __restrict__ hi, __nv_bfloat16* __restrict__ lo) {
    int t = blockIdx.x, c = threadIdx.x;
    __shared__ float rws[Eq];
    __shared__ float ams[Eq];
    if (c < Eq) {
        rws[c] = rw[(size_t)t * Eq + c];
        ams[c] = am[(size_t)t * Eq + c];
    }
    __syncthreads();
    float s = hs[(size_t)t * Cq + c];
#pragma unroll
    for (int e = 0; e < Eq; e++) {
        float* fp = &feo[((size_t)t * Eq + e) * Cq + c];
        if (ams[e] == 0.f) *fp = 0.f;
        else s += rws[e] * (*fp);
    }
    uint16_t h, l;
    split_bf16(s, h, l);
    ((uint16_t*)hi)[(size_t)t * Cq + c] = h;
    ((uint16_t*)lo)[(size_t)t * Cq + c] = l;
}

// ---------------- host ----------------
extern "C" void kernel_launch(void* const* d_in, const int* in_sizes, int n_in,
                              void* d_out, int out_size) {
    const int*   ids   = (const int*)d_in[0];
    const float* emb   = (const float*)d_in[1];
    const float* wq    = (const float*)d_in[2];
    const float* wk    = (const float*)d_in[3];
    const float* wv    = (const float*)d_in[4];
    const float* wo    = (const float*)d_in[5];
    const float* ln1w  = (const float*)d_in[6];
    const float* ln1b  = (const float*)d_in[7];
    const float* ln2w  = (const float*)d_in[8];
    const float* ln2b  = (const float*)d_in[9];
    const float* sim   = (const float*)d_in[10];
    const float* gates = (const float*)d_in[11];
    const float* w1    = (const float*)d_in[12];
    const float* w2    = (const float*)d_in[13];
    const float* lmh   = (const float*)d_in[14];

    float *hs, *qkv, *xt, *sn, *rw, *feo_s, *pre_s, *am_s;
    int *cnt, *tok;
    __nv_bfloat16 *ahi, *alo, *bhi, *blo, *xhi, *xlo, *w1h, *w1l, *w2h, *w2l;
    __nv_bfloat16 *w3h, *w3l, *wph, *wpl, *hh, *hl;
    cudaGetSymbolAddress((void**)&hs, g_hs);
    cudaGetSymbolAddress((void**)&qkv, g_qkv);
    cudaGetSymbolAddress((void**)&xt, g_xt);
    cudaGetSymbolAddress((void**)&sn, g_sn);
    cudaGetSymbolAddress((void**)&rw, g_rw);
    cudaGetSymbolAddress((void**)&feo_s, g_feo);
    cudaGetSymbolAddress((void**)&pre_s, g_pre);
    cudaGetSymbolAddress((void**)&am_s, g_am);
    cudaGetSymbolAddress((void**)&cnt, g_cnt);
    cudaGetSymbolAddress((void**)&tok, g_tok);
    cudaGetSymbolAddress((void**)&ahi, g_ahi);
    cudaGetSymbolAddress((void**)&alo, g_alo);
    cudaGetSymbolAddress((void**)&bhi, g_bhi);
    cudaGetSymbolAddress((void**)&blo, g_blo);
    cudaGetSymbolAddress((void**)&xhi, g_xhi);
    cudaGetSymbolAddress((void**)&xlo, g_xlo);
    cudaGetSymbolAddress((void**)&w1h, g_w1h);
    cudaGetSymbolAddress((void**)&w1l, g_w1l);
    cudaGetSymbolAddress((void**)&w2h, g_w2h);
    cudaGetSymbolAddress((void**)&w2l, g_w2l);
    cudaGetSymbolAddress((void**)&w3h, g_w3h);
    cudaGetSymbolAddress((void**)&w3l, g_w3l);
    cudaGetSymbolAddress((void**)&wph, g_wph);
    cudaGetSymbolAddress((void**)&wpl, g_wpl);
    cudaGetSymbolAddress((void**)&hh, g_hh);
    cudaGetSymbolAddress((void**)&hl, g_hl);

    float* out = (float*)d_out;
    const size_t NV  = (size_t)Nq * Vq;
    const size_t FEO = (size_t)Nq * Eq * Cq;
    const size_t NE  = (size_t)Nq * Eq;
    float *feo, *pre_o, *am_o;
    if ((size_t)out_size >= NV + FEO + 2 * NE) {
        feo = out + NV;
        pre_o = out + NV + FEO;
        am_o = pre_o + NE;
    } else {
        feo = feo_s; pre_o = pre_s; am_o = am_s;
    }

    cudaFuncSetAttribute(k_gemm_mma, cudaFuncAttributeMaxDynamicSharedMemorySize, MM_SMEM);
    cudaFuncSetAttribute(k_lmhead_mma, cudaFuncAttributeMaxDynamicSharedMemorySize, LM_SMEM);

    cudaMemsetAsync(cnt, 0, Eq * sizeof(int));
    // pre-split constant weights
    k_split_b<<<(Cq * VP / 2) / 256, 256>>>(lmh, bhi, blo);
    k_split_a<<<((size_t)Eq * Cq * Fq / 2) / 256, 256>>>(w1, w1h, w1l);
    k_split_a<<<((size_t)Eq * Fq * Cq / 2) / 256, 256>>>(w2, w2h, w2l);
    k_split_w3<<<(Cq * C3 / 2) / 256, 256>>>(wq, wk, wv, w3h, w3l);
    k_split_a<<<(Cq * Cq / 2) / 256, 256>>>(wo, wph, wpl);

    // embed + ln1 + split
    k_embed_ln<<<Nq, Cq>>>(ids, emb, ln1w, ln1b, hs, ahi, alo);

    // fused QKV GEMM -> packed qkv [t][768]
    k_gemm_mma<<<dim3(C3 / 128, Nq / 128), 256, MM_SMEM>>>(
        ahi, alo, w3h, w3l, nullptr, nullptr, qkv, nullptr, nullptr, nullptr,
        Cq, Cq, C3, C3, 0, 2);

    // attention -> bf16 split output (reuses ahi/alo)
    k_attn<<<dim3(Tq / 64, Hq, Bq), 64>>>(qkv, ahi, alo);

    // hs = hs + attn_out @ wo
    k_gemm_mma<<<dim3(Cq / 128, Nq / 128), 256, MM_SMEM>>>(
        ahi, alo, wph, wpl, nullptr, nullptr, hs, hs, nullptr, nullptr,
        Cq, Cq, Cq, Cq, 0, 2);

    // ln2 -> fp32 xt (for gating) + bf16 split (for MoE)
    k_layernorm_split<<<Nq, Cq>>>(hs, ln2w, ln2b, xt, xhi, xlo);
    k_simnorm<<<1, 256>>>(sim, sn);
    k_gate_fused<<<Nq / 8, 256>>>(xt, sn, gates, pre_o, am_o, rw);

    // sparse MoE: up-proj gathers active tokens per expert, down-proj scatters
    k_gemm_mma<<<dim3(Fq / 128, Nq / 128, Eq), 256, MM_SMEM>>>(
        xhi, xlo, w1h, w1l, hh, hl, nullptr, nullptr, tok, cnt,
        Cq, Cq, Fq, 0, 0, 0);
    k_gemm_mma<<<dim3(Cq / 128, Nq / 128, Eq), 256, MM_SMEM>>>(
        hh, hl, w2h, w2l, nullptr, nullptr, feo, nullptr, tok, cnt,
        Fq, Fq, Cq, 0, Nq * Fq, 1);

    // combine + zero inactive feo + split for lm_head input
    k_combine_zero<<<Nq, Cq>>>(rw, am_o, feo, hs, ahi, alo);

    // lm_head
    k_lmhead_mma<<<VP / 128, 256, LM_SMEM>>>(ahi, alo, bhi, blo, out);
}

// round 13
// speedup vs baseline: 4.3513x; 1.0277x over previous
#include <cuda_runtime.h>
#include <cuda_bf16.h>
#include <math.h>
#include <stdint.h>

// ---------------- problem constants ----------------
static constexpr int Bq = 2;
static constexpr int Tq = 1024;
static constexpr int Cq = 256;
static constexpr int Fq = 1024;
static constexpr int Eq = 32;
static constexpr int Vq = 50257;
static constexpr int Hq = 8;
static constexpr int Dq = 32;      // Cq / Hq
static constexpr int Nq = Bq * Tq; // 2048 tokens
static constexpr int VP = 50304;   // Vq padded to 128 (393 tiles)
static constexpr int C3 = 3 * Cq;  // 768, packed QKV width

// ---------------- device scratch (no allocations allowed) ----------------
__device__ float g_hs[Nq * Cq];
__device__ float g_qkv[Nq * C3];
__device__ float g_xt[Nq * Cq];
__device__ float g_sn[Cq * Eq];
__device__ float g_rw[Nq * Eq];
__device__ float g_feo[(size_t)Nq * Eq * Cq];
__device__ float g_pre[Nq * Eq];
__device__ float g_am[Nq * Eq];
// MoE dispatch
__device__ int g_cnt[Eq];
__device__ int g_tok[Eq * Nq];
// bf16 hi/lo splits
__device__ __nv_bfloat16 g_ahi[Nq * Cq];           // x -> attn-out -> combine-out
__device__ __nv_bfloat16 g_alo[Nq * Cq];
__device__ __nv_bfloat16 g_bhi[(size_t)Cq * VP];   // lm_head
__device__ __nv_bfloat16 g_blo[(size_t)Cq * VP];
__device__ __nv_bfloat16 g_xhi[Nq * Cq];           // xt (MoE)
__device__ __nv_bfloat16 g_xlo[Nq * Cq];
__device__ __nv_bfloat16 g_w1h[(size_t)Eq * Cq * Fq];
__device__ __nv_bfloat16 g_w1l[(size_t)Eq * Cq * Fq];
__device__ __nv_bfloat16 g_w2h[(size_t)Eq * Fq * Cq];
__device__ __nv_bfloat16 g_w2l[(size_t)Eq * Fq * Cq];
__device__ __nv_bfloat16 g_w3h[Cq * C3];           // packed wq|wk|wv
__device__ __nv_bfloat16 g_w3l[Cq * C3];
__device__ __nv_bfloat16 g_wph[Cq * Cq];           // wo
__device__ __nv_bfloat16 g_wpl[Cq * Cq];
__device__ __nv_bfloat16 g_hh[(size_t)Eq * Nq * Fq];  // compact gelu(X@W1) hi
__device__ __nv_bfloat16 g_hl[(size_t)Eq * Nq * Fq];

// ================= helpers =================
__device__ __forceinline__ uint32_t smem_u32(const void* p) {
    uint32_t a;
    asm("{ .reg .u64 t; cvta.to.shared.u64 t, %1; cvt.u32.u64 %0, t; }" : "=r"(a) : "l"(p));
    return a;
}
__device__ __forceinline__ void split_bf16(float f, uint16_t& hi, uint16_t& lo) {
    __nv_bfloat16 h = __float2bfloat16(f);
    hi = __bfloat16_as_ushort(h);
    lo = __bfloat16_as_ushort(__float2bfloat16(f - __bfloat162float(h)));
}
__device__ __forceinline__ void cp16(uint32_t dst, const void* gsrc) {
    uint64_t g = __cvta_generic_to_global(gsrc);
    asm volatile("cp.async.ca.shared.global [%0], [%1], 16;" :: "r"(dst), "l"(g));
}
__device__ __forceinline__ void cp_commit() { asm volatile("cp.async.commit_group;"); }
__device__ __forceinline__ void cp_wait1() { asm volatile("cp.async.wait_group 1;" ::: "memory"); }
__device__ __forceinline__ void cp_wait0() { asm volatile("cp.async.wait_group 0;" ::: "memory"); }
__device__ __forceinline__ void ldsm_x4(uint32_t* r, uint32_t a) {
    asm volatile("ldmatrix.sync.aligned.m8n8.x4.shared.b16 {%0,%1,%2,%3}, [%4];"
                 : "=r"(r[0]), "=r"(r[1]), "=r"(r[2]), "=r"(r[3]) : "r"(a) : "memory");
}
__device__ __forceinline__ void ldsm_x4_t(uint32_t* r, uint32_t a) {
    asm volatile("ldmatrix.sync.aligned.m8n8.x4.trans.shared.b16 {%0,%1,%2,%3}, [%4];"
                 : "=r"(r[0]), "=r"(r[1]), "=r"(r[2]), "=r"(r[3]) : "r"(a) : "memory");
}
__device__ __forceinline__ void mma16816(float* c, const uint32_t* a, uint32_t b0, uint32_t b1) {
    asm volatile(
        "mma.sync.aligned.m16n8k16.row.col.f32.bf16.bf16.f32 "
        "{%0,%1,%2,%3}, {%4,%5,%6,%7}, {%8,%9}, {%0,%1,%2,%3};"
        : "+f"(c[0]), "+f"(c[1]), "+f"(c[2]), "+f"(c[3])
        : "r"(a[0]), "r"(a[1]), "r"(a[2]), "r"(a[3]), "r"(b0), "r"(b1));
}
__device__ __forceinline__ float gelu_exact(float x) {
    return 0.5f * x * (1.0f + erff(x * 0.70710678118654752f));
}

// ---------------- mega split: ALL constant weights in one kernel ----------------
// flat pair-index regions (all boundaries multiple of 256):
static constexpr size_t P_W1 = (size_t)Eq * Cq * Fq / 2;           //  4,194,304
static constexpr size_t P_W2 = P_W1 + (size_t)Eq * Fq * Cq / 2;    //  8,388,608
static constexpr size_t P_W3 = P_W2 + (size_t)Cq * C3 / 2;         //  8,486,912
static constexpr size_t P_WO = P_W3 + (size_t)Cq * Cq / 2;         //  8,519,680
static constexpr size_t P_LM = P_WO + (size_t)Cq * VP / 2;         // 14,958,592

__global__ void k_split_all(const float* __restrict__ w1, const float* __restrict__ w2,
                            const float* __restrict__ wq, const float* __restrict__ wk,
                            const float* __restrict__ wv, const float* __restrict__ wo,
                            const float* __restrict__ lmh,
                            __nv_bfloat16* __restrict__ w1h, __nv_bfloat16* __restrict__ w1l,
                            __nv_bfloat16* __restrict__ w2h, __nv_bfloat16* __restrict__ w2l,
                            __nv_bfloat16* __restrict__ w3h, __nv_bfloat16* __restrict__ w3l,
                            __nv_bfloat16* __restrict__ wph, __nv_bfloat16* __restrict__ wpl,
                            __nv_bfloat16* __restrict__ bhi, __nv_bfloat16* __restrict__ blo) {
    size_t i = (size_t)blockIdx.x * 256 + threadIdx.x;
    float v0, v1;
    __nv_bfloat16 *dh, *dl;
    size_t o;
    if (i < P_W1) {
        o = i;
        float2 v = *(const float2*)&w1[o * 2];
        v0 = v.x; v1 = v.y; dh = w1h; dl = w1l;
    } else if (i < P_W2) {
        o = i - P_W1;
        float2 v = *(const float2*)&w2[o * 2];
        v0 = v.x; v1 = v.y; dh = w2h; dl = w2l;
    } else if (i < P_W3) {
        o = i - P_W2;                       // packed wq|wk|wv -> [Cq][768]
        int k = (int)(o / (C3 / 2));
        int n = (int)(o - (size_t)k * (C3 / 2)) * 2;
        const float* src = (n < Cq) ? wq : ((n < 2 * Cq) ? wk : wv);
        int nn = n & (Cq - 1);
        v0 = src[k * Cq + nn]; v1 = src[k * Cq + nn + 1];
        dh = w3h; dl = w3l;
    } else if (i < P_WO) {
        o = i - P_W3;
        float2 v = *(const float2*)&wo[o * 2];
        v0 = v.x; v1 = v.y; dh = wph; dl = wpl;
    } else {
        o = i - P_WO;                       // lm_head padded [Cq][VP]
        int k = (int)(o / (VP / 2));
        int n = (int)(o - (size_t)k * (VP / 2)) * 2;
        v0 = (n < Vq) ? lmh[(size_t)k * Vq + n] : 0.f;
        v1 = (n + 1 < Vq) ? lmh[(size_t)k * Vq + n + 1] : 0.f;
        dh = bhi; dl = blo;
    }
    uint16_t h0, l0, h1, l1;
    split_bf16(v0, h0, l0);
    split_bf16(v1, h1, l1);
    ((uint32_t*)dh)[o] = (uint32_t)h0 | ((uint32_t)h1 << 16);
    ((uint32_t*)dl)[o] = (uint32_t)l0 | ((uint32_t)l1 << 16);
}

// ================= generic HMMA GEMM (bf16 3-split) =================
static constexpr int MM_SMEM = 131072;

__global__ void __launch_bounds__(256, 1) k_gemm_mma(
    const __nv_bfloat16* __restrict__ Ah, const __nv_bfloat16* __restrict__ Al,
    const __nv_bfloat16* __restrict__ Bh, const __nv_bfloat16* __restrict__ Bl,
    __nv_bfloat16* __restrict__ Oh, __nv_bfloat16* __restrict__ Ol,
    float* __restrict__ fout, const float* __restrict__ res,
    const int* __restrict__ toks, const int* __restrict__ cnts,
    int K, int lda, int ldb, int ldo, int aExpStride, int epi) {
    extern __shared__ char smem[];
    uint32_t sb = smem_u32(smem);
    int tid = threadIdx.x, wid = tid >> 5, lane = tid & 31;
    int wm = wid >> 2, wn = wid & 3;
    int g = lane >> 3, gr = lane & 7;
    int n0 = blockIdx.x * 128, m0 = blockIdx.y * 128, e = blockIdx.z;

    int ce = cnts ? cnts[e] : 0x7fffffff;
    if (cnts) {
        int lim = (epi == 0) ? ((ce + 127) & ~127) : ce;
        if (m0 >= lim) return;
    }
    const int* tokE = toks ? toks + (size_t)e * Nq : nullptr;

    const __nv_bfloat16* Abh = Ah + (size_t)e * aExpStride;
    const __nv_bfloat16* Abl = Al + (size_t)e * aExpStride;
    const __nv_bfloat16* Bbh = Bh + (size_t)e * K * ldb + n0;
    const __nv_bfloat16* Bbl = Bl + (size_t)e * K * ldb + n0;

    auto copyChunk = [&](int ch) {
        uint32_t base = sb + (ch & 1) * 65536;
        int kc = ch * 64;
#pragma unroll
        for (int it = 0; it < 8; it++) {         // A: [128m][64k] hi+lo
            int lin = tid + it * 256;
            int half = lin >> 10;
            int r = lin & 1023;
            int m = r >> 3, k8 = r & 7;
            int row = m0 + m;
            if (epi == 0 && tokE) {              // token gather (up-proj), clamp pad
                int slot = row;
                if (slot >= ce) slot = ce - 1;
                row = tokE[slot];
            }
            uint32_t dst = base + half * 16384 + m * 128 + (((k8 ^ (m & 7))) << 4);
            cp16(dst, (half ? Abl : Abh) + (size_t)row * lda + kc + k8 * 8);
        }
#pragma unroll
        for (int it = 0; it < 8; it++) {         // B: [64k][128n] hi+lo
            int lin = tid + it * 256;
            int half = lin >> 10;
            int r = lin & 1023;
            int k = r >> 4, n8 = r & 15;
            uint32_t dst = base + 32768 + half * 16384 + k * 256 + (((n8 ^ (k & 7))) << 4);
            cp16(dst, (half ? Bbl : Bbh) + (size_t)(kc + k) * ldb + n8 * 8);
        }
    };

    float acc[4][4][4];
#pragma unroll
    for (int a = 0; a < 4; a++)
#pragma unroll
        for (int b = 0; b < 4; b++)
#pragma unroll
            for (int c = 0; c < 4; c++) acc[a][b][c] = 0.f;

    const int k_extra = (g & 1) * 8;
    const int n_extra = (g >> 1) * 8;
    const int nch = K / 64;

    copyChunk(0);
    cp_commit();
    for (int t = 0; t < nch; t++) {
        if (t + 1 < nch) { copyChunk(t + 1); cp_commit(); cp_wait1(); }
        else cp_wait0();
        __syncthreads();
        uint32_t ab = sb + (t & 1) * 65536;
        uint32_t bb = ab + 32768;
#pragma unroll
        for (int ks = 0; ks < 4; ks++) {
            uint32_t Bhf[2][4], Blf[2][4];
#pragma unroll
            for (int b = 0; b < 2; b++) {
                int kx = ks * 16 + k_extra + gr;
                int nf = wn * 32 + b * 16 + n_extra;
                uint32_t off = kx * 256 + ((((nf >> 3) ^ (kx & 7))) << 4);
                ldsm_x4_t(Bhf[b], bb + off);
                ldsm_x4_t(Blf[b], bb + 16384 + off);
            }
#pragma unroll
            for (int ma = 0; ma < 4; ma++) {
                int rowa = wm * 64 + ma * 16 + (g & 1) * 8 + gr;
                int kk = ks * 16 + n_extra;
                uint32_t ao = rowa * 128 + ((((kk >> 3) ^ (rowa & 7))) << 4);
                uint32_t Ahf[4], Alf[4];
                ldsm_x4(Ahf, ab + ao);
                ldsm_x4(Alf, ab + 16384 + ao);
#pragma unroll
                for (int b = 0; b < 2; b++) {
                    mma16816(acc[ma][2 * b],     Ahf, Bhf[b][0], Bhf[b][1]);
                    mma16816(acc[ma][2 * b],     Ahf, Blf[b][0], Blf[b][1]);
                    mma16816(acc[ma][2 * b],     Alf, Bhf[b][0], Bhf[b][1]);
                    mma16816(acc[ma][2 * b + 1], Ahf, Bhf[b][2], Bhf[b][3]);
                    mma16816(acc[ma][2 * b + 1], Ahf, Blf[b][2], Blf[b][3]);
                    mma16816(acc[ma][2 * b + 1], Alf, Bhf[b][2], Bhf[b][3]);
                }
            }
        }
        __syncthreads();
    }

    // ---- SMEM-staged epilogue ----
    float* stage = (float*)smem;
#pragma unroll
    for (int ma = 0; ma < 4; ma++) {
        int lr = wm * 64 + ma * 16 + (lane >> 2);
#pragma unroll
        for (int na = 0; na < 4; na++) {
            int lc = wn * 32 + na * 8 + (lane & 3) * 2;
            float v0 = acc[ma][na][0], v1 = acc[ma][na][1];
            float v2 = acc[ma][na][2], v3 = acc[ma][na][3];
            if (epi == 0) { v0 = gelu_exact(v0); v1 = gelu_exact(v1);
                            v2 = gelu_exact(v2); v3 = gelu_exact(v3); }
            stage[lr * 132 + lc] = v0;
            stage[lr * 132 + lc + 1] = v1;
            stage[(lr + 8) * 132 + lc] = v2;
            stage[(lr + 8) * 132 + lc + 1] = v3;
        }
    }
    __syncthreads();

    if (epi == 0) {
#pragma unroll
        for (int it = 0; it < 8; it++) {
            int idx = tid + it * 256;
            int r = idx >> 4, c8 = (idx & 15) * 8;
            float4 a = *(float4*)&stage[r * 132 + c8];
            float4 b = *(float4*)&stage[r * 132 + c8 + 4];
            uint16_t h[8], l[8];
            split_bf16(a.x, h[0], l[0]); split_bf16(a.y, h[1], l[1]);
            split_bf16(a.z, h[2], l[2]); split_bf16(a.w, h[3], l[3]);
            split_bf16(b.x, h[4], l[4]); split_bf16(b.y, h[5], l[5]);
            split_bf16(b.z, h[6], l[6]); split_bf16(b.w, h[7], l[7]);
            size_t o = ((size_t)e * Nq + m0 + r) * Fq + n0 + c8;
            *(uint4*)(Oh + o) = make_uint4(
                (uint32_t)h[0] | ((uint32_t)h[1] << 16), (uint32_t)h[2] | ((uint32_t)h[3] << 16),
                (uint32_t)h[4] | ((uint32_t)h[5] << 16), (uint32_t)h[6] | ((uint32_t)h[7] << 16));
            *(uint4*)(Ol + o) = make_uint4(
                (uint32_t)l[0] | ((uint32_t)l[1] << 16), (uint32_t)l[2] | ((uint32_t)l[3] << 16),
                (uint32_t)l[4] | ((uint32_t)l[5] << 16), (uint32_t)l[6] | ((uint32_t)l[7] << 16));
        }
    } else if (epi == 1) {
#pragma unroll
        for (int it = 0; it < 16; it++) {
            int idx = tid + it * 256;
            int r = idx >> 5, c4 = (idx & 31) * 4;
            int slot = m0 + r;
            if (slot >= ce) continue;
            int t = tokE ? tokE[slot] : slot;
            float4 v = *(float4*)&stage[r * 132 + c4];
            *(float4*)&fout[((size_t)t * Eq + e) * Cq + n0 + c4] = v;
        }
    } else {
#pragma unroll
        for (int it = 0; it < 16; it++) {
            int idx = tid + it * 256;
            int r = idx >> 5, c4 = (idx & 31) * 4;
            float4 v = *(float4*)&stage[r * 132 + c4];
            size_t o = (size_t)(m0 + r) * ldo + n0 + c4;
            if (res) {
                float4 rr = *(const float4*)&res[o];
                v.x += rr.x; v.y += rr.y; v.z += rr.z; v.w += rr.w;
            }
            *(float4*)&fout[o] = v;
        }
    }
}

// ================= lm_head HMMA GEMM (R8/R11-passing version) =================
static constexpr int SM_B_HI = 0;
static constexpr int SM_B_LO = 65536;
static constexpr int SM_A    = 131072;
static constexpr int LM_SMEM = 196608;

__global__ void __launch_bounds__(256, 1) k_lmhead_mma(const __nv_bfloat16* __restrict__ Ah,
                                                       const __nv_bfloat16* __restrict__ Al,
                                                       const __nv_bfloat16* __restrict__ Bh,
                                                       const __nv_bfloat16* __restrict__ Bl,
                                                       float* __restrict__ out) {
    extern __shared__ char smem[];
    uint32_t sb = smem_u32(smem);
    int tid = threadIdx.x;
    int wid = tid >> 5, lane = tid & 31;
    int wm = wid >> 2, wn = wid & 3;
    int g = lane >> 3, gr = lane & 7;
    int n0 = blockIdx.x * 128;

#pragma unroll
    for (int it = 0; it < 32; it++) {
        int lin = tid + it * 256;
        int half = lin >> 12;
        int r = lin & 4095;
        int k = r >> 4, n8 = r & 15;
        uint32_t dst = sb + (half ? SM_B_LO : SM_B_HI) + k * 256 + (((n8 ^ (k & 7))) << 4);
        const __nv_bfloat16* srcb = (half ? Bl : Bh) + (size_t)k * VP + n0 + n8 * 8;
        cp16(dst, srcb);
    }
    auto copyA = [&](int t) {
        int mb = t >> 2;
        int kc = (t & 3) * 64;
        uint32_t abase = sb + SM_A + (t & 1) * 32768;
#pragma unroll
        for (int it = 0; it < 8; it++) {
            int lin = tid + it * 256;
            int half = lin >> 10;
            int r = lin & 1023;
            int m = r >> 3, k8 = r & 7;
            uint32_t dst = abase + half * 16384 + m * 128 + (((k8 ^ (m & 7))) << 4);
            const __nv_bfloat16* srca = (half ? Al : Ah) + (size_t)(mb * 128 + m) * Cq + kc + k8 * 8;
            cp16(dst, srca);
        }
    };
    copyA(0);
    cp_commit();

    float acc[4][4][4];
#pragma unroll
    for (int a = 0; a < 4; a++)
#pragma unroll
        for (int b = 0; b < 4; b++)
#pragma unroll
            for (int c = 0; c < 4; c++) acc[a][b][c] = 0.f;

    const int k_extra = (g & 1) * 8;
    const int n_extra = (g >> 1) * 8;

    for (int t = 0; t < 64; t++) {
        if (t + 1 < 64) { copyA(t + 1); cp_commit(); cp_wait1(); }
        else cp_wait0();
        __syncthreads();

        int kc = (t & 3) * 64;
        uint32_t ah_base = sb + SM_A + (t & 1) * 32768;
        uint32_t al_base = ah_base + 16384;
#pragma unroll
        for (int ks = 0; ks < 4; ks++) {
            uint32_t Bhf[2][4], Blf[2][4];
#pragma unroll
            for (int b = 0; b < 2; b++) {
                int kx = kc + ks * 16 + k_extra + gr;
                int nf = wn * 32 + b * 16 + n_extra;
                uint32_t off = kx * 256 + ((((nf >> 3) ^ (kx & 7))) << 4);
                ldsm_x4_t(Bhf[b], sb + SM_B_HI + off);
                ldsm_x4_t(Blf[b], sb + SM_B_LO + off);
            }
#pragma unroll
            for (int ma = 0; ma < 4; ma++) {
                int rowa = wm * 64 + ma * 16 + (g & 1) * 8 + gr;
                int kkl = ks * 16 + n_extra;
                uint32_t ao = rowa * 128 + ((((kkl >> 3) ^ (rowa & 7))) << 4);
                uint32_t Ahf[4], Alf[4];
                ldsm_x4(Ahf, ah_base + ao);
                ldsm_x4(Alf, al_base + ao);
#pragma unroll
                for (int b = 0; b < 2; b++) {
                    mma16816(acc[ma][2 * b],     Ahf, Bhf[b][0], Bhf[b][1]);
                    mma16816(acc[ma][2 * b],     Ahf, Blf[b][0], Blf[b][1]);
                    mma16816(acc[ma][2 * b],     Alf, Bhf[b][0], Bhf[b][1]);
                    mma16816(acc[ma][2 * b + 1], Ahf, Bhf[b][2], Bhf[b][3]);
                    mma16816(acc[ma][2 * b + 1], Ahf, Blf[b][2], Blf[b][3]);
                    mma16816(acc[ma][2 * b + 1], Alf, Bhf[b][2], Bhf[b][3]);
                }
            }
        }
        if ((t & 3) == 3) {
            // scalar stores: Vq odd -> wider stores misalign on odd rows;
            // quad-contiguous 8-float groups still fill 32B sectors.
            int mbase = (t >> 2) * 128 + wm * 64;
#pragma unroll
            for (int ma = 0; ma < 4; ma++) {
#pragma unroll
                for (int na = 0; na < 4; na++) {
                    int gm = mbase + ma * 16 + (lane >> 2);
                    int gn = n0 + wn * 32 + na * 8 + (lane & 3) * 2;
                    float* p0 = out + (size_t)gm * Vq + gn;
                    float* p1 = out + (size_t)(gm + 8) * Vq + gn;
                    if (gn < Vq)     { p0[0] = acc[ma][na][0]; p1[0] = acc[ma][na][2]; }
                    if (gn + 1 < Vq) { p0[1] = acc[ma][na][1]; p1[1] = acc[ma][na][3]; }
                    acc[ma][na][0] = acc[ma][na][1] = acc[ma][na][2] = acc[ma][na][3] = 0.f;
                }
            }
        }
        __syncthreads();
    }
}

// ---------------- fused embed + LN1 + bf16 split ----------------
__global__ void k_embed_ln(const int* __restrict__ ids, const float* __restrict__ emb,
                           const float* __restrict__ w, const float* __restrict__ b,
                           float* __restrict__ hs,
                           __nv_bfloat16* __restrict__ hi, __nv_bfloat16* __restrict__ lo) {
    int t = blockIdx.x, c = threadIdx.x;
    float x = emb[(size_t)ids[t] * Cq + c];
    hs[(size_t)t * Cq + c] = x;
    __shared__ float red[8];
    float s = x;
#pragma unroll
    for (int o = 16; o; o >>= 1) s += __shfl_xor_sync(0xffffffffu, s, o);
    if ((c & 31) == 0) red[c >> 5] = s;
    __syncthreads();
    float mu = 0.f;
#pragma unroll
    for (int i = 0; i < 8; i++) mu += red[i];
    mu *= (1.f / Cq);
    float d = x - mu;
    float s2 = d * d;
#pragma unroll
    for (int o = 16; o; o >>= 1) s2 += __shfl_xor_sync(0xffffffffu, s2, o);
    __syncthreads();
    if ((c & 31) == 0) red[c >> 5] = s2;
    __syncthreads();
    float var = 0.f;
#pragma unroll
    for (int i = 0; i < 8; i++) var += red[i];
    var *= (1.f / Cq);
    float y = d * rsqrtf(var + 1e-5f) * w[c] + b[c];
    uint16_t h, l;
    split_bf16(y, h, l);
    ((uint16_t*)hi)[(size_t)t * Cq + c] = h;
    ((uint16_t*)lo)[(size_t)t * Cq + c] = l;
}

// ---------------- layernorm fused with bf16 split ----------------
__global__ void k_layernorm_split(const float* __restrict__ in, const float* __restrict__ w,
                                  const float* __restrict__ b, float* __restrict__ fp32out,
                                  __nv_bfloat16* __restrict__ hi, __nv_bfloat16* __restrict__ lo) {
    int t = blockIdx.x, c = threadIdx.x;
    float x = in[(size_t)t * Cq + c];
    __shared__ float red[8];
    float s = x;
#pragma unroll
    for (int o = 16; o; o >>= 1) s += __shfl_xor_sync(0xffffffffu, s, o);
    if ((c & 31) == 0) red[c >> 5] = s;
    __syncthreads();
    float mu = 0.f;
#pragma unroll
    for (int i = 0; i < 8; i++) mu += red[i];
    mu *= (1.f / Cq);
    float d = x - mu;
    float s2 = d * d;
#pragma unroll
    for (int o = 16; o; o >>= 1) s2 += __shfl_xor_sync(0xffffffffu, s2, o);
    __syncthreads();
    if ((c & 31) == 0) red[c >> 5] = s2;
    __syncthreads();
    float var = 0.f;
#pragma unroll
    for (int i = 0; i < 8; i++) var += red[i];
    var *= (1.f / Cq);
    float y = d * rsqrtf(var + 1e-5f) * w[c] + b[c];
    if (fp32out) fp32out[(size_t)t * Cq + c] = y;
    uint16_t h, l;
    split_bf16(y, h, l);
    ((uint16_t*)hi)[(size_t)t * Cq + c] = h;
    ((uint16_t*)lo)[(size_t)t * Cq + c] = l;
}

// ---------------- causal attention: 128 queries/block, 4-key unroll, __expf ----------------
__global__ void k_attn(const float* __restrict__ qkv, __nv_bfloat16* __restrict__ ohi,
                       __nv_bfloat16* __restrict__ olo) {
    int b = blockIdx.z, h = blockIdx.y;
    int t0 = blockIdx.x * 128;
    int qi = t0 + threadIdx.x;
    const float scale = 0.17677669529663687f;
    float qr[Dq];
    const float* qp = qkv + ((size_t)(b * Tq + qi)) * C3 + h * Dq;
#pragma unroll
    for (int d = 0; d < Dq; d++) qr[d] = qp[d] * scale;
    float acc[Dq];
#pragma unroll
    for (int d = 0; d < Dq; d++) acc[d] = 0.f;
    float m = -INFINITY, l = 0.f;
    __shared__ float Ks[64 * Dq], Vs[64 * Dq];

    for (int kt = 0; kt < t0 + 128; kt += 64) {
        // 512 float4 over 128 threads (4 iters)
#pragma unroll
        for (int i = threadIdx.x; i < 512; i += 128) {
            int r = i >> 3, d4 = (i & 7) * 4;
            size_t gi = ((size_t)(b * Tq + kt + r)) * C3 + h * Dq + d4;
            *(float4*)&Ks[r * Dq + d4] = *(const float4*)&qkv[gi + Cq];
            *(float4*)&Vs[r * Dq + d4] = *(const float4*)&qkv[gi + 2 * Cq];
        }
        __syncthreads();
        int jmax = qi - kt + 1;
        if (jmax > 64) jmax = 64;
        int j = 0;
        for (; j + 3 < jmax; j += 4) {
            float s0 = 0.f, s1 = 0.f, s2 = 0.f, s3 = 0.f;
#pragma unroll
            for (int d = 0; d < Dq; d++) {
                float qv = qr[d];
                s0 += qv * Ks[(j + 0) * Dq + d];
                s1 += qv * Ks[(j + 1) * Dq + d];
                s2 += qv * Ks[(j + 2) * Dq + d];
                s3 += qv * Ks[(j + 3) * Dq + d];
            }
            float mx = fmaxf(fmaxf(s0, s1), fmaxf(s2, s3));
            float nm = fmaxf(m, mx);
            float corr = __expf(m - nm);
            float p0 = __expf(s0 - nm), p1 = __expf(s1 - nm);
            float p2 = __expf(s2 - nm), p3 = __expf(s3 - nm);
            l = l * corr + p0 + p1 + p2 + p3;
#pragma unroll
            for (int d = 0; d < Dq; d++)
                acc[d] = acc[d] * corr + p0 * Vs[(j + 0) * Dq + d] + p1 * Vs[(j + 1) * Dq + d]
                                       + p2 * Vs[(j + 2) * Dq + d] + p3 * Vs[(j + 3) * Dq + d];
            m = nm;
        }
        for (; j < jmax; j++) {
            float s = 0.f;
#pragma unroll
            for (int d = 0; d < Dq; d++) s += qr[d] * Ks[j * Dq + d];
            float nm = fmaxf(m, s);
            float corr = __expf(m - nm);
            float p = __expf(s - nm);
            l = l * corr + p;
#pragma unroll
            for (int d = 0; d < Dq; d++) acc[d] = acc[d] * corr + p * Vs[j * Dq + d];
            m = nm;
        }
        __syncthreads();
    }
    float inv = 1.f / l;
    size_t ob = ((size_t)(b * Tq + qi)) * Cq + h * Dq;
#pragma unroll
    for (int d = 0; d < Dq; d++) {
        uint16_t hh, ll;
        split_bf16(acc[d] * inv, hh, ll);
        ((uint16_t*)ohi)[ob + d] = hh;
        ((uint16_t*)olo)[ob + d] = ll;
    }
}

// ---------------- normalize sim_matrix columns ----------------
__global__ void k_simnorm(const float* __restrict__ sim, float* __restrict__ sn) {
    __shared__ float ps[8][32];
    __shared__ float inv[32];
    int tid = threadIdx.x;
    int e = tid & 31, part = tid >> 5;
    float s = 0.f;
    for (int c = part * 32; c < part * 32 + 32; c++) {
        float vv = sim[(size_t)c * Eq + e];
        s += vv * vv;
    }
    ps[part][e] = s;
    __syncthreads();
    if (tid < 32) {
        float tot = 0.f;
#pragma unroll
        for (int p = 0; p < 8; p++) tot += ps[p][tid];
        inv[tid] = 1.f / fmaxf(sqrtf(tot), 1e-12f);
    }
    __syncthreads();
    for (int i = tid; i < Cq * Eq; i += 256) sn[i] = sim[i] * inv[i & 31];
}

// ---------------- fused gate: logits + decision + softmax + dispatch ----------------
__global__ void k_gate_fused(const float* __restrict__ xt, const float* __restrict__ sn,
                             const float* __restrict__ gates,
                             float* __restrict__ pre_o, float* __restrict__ am_o,
                             float* __restrict__ rw) {
    __shared__ float xs[8 * Cq];
    int tid = threadIdx.x;
    int t0 = blockIdx.x * 8;
    for (int i = tid; i < 8 * Cq; i += 256) xs[i] = xt[(size_t)t0 * Cq + i];
    __syncthreads();
    int w = tid >> 5, lane = tid & 31;
    int t = t0 + w;
    float s = 0.f;
    for (int c = lane; c < Cq; c += 32) {
        float vv = xs[w * Cq + c];
        s += vv * vv;
    }
#pragma unroll
    for (int o = 16; o; o >>= 1) s += __shfl_xor_sync(0xffffffffu, s, o);
    float inv = 1.f / fmaxf(sqrtf(s), 1e-12f);
    float acc = 0.f;
    for (int c = 0; c < Cq; c++) acc += xs[w * Cq + c] * sn[c * Eq + lane];
    float lg = acc * inv;

    float pre = lg - 1.f / (1.f + __expf(-gates[lane]));
    float gated = fmaxf(pre, 0.f);
    unsigned act = __ballot_sync(0xffffffffu, pre > 0.f);
    float am;
    if (act == 0u) {
        int rank = 0;
#pragma unroll
        for (int j = 0; j < 32; j++) {
            float lj = __shfl_sync(0xffffffffu, lg, j);
            rank += (lj > lg) || (lj == lg && j < lane);
        }
        am = (rank < 16) ? 1.f : 0.f;
    } else {
        am = (pre > 0.f) ? 1.f : 0.f;
    }
    float g2 = (am > 0.f) ? gated : -INFINITY;
    float mx = g2;
#pragma unroll
    for (int o = 16; o; o >>= 1) mx = fmaxf(mx, __shfl_xor_sync(0xffffffffu, mx, o));
    float p = (am > 0.f) ? __expf(gated - mx) : 0.f;
    float sum = p;
#pragma unroll
    for (int o = 16; o; o >>= 1) sum += __shfl_xor_sync(0xffffffffu, sum, o);
    rw[(size_t)t * Eq + lane] = p / sum;
    pre_o[(size_t)t * Eq + lane] = pre;
    am_o[(size_t)t * Eq + lane] = am;
    if (am > 0.f) {
        int slot = atomicAdd(&g_cnt[lane], 1);
        g_tok[lane * Nq + slot] = t;
    }
}

// ---------------- combine + zero-inactive-feo + bf16 split ----------------
__global__ void k_combine_zero(const float* __restrict__ rw, const float* __restrict__ am,
                               float* __restrict__ feo, const float* __restrict__ hs,
                               __nv_bfloat16* __restrict__ hi, __nv_bfloat16* __restrict__ lo) {
    int t = blockIdx.x, c = threadIdx.x;
    __shared__ float rws[Eq];
    __shared__ float ams[Eq];
    if (c < Eq) {
        rws[c] = rw[(size_t)t * Eq + c];
        ams[c] = am[(size_t)t * Eq + c];
    }
    __syncthreads();
    float s = hs[(size_t)t * Cq + c];
#pragma unroll
    for (int e = 0; e < Eq; e++) {
        float* fp = &feo[((size_t)t * Eq + e) * Cq + c];
        if (ams[e] == 0.f) *fp = 0.f;
        else s += rws[e] * (*fp);
    }
    uint16_t h, l;
    split_bf16(s, h, l);
    ((uint16_t*)hi)[(size_t)t * Cq + c] = h;
    ((uint16_t*)lo)[(size_t)t * Cq + c] = l;
}

// ---------------- host ----------------
extern "C" void kernel_launch(void* const* d_in, const int* in_sizes, int n_in,
                              void* d_out, int out_size) {
    const int*   ids   = (const int*)d_in[0];
    const float* emb   = (const float*)d_in[1];
    const float* wq    = (const float*)d_in[2];
    const float* wk    = (const float*)d_in[3];
    const float* wv    = (const float*)d_in[4];
    const float* wo    = (const float*)d_in[5];
    const float* ln1w  = (const float*)d_in[6];
    const float* ln1b  = (const float*)d_in[7];
    const float* ln2w  = (const float*)d_in[8];
    const float* ln2b  = (const float*)d_in[9];
    const float* sim   = (const float*)d_in[10];
    const float* gates = (const float*)d_in[11];
    const float* w1    = (const float*)d_in[12];
    const float* w2    = (const float*)d_in[13];
    const float* lmh   = (const float*)d_in[14];

    float *hs, *qkv, *xt, *sn, *rw, *feo_s, *pre_s, *am_s;
    int *cnt, *tok;
    __nv_bfloat16 *ahi, *alo, *bhi, *blo, *xhi, *xlo, *w1h, *w1l, *w2h, *w2l;
    __nv_bfloat16 *w3h, *w3l, *wph, *wpl, *hh, *hl;
    cudaGetSymbolAddress((void**)&hs, g_hs);
    cudaGetSymbolAddress((void**)&qkv, g_qkv);
    cudaGetSymbolAddress((void**)&xt, g_xt);
    cudaGetSymbolAddress((void**)&sn, g_sn);
    cudaGetSymbolAddress((void**)&rw, g_rw);
    cudaGetSymbolAddress((void**)&feo_s, g_feo);
    cudaGetSymbolAddress((void**)&pre_s, g_pre);
    cudaGetSymbolAddress((void**)&am_s, g_am);
    cudaGetSymbolAddress((void**)&cnt, g_cnt);
    cudaGetSymbolAddress((void**)&tok, g_tok);
    cudaGetSymbolAddress((void**)&ahi, g_ahi);
    cudaGetSymbolAddress((void**)&alo, g_alo);
    cudaGetSymbolAddress((void**)&bhi, g_bhi);
    cudaGetSymbolAddress((void**)&blo, g_blo);
    cudaGetSymbolAddress((void**)&xhi, g_xhi);
    cudaGetSymbolAddress((void**)&xlo, g_xlo);
    cudaGetSymbolAddress((void**)&w1h, g_w1h);
    cudaGetSymbolAddress((void**)&w1l, g_w1l);
    cudaGetSymbolAddress((void**)&w2h, g_w2h);
    cudaGetSymbolAddress((void**)&w2l, g_w2l);
    cudaGetSymbolAddress((void**)&w3h, g_w3h);
    cudaGetSymbolAddress((void**)&w3l, g_w3l);
    cudaGetSymbolAddress((void**)&wph, g_wph);
    cudaGetSymbolAddress((void**)&wpl, g_wpl);
    cudaGetSymbolAddress((void**)&hh, g_hh);
    cudaGetSymbolAddress((void**)&hl, g_hl);

    float* out = (float*)d_out;
    const size_t NV  = (size_t)Nq * Vq;
    const size_t FEO = (size_t)Nq * Eq * Cq;
    const size_t NE  = (size_t)Nq * Eq;
    float *feo, *pre_o, *am_o;
    if ((size_t)out_size >= NV + FEO + 2 * NE) {
        feo = out + NV;
        pre_o = out + NV + FEO;
        am_o = pre_o + NE;
    } else {
        feo = feo_s; pre_o = pre_s; am_o = am_s;
    }

    cudaFuncSetAttribute(k_gemm_mma, cudaFuncAttributeMaxDynamicSharedMemorySize, MM_SMEM);
    cudaFuncSetAttribute(k_lmhead_mma, cudaFuncAttributeMaxDynamicSharedMemorySize, LM_SMEM);

    cudaMemsetAsync(cnt, 0, Eq * sizeof(int));
    // all constant-weight splits in ONE kernel
    k_split_all<<<(int)(P_LM / 256), 256>>>(w1, w2, wq, wk, wv, wo, lmh,
                                            w1h, w1l, w2h, w2l, w3h, w3l, wph, wpl, bhi, blo);

    // embed + ln1 + split
    k_embed_ln<<<Nq, Cq>>>(ids, emb, ln1w, ln1b, hs, ahi, alo);

    // fused QKV GEMM -> packed qkv [t][768]
    k_gemm_mma<<<dim3(C3 / 128, Nq / 128), 256, MM_SMEM>>>(
        ahi, alo, w3h, w3l, nullptr, nullptr, qkv, nullptr, nullptr, nullptr,
        Cq, Cq, C3, C3, 0, 2);

    // attention -> bf16 split output (reuses ahi/alo)
    k_attn<<<dim3(Tq / 128, Hq, Bq), 128>>>(qkv, ahi, alo);

    // hs = hs + attn_out @ wo
    k_gemm_mma<<<dim3(Cq / 128, Nq / 128), 256, MM_SMEM>>>(
        ahi, alo, wph, wpl, nullptr, nullptr, hs, hs, nullptr, nullptr,
        Cq, Cq, Cq, Cq, 0, 2);

    // ln2 -> fp32 xt (for gating) + bf16 split (for MoE)
    k_layernorm_split<<<Nq, Cq>>>(hs, ln2w, ln2b, xt, xhi, xlo);
    k_simnorm<<<1, 256>>>(sim, sn);
    k_gate_fused<<<Nq / 8, 256>>>(xt, sn, gates, pre_o, am_o, rw);

    // sparse MoE: up-proj gathers active tokens per expert, down-proj scatters
    k_gemm_mma<<<dim3(Fq / 128, Nq / 128, Eq), 256, MM_SMEM>>>(
        xhi, xlo, w1h, w1l, hh, hl, nullptr, nullptr, tok, cnt,
        Cq, Cq, Fq, 0, 0, 0);
    k_gemm_mma<<<dim3(Cq / 128, Nq / 128, Eq), 256, MM_SMEM>>>(
        hh, hl, w2h, w2l, nullptr, nullptr, feo, nullptr, tok, cnt,
        Fq, Fq, Cq, 0, Nq * Fq, 1);

    // combine + zero inactive feo + split for lm_head input
    k_combine_zero<<<Nq, Cq>>>(rw, am_o, feo, hs, ahi, alo);

    // lm_head
    k_lmhead_mma<<<VP / 128, 256, LM_SMEM>>>(ahi, alo, bhi, blo, out);
}

// round 14
// speedup vs baseline: 4.6280x; 1.0636x over previous
#include <cuda_runtime.h>
#include <cuda_bf16.h>
#include <math.h>
#include <stdint.h>

// ---------------- problem constants ----------------
static constexpr int Bq = 2;
static constexpr int Tq = 1024;
static constexpr int Cq = 256;
static constexpr int Fq = 1024;
static constexpr int Eq = 32;
static constexpr int Vq = 50257;
static constexpr int Hq = 8;
static constexpr int Dq = 32;      // Cq / Hq
static constexpr int Nq = Bq * Tq; // 2048 tokens
static constexpr int VP = 50304;   // Vq padded to 128 (393 tiles)
static constexpr int C3 = 3 * Cq;  // 768, packed QKV width
static constexpr int NC = 4;       // attention key chunks
static constexpr int CK = Tq / NC; // 256 keys per chunk

// ---------------- device scratch (no allocations allowed) ----------------
__device__ float g_hs[Nq * Cq];
__device__ float g_qkv[Nq * C3];
__device__ float g_xt[Nq * Cq];
__device__ float g_sn[Cq * Eq];
__device__ float g_rw[Nq * Eq];
__device__ float g_feo[(size_t)Nq * Eq * Cq];
__device__ float g_pre[Nq * Eq];
__device__ float g_am[Nq * Eq];
// attention split-K partials
__device__ float g_pm[(size_t)Bq * Hq * Tq * NC];
__device__ float g_pl[(size_t)Bq * Hq * Tq * NC];
__device__ float g_pa[(size_t)Bq * Hq * Tq * NC * Dq];
// MoE dispatch
__device__ int g_cnt[Eq];
__device__ int g_tok[Eq * Nq];
// bf16 hi/lo splits
__device__ __nv_bfloat16 g_ahi[Nq * Cq];           // x -> attn-out -> combine-out
__device__ __nv_bfloat16 g_alo[Nq * Cq];
__device__ __nv_bfloat16 g_bhi[(size_t)Cq * VP];   // lm_head
__device__ __nv_bfloat16 g_blo[(size_t)Cq * VP];
__device__ __nv_bfloat16 g_xhi[Nq * Cq];           // xt (MoE)
__device__ __nv_bfloat16 g_xlo[Nq * Cq];
__device__ __nv_bfloat16 g_w1h[(size_t)Eq * Cq * Fq];
__device__ __nv_bfloat16 g_w1l[(size_t)Eq * Cq * Fq];
__device__ __nv_bfloat16 g_w2h[(size_t)Eq * Fq * Cq];
__device__ __nv_bfloat16 g_w2l[(size_t)Eq * Fq * Cq];
__device__ __nv_bfloat16 g_w3h[Cq * C3];           // packed wq|wk|wv
__device__ __nv_bfloat16 g_w3l[Cq * C3];
__device__ __nv_bfloat16 g_wph[Cq * Cq];           // wo
__device__ __nv_bfloat16 g_wpl[Cq * Cq];
__device__ __nv_bfloat16 g_hh[(size_t)Eq * Nq * Fq];  // compact gelu(X@W1) hi
__device__ __nv_bfloat16 g_hl[(size_t)Eq * Nq * Fq];

// ================= helpers =================
__device__ __forceinline__ uint32_t smem_u32(const void* p) {
    uint32_t a;
    asm("{ .reg .u64 t; cvta.to.shared.u64 t, %1; cvt.u32.u64 %0, t; }" : "=r"(a) : "l"(p));
    return a;
}
__device__ __forceinline__ void split_bf16(float f, uint16_t& hi, uint16_t& lo) {
    __nv_bfloat16 h = __float2bfloat16(f);
    hi = __bfloat16_as_ushort(h);
    lo = __bfloat16_as_ushort(__float2bfloat16(f - __bfloat162float(h)));
}
__device__ __forceinline__ void cp16(uint32_t dst, const void* gsrc) {
    uint64_t g = __cvta_generic_to_global(gsrc);
    asm volatile("cp.async.ca.shared.global [%0], [%1], 16;" :: "r"(dst), "l"(g));
}
__device__ __forceinline__ void cp_commit() { asm volatile("cp.async.commit_group;"); }
__device__ __forceinline__ void cp_wait1() { asm volatile("cp.async.wait_group 1;" ::: "memory"); }
__device__ __forceinline__ void cp_wait0() { asm volatile("cp.async.wait_group 0;" ::: "memory"); }
__device__ __forceinline__ void ldsm_x4(uint32_t* r, uint32_t a) {
    asm volatile("ldmatrix.sync.aligned.m8n8.x4.shared.b16 {%0,%1,%2,%3}, [%4];"
                 : "=r"(r[0]), "=r"(r[1]), "=r"(r[2]), "=r"(r[3]) : "r"(a) : "memory");
}
__device__ __forceinline__ void ldsm_x4_t(uint32_t* r, uint32_t a) {
    asm volatile("ldmatrix.sync.aligned.m8n8.x4.trans.shared.b16 {%0,%1,%2,%3}, [%4];"
                 : "=r"(r[0]), "=r"(r[1]), "=r"(r[2]), "=r"(r[3]) : "r"(a) : "memory");
}
__device__ __forceinline__ void mma16816(float* c, const uint32_t* a, uint32_t b0, uint32_t b1) {
    asm volatile(
        "mma.sync.aligned.m16n8k16.row.col.f32.bf16.bf16.f32 "
        "{%0,%1,%2,%3}, {%4,%5,%6,%7}, {%8,%9}, {%0,%1,%2,%3};"
        : "+f"(c[0]), "+f"(c[1]), "+f"(c[2]), "+f"(c[3])
        : "r"(a[0]), "r"(a[1]), "r"(a[2]), "r"(a[3]), "r"(b0), "r"(b1));
}
__device__ __forceinline__ float gelu_exact(float x) {
    return 0.5f * x * (1.0f + erff(x * 0.70710678118654752f));
}

// ---------------- mega split: ALL constant weights in one kernel ----------------
static constexpr size_t P_W1 = (size_t)Eq * Cq * Fq / 2;
static constexpr size_t P_W2 = P_W1 + (size_t)Eq * Fq * Cq / 2;
static constexpr size_t P_W3 = P_W2 + (size_t)Cq * C3 / 2;
static constexpr size_t P_WO = P_W3 + (size_t)Cq * Cq / 2;
static constexpr size_t P_LM = P_WO + (size_t)Cq * VP / 2;

__global__ void k_split_all(const float* __restrict__ w1, const float* __restrict__ w2,
                            const float* __restrict__ wq, const float* __restrict__ wk,
                            const float* __restrict__ wv, const float* __restrict__ wo,
                            const float* __restrict__ lmh,
                            __nv_bfloat16* __restrict__ w1h, __nv_bfloat16* __restrict__ w1l,
                            __nv_bfloat16* __restrict__ w2h, __nv_bfloat16* __restrict__ w2l,
                            __nv_bfloat16* __restrict__ w3h, __nv_bfloat16* __restrict__ w3l,
                            __nv_bfloat16* __restrict__ wph, __nv_bfloat16* __restrict__ wpl,
                            __nv_bfloat16* __restrict__ bhi, __nv_bfloat16* __restrict__ blo) {
    size_t i = (size_t)blockIdx.x * 256 + threadIdx.x;
    float v0, v1;
    __nv_bfloat16 *dh, *dl;
    size_t o;
    if (i < P_W1) {
        o = i;
        float2 v = *(const float2*)&w1[o * 2];
        v0 = v.x; v1 = v.y; dh = w1h; dl = w1l;
    } else if (i < P_W2) {
        o = i - P_W1;
        float2 v = *(const float2*)&w2[o * 2];
        v0 = v.x; v1 = v.y; dh = w2h; dl = w2l;
    } else if (i < P_W3) {
        o = i - P_W2;
        int k = (int)(o / (C3 / 2));
        int n = (int)(o - (size_t)k * (C3 / 2)) * 2;
        const float* src = (n < Cq) ? wq : ((n < 2 * Cq) ? wk : wv);
        int nn = n & (Cq - 1);
        v0 = src[k * Cq + nn]; v1 = src[k * Cq + nn + 1];
        dh = w3h; dl = w3l;
    } else if (i < P_WO) {
        o = i - P_W3;
        float2 v = *(const float2*)&wo[o * 2];
        v0 = v.x; v1 = v.y; dh = wph; dl = wpl;
    } else {
        o = i - P_WO;
        int k = (int)(o / (VP / 2));
        int n = (int)(o - (size_t)k * (VP / 2)) * 2;
        v0 = (n < Vq) ? lmh[(size_t)k * Vq + n] : 0.f;
        v1 = (n + 1 < Vq) ? lmh[(size_t)k * Vq + n + 1] : 0.f;
        dh = bhi; dl = blo;
    }
    uint16_t h0, l0, h1, l1;
    split_bf16(v0, h0, l0);
    split_bf16(v1, h1, l1);
    ((uint32_t*)dh)[o] = (uint32_t)h0 | ((uint32_t)h1 << 16);
    ((uint32_t*)dl)[o] = (uint32_t)l0 | ((uint32_t)l1 << 16);
}

// ================= generic HMMA GEMM (bf16 3-split) =================
static constexpr int MM_SMEM = 131072;

__global__ void __launch_bounds__(256, 1) k_gemm_mma(
    const __nv_bfloat16* __restrict__ Ah, const __nv_bfloat16* __restrict__ Al,
    const __nv_bfloat16* __restrict__ Bh, const __nv_bfloat16* __restrict__ Bl,
    __nv_bfloat16* __restrict__ Oh, __nv_bfloat16* __restrict__ Ol,
    float* __restrict__ fout, const float* __restrict__ res,
    const int* __restrict__ toks, const int* __restrict__ cnts,
    int K, int lda, int ldb, int ldo, int aExpStride, int epi) {
    extern __shared__ char smem[];
    uint32_t sb = smem_u32(smem);
    int tid = threadIdx.x, wid = tid >> 5, lane = tid & 31;
    int wm = wid >> 2, wn = wid & 3;
    int g = lane >> 3, gr = lane & 7;
    int n0 = blockIdx.x * 128, m0 = blockIdx.y * 128, e = blockIdx.z;

    int ce = cnts ? cnts[e] : 0x7fffffff;
    if (cnts) {
        int lim = (epi == 0) ? ((ce + 127) & ~127) : ce;
        if (m0 >= lim) return;
    }
    const int* tokE = toks ? toks + (size_t)e * Nq : nullptr;

    const __nv_bfloat16* Abh = Ah + (size_t)e * aExpStride;
    const __nv_bfloat16* Abl = Al + (size_t)e * aExpStride;
    const __nv_bfloat16* Bbh = Bh + (size_t)e * K * ldb + n0;
    const __nv_bfloat16* Bbl = Bl + (size_t)e * K * ldb + n0;

    auto copyChunk = [&](int ch) {
        uint32_t base = sb + (ch & 1) * 65536;
        int kc = ch * 64;
#pragma unroll
        for (int it = 0; it < 8; it++) {
            int lin = tid + it * 256;
            int half = lin >> 10;
            int r = lin & 1023;
            int m = r >> 3, k8 = r & 7;
            int row = m0 + m;
            if (epi == 0 && tokE) {
                int slot = row;
                if (slot >= ce) slot = ce - 1;
                row = tokE[slot];
            }
            uint32_t dst = base + half * 16384 + m * 128 + (((k8 ^ (m & 7))) << 4);
            cp16(dst, (half ? Abl : Abh) + (size_t)row * lda + kc + k8 * 8);
        }
#pragma unroll
        for (int it = 0; it < 8; it++) {
            int lin = tid + it * 256;
            int half = lin >> 10;
            int r = lin & 1023;
            int k = r >> 4, n8 = r & 15;
            uint32_t dst = base + 32768 + half * 16384 + k * 256 + (((n8 ^ (k & 7))) << 4);
            cp16(dst, (half ? Bbl : Bbh) + (size_t)(kc + k) * ldb + n8 * 8);
        }
    };

    float acc[4][4][4];
#pragma unroll
    for (int a = 0; a < 4; a++)
#pragma unroll
        for (int b = 0; b < 4; b++)
#pragma unroll
            for (int c = 0; c < 4; c++) acc[a][b][c] = 0.f;

    const int k_extra = (g & 1) * 8;
    const int n_extra = (g >> 1) * 8;
    const int nch = K / 64;

    copyChunk(0);
    cp_commit();
    for (int t = 0; t < nch; t++) {
        if (t + 1 < nch) { copyChunk(t + 1); cp_commit(); cp_wait1(); }
        else cp_wait0();
        __syncthreads();
        uint32_t ab = sb + (t & 1) * 65536;
        uint32_t bb = ab + 32768;
#pragma unroll
        for (int ks = 0; ks < 4; ks++) {
            uint32_t Bhf[2][4], Blf[2][4];
#pragma unroll
            for (int b = 0; b < 2; b++) {
                int kx = ks * 16 + k_extra + gr;
                int nf = wn * 32 + b * 16 + n_extra;
                uint32_t off = kx * 256 + ((((nf >> 3) ^ (kx & 7))) << 4);
                ldsm_x4_t(Bhf[b], bb + off);
                ldsm_x4_t(Blf[b], bb + 16384 + off);
            }
#pragma unroll
            for (int ma = 0; ma < 4; ma++) {
                int rowa = wm * 64 + ma * 16 + (g & 1) * 8 + gr;
                int kk = ks * 16 + n_extra;
                uint32_t ao = rowa * 128 + ((((kk >> 3) ^ (rowa & 7))) << 4);
                uint32_t Ahf[4], Alf[4];
                ldsm_x4(Ahf, ab + ao);
                ldsm_x4(Alf, ab + 16384 + ao);
#pragma unroll
                for (int b = 0; b < 2; b++) {
                    mma16816(acc[ma][2 * b],     Ahf, Bhf[b][0], Bhf[b][1]);
                    mma16816(acc[ma][2 * b],     Ahf, Blf[b][0], Blf[b][1]);
                    mma16816(acc[ma][2 * b],     Alf, Bhf[b][0], Bhf[b][1]);
                    mma16816(acc[ma][2 * b + 1], Ahf, Bhf[b][2], Bhf[b][3]);
                    mma16816(acc[ma][2 * b + 1], Ahf, Blf[b][2], Blf[b][3]);
                    mma16816(acc[ma][2 * b + 1], Alf, Bhf[b][2], Bhf[b][3]);
                }
            }
        }
        __syncthreads();
    }

    // ---- SMEM-staged epilogue ----
    float* stage = (float*)smem;
#pragma unroll
    for (int ma = 0; ma < 4; ma++) {
        int lr = wm * 64 + ma * 16 + (lane >> 2);
#pragma unroll
        for (int na = 0; na < 4; na++) {
            int lc = wn * 32 + na * 8 + (lane & 3) * 2;
            float v0 = acc[ma][na][0], v1 = acc[ma][na][1];
            float v2 = acc[ma][na][2], v3 = acc[ma][na][3];
            if (epi == 0) { v0 = gelu_exact(v0); v1 = gelu_exact(v1);
                            v2 = gelu_exact(v2); v3 = gelu_exact(v3); }
            stage[lr * 132 + lc] = v0;
            stage[lr * 132 + lc + 1] = v1;
            stage[(lr + 8) * 132 + lc] = v2;
            stage[(lr + 8) * 132 + lc + 1] = v3;
        }
    }
    __syncthreads();

    if (epi == 0) {
#pragma unroll
        for (int it = 0; it < 8; it++) {
            int idx = tid + it * 256;
            int r = idx >> 4, c8 = (idx & 15) * 8;
            float4 a = *(float4*)&stage[r * 132 + c8];
            float4 b = *(float4*)&stage[r * 132 + c8 + 4];
            uint16_t h[8], l[8];
            split_bf16(a.x, h[0], l[0]); split_bf16(a.y, h[1], l[1]);
            split_bf16(a.z, h[2], l[2]); split_bf16(a.w, h[3], l[3]);
            split_bf16(b.x, h[4], l[4]); split_bf16(b.y, h[5], l[5]);
            split_bf16(b.z, h[6], l[6]); split_bf16(b.w, h[7], l[7]);
            size_t o = ((size_t)e * Nq + m0 + r) * Fq + n0 + c8;
            *(uint4*)(Oh + o) = make_uint4(
                (uint32_t)h[0] | ((uint32_t)h[1] << 16), (uint32_t)h[2] | ((uint32_t)h[3] << 16),
                (uint32_t)h[4] | ((uint32_t)h[5] << 16), (uint32_t)h[6] | ((uint32_t)h[7] << 16));
            *(uint4*)(Ol + o) = make_uint4(
                (uint32_t)l[0] | ((uint32_t)l[1] << 16), (uint32_t)l[2] | ((uint32_t)l[3] << 16),
                (uint32_t)l[4] | ((uint32_t)l[5] << 16), (uint32_t)l[6] | ((uint32_t)l[7] << 16));
        }
    } else if (epi == 1) {
#pragma unroll
        for (int it = 0; it < 16; it++) {
            int idx = tid + it * 256;
            int r = idx >> 5, c4 = (idx & 31) * 4;
            int slot = m0 + r;
            if (slot >= ce) continue;
            int t = tokE ? tokE[slot] : slot;
            float4 v = *(float4*)&stage[r * 132 + c4];
            *(float4*)&fout[((size_t)t * Eq + e) * Cq + n0 + c4] = v;
        }
    } else {
#pragma unroll
        for (int it = 0; it < 16; it++) {
            int idx = tid + it * 256;
            int r = idx >> 5, c4 = (idx & 31) * 4;
            float4 v = *(float4*)&stage[r * 132 + c4];
            size_t o = (size_t)(m0 + r) * ldo + n0 + c4;
            if (res) {
                float4 rr = *(const float4*)&res[o];
                v.x += rr.x; v.y += rr.y; v.z += rr.z; v.w += rr.w;
            }
            *(float4*)&fout[o] = v;
        }
    }
}

// ================= lm_head HMMA GEMM =================
static constexpr int SM_B_HI = 0;
static constexpr int SM_B_LO = 65536;
static constexpr int SM_A    = 131072;
static constexpr int LM_SMEM = 196608;

__global__ void __launch_bounds__(256, 1) k_lmhead_mma(const __nv_bfloat16* __restrict__ Ah,
                                                       const __nv_bfloat16* __restrict__ Al,
                                                       const __nv_bfloat16* __restrict__ Bh,
                                                       const __nv_bfloat16* __restrict__ Bl,
                                                       float* __restrict__ out) {
    extern __shared__ char smem[];
    uint32_t sb = smem_u32(smem);
    int tid = threadIdx.x;
    int wid = tid >> 5, lane = tid & 31;
    int wm = wid >> 2, wn = wid & 3;
    int g = lane >> 3, gr = lane & 7;
    int n0 = blockIdx.x * 128;

#pragma unroll
    for (int it = 0; it < 32; it++) {
        int lin = tid + it * 256;
        int half = lin >> 12;
        int r = lin & 4095;
        int k = r >> 4, n8 = r & 15;
        uint32_t dst = sb + (half ? SM_B_LO : SM_B_HI) + k * 256 + (((n8 ^ (k & 7))) << 4);
        const __nv_bfloat16* srcb = (half ? Bl : Bh) + (size_t)k * VP + n0 + n8 * 8;
        cp16(dst, srcb);
    }
    auto copyA = [&](int t) {
        int mb = t >> 2;
        int kc = (t & 3) * 64;
        uint32_t abase = sb + SM_A + (t & 1) * 32768;
#pragma unroll
        for (int it = 0; it < 8; it++) {
            int lin = tid + it * 256;
            int half = lin >> 10;
            int r = lin & 1023;
            int m = r >> 3, k8 = r & 7;
            uint32_t dst = abase + half * 16384 + m * 128 + (((k8 ^ (m & 7))) << 4);
            const __nv_bfloat16* srca = (half ? Al : Ah) + (size_t)(mb * 128 + m) * Cq + kc + k8 * 8;
            cp16(dst, srca);
        }
    };
    copyA(0);
    cp_commit();

    float acc[4][4][4];
#pragma unroll
    for (int a = 0; a < 4; a++)
#pragma unroll
        for (int b = 0; b < 4; b++)
#pragma unroll
            for (int c = 0; c < 4; c++) acc[a][b][c] = 0.f;

    const int k_extra = (g & 1) * 8;
    const int n_extra = (g >> 1) * 8;

    for (int t = 0; t < 64; t++) {
        if (t + 1 < 64) { copyA(t + 1); cp_commit(); cp_wait1(); }
        else cp_wait0();
        __syncthreads();

        int kc = (t & 3) * 64;
        uint32_t ah_base = sb + SM_A + (t & 1) * 32768;
        uint32_t al_base = ah_base + 16384;
#pragma unroll
        for (int ks = 0; ks < 4; ks++) {
            uint32_t Bhf[2][4], Blf[2][4];
#pragma unroll
            for (int b = 0; b < 2; b++) {
                int kx = kc + ks * 16 + k_extra + gr;
                int nf = wn * 32 + b * 16 + n_extra;
                uint32_t off = kx * 256 + ((((nf >> 3) ^ (kx & 7))) << 4);
                ldsm_x4_t(Bhf[b], sb + SM_B_HI + off);
                ldsm_x4_t(Blf[b], sb + SM_B_LO + off);
            }
#pragma unroll
            for (int ma = 0; ma < 4; ma++) {
                int rowa = wm * 64 + ma * 16 + (g & 1) * 8 + gr;
                int kkl = ks * 16 + n_extra;
                uint32_t ao = rowa * 128 + ((((kkl >> 3) ^ (rowa & 7))) << 4);
                uint32_t Ahf[4], Alf[4];
                ldsm_x4(Ahf, ah_base + ao);
                ldsm_x4(Alf, al_base + ao);
#pragma unroll
                for (int b = 0; b < 2; b++) {
                    mma16816(acc[ma][2 * b],     Ahf, Bhf[b][0], Bhf[b][1]);
                    mma16816(acc[ma][2 * b],     Ahf, Blf[b][0], Blf[b][1]);
                    mma16816(acc[ma][2 * b],     Alf, Bhf[b][0], Bhf[b][1]);
                    mma16816(acc[ma][2 * b + 1], Ahf, Bhf[b][2], Bhf[b][3]);
                    mma16816(acc[ma][2 * b + 1], Ahf, Blf[b][2], Blf[b][3]);
                    mma16816(acc[ma][2 * b + 1], Alf, Bhf[b][2], Bhf[b][3]);
                }
            }
        }
        if ((t & 3) == 3) {
            int mbase = (t >> 2) * 128 + wm * 64;
#pragma unroll
            for (int ma = 0; ma < 4; ma++) {
#pragma unroll
                for (int na = 0; na < 4; na++) {
                    int gm = mbase + ma * 16 + (lane >> 2);
                    int gn = n0 + wn * 32 + na * 8 + (lane & 3) * 2;
                    float* p0 = out + (size_t)gm * Vq + gn;
                    float* p1 = out + (size_t)(gm + 8) * Vq + gn;
                    if (gn < Vq)     { p0[0] = acc[ma][na][0]; p1[0] = acc[ma][na][2]; }
                    if (gn + 1 < Vq) { p0[1] = acc[ma][na][1]; p1[1] = acc[ma][na][3]; }
                    acc[ma][na][0] = acc[ma][na][1] = acc[ma][na][2] = acc[ma][na][3] = 0.f;
                }
            }
        }
        __syncthreads();
    }
}

// ---------------- fused embed + LN1 + bf16 split ----------------
__global__ void k_embed_ln(const int* __restrict__ ids, const float* __restrict__ emb,
                           const float* __restrict__ w, const float* __restrict__ b,
                           float* __restrict__ hs,
                           __nv_bfloat16* __restrict__ hi, __nv_bfloat16* __restrict__ lo) {
    int t = blockIdx.x, c = threadIdx.x;
    float x = emb[(size_t)ids[t] * Cq + c];
    hs[(size_t)t * Cq + c] = x;
    __shared__ float red[8];
    float s = x;
#pragma unroll
    for (int o = 16; o; o >>= 1) s += __shfl_xor_sync(0xffffffffu, s, o);
    if ((c & 31) == 0) red[c >> 5] = s;
    __syncthreads();
    float mu = 0.f;
#pragma unroll
    for (int i = 0; i < 8; i++) mu += red[i];
    mu *= (1.f / Cq);
    float d = x - mu;
    float s2 = d * d;
#pragma unroll
    for (int o = 16; o; o >>= 1) s2 += __shfl_xor_sync(0xffffffffu, s2, o);
    __syncthreads();
    if ((c & 31) == 0) red[c >> 5] = s2;
    __syncthreads();
    float var = 0.f;
#pragma unroll
    for (int i = 0; i < 8; i++) var += red[i];
    var *= (1.f / Cq);
    float y = d * rsqrtf(var + 1e-5f) * w[c] + b[c];
    uint16_t h, l;
    split_bf16(y, h, l);
    ((uint16_t*)hi)[(size_t)t * Cq + c] = h;
    ((uint16_t*)lo)[(size_t)t * Cq + c] = l;
}

// ---------------- layernorm fused with bf16 split ----------------
__global__ void k_layernorm_split(const float* __restrict__ in, const float* __restrict__ w,
                                  const float* __restrict__ b, float* __restrict__ fp32out,
                                  __nv_bfloat16* __restrict__ hi, __nv_bfloat16* __restrict__ lo) {
    int t = blockIdx.x, c = threadIdx.x;
    float x = in[(size_t)t * Cq + c];
    __shared__ float red[8];
    float s = x;
#pragma unroll
    for (int o = 16; o; o >>= 1) s += __shfl_xor_sync(0xffffffffu, s, o);
    if ((c & 31) == 0) red[c >> 5] = s;
    __syncthreads();
    float mu = 0.f;
#pragma unroll
    for (int i = 0; i < 8; i++) mu += red[i];
    mu *= (1.f / Cq);
    float d = x - mu;
    float s2 = d * d;
#pragma unroll
    for (int o = 16; o; o >>= 1) s2 += __shfl_xor_sync(0xffffffffu, s2, o);
    __syncthreads();
    if ((c & 31) == 0) red[c >> 5] = s2;
    __syncthreads();
    float var = 0.f;
#pragma unroll
    for (int i = 0; i < 8; i++) var += red[i];
    var *= (1.f / Cq);
    float y = d * rsqrtf(var + 1e-5f) * w[c] + b[c];
    if (fp32out) fp32out[(size_t)t * Cq + c] = y;
    uint16_t h, l;
    split_bf16(y, h, l);
    ((uint16_t*)hi)[(size_t)t * Cq + c] = h;
    ((uint16_t*)lo)[(size_t)t * Cq + c] = l;
}

// ---------------- attention split-K: partial pass ----------------
// grid (Tq/128, Hq, Bq*NC), 128 threads; thread = query, chunk c = keys [c*CK, c*CK+CK)
__global__ void __launch_bounds__(128) k_attn_part(const float* __restrict__ qkv) {
    int zc = blockIdx.z;
    int b = zc / NC, c = zc - b * NC;
    int h = blockIdx.y;
    int t0 = blockIdx.x * 128;
    int qi = t0 + threadIdx.x;
    int k0 = c * CK;
    const float scale = 0.17677669529663687f;

    float m = -INFINITY, l = 0.f;
    float acc[Dq];
#pragma unroll
    for (int d = 0; d < Dq; d++) acc[d] = 0.f;

    if (t0 + 127 >= k0) {   // block-uniform: some query in block sees this chunk
        float qr[Dq];
        const float* qp = qkv + ((size_t)(b * Tq + qi)) * C3 + h * Dq;
#pragma unroll
        for (int d = 0; d < Dq; d++) qr[d] = qp[d] * scale;
        __shared__ float Ks[64 * Dq], Vs[64 * Dq];
        int kend = k0 + CK;
        int kcap = t0 + 128;
        if (kend > kcap) kend = kcap;
        for (int kt = k0; kt < kend; kt += 64) {
#pragma unroll
            for (int i = threadIdx.x; i < 512; i += 128) {
                int r = i >> 3, d4 = (i & 7) * 4;
                size_t gi = ((size_t)(b * Tq + kt + r)) * C3 + h * Dq + d4;
                *(float4*)&Ks[r * Dq + d4] = *(const float4*)&qkv[gi + Cq];
                *(float4*)&Vs[r * Dq + d4] = *(const float4*)&qkv[gi + 2 * Cq];
            }
            __syncthreads();
            int jmax = qi - kt + 1;
            if (jmax > 64) jmax = 64;
            int j = 0;
            for (; j + 3 < jmax; j += 4) {
                float s0 = 0.f, s1 = 0.f, s2 = 0.f, s3 = 0.f;
#pragma unroll
                for (int d = 0; d < Dq; d++) {
                    float qv = qr[d];
                    s0 += qv * Ks[(j + 0) * Dq + d];
                    s1 += qv * Ks[(j + 1) * Dq + d];
                    s2 += qv * Ks[(j + 2) * Dq + d];
                    s3 += qv * Ks[(j + 3) * Dq + d];
                }
                float mx = fmaxf(fmaxf(s0, s1), fmaxf(s2, s3));
                float nm = fmaxf(m, mx);
                float corr = __expf(m - nm);
                float p0 = __expf(s0 - nm), p1 = __expf(s1 - nm);
                float p2 = __expf(s2 - nm), p3 = __expf(s3 - nm);
                l = l * corr + p0 + p1 + p2 + p3;
#pragma unroll
                for (int d = 0; d < Dq; d++)
                    acc[d] = acc[d] * corr + p0 * Vs[(j + 0) * Dq + d] + p1 * Vs[(j + 1) * Dq + d]
                                           + p2 * Vs[(j + 2) * Dq + d] + p3 * Vs[(j + 3) * Dq + d];
                m = nm;
            }
            for (; j < jmax; j++) {
                float s = 0.f;
#pragma unroll
                for (int d = 0; d < Dq; d++) s += qr[d] * Ks[j * Dq + d];
                float nm = fmaxf(m, s);
                float corr = __expf(m - nm);
                float p = __expf(s - nm);
                l = l * corr + p;
#pragma unroll
                for (int d = 0; d < Dq; d++) acc[d] = acc[d] * corr + p * Vs[j * Dq + d];
                m = nm;
            }
            __syncthreads();
        }
    }
    size_t pidx = (((size_t)(b * Hq + h) * Tq + qi) * NC + c);
    g_pm[pidx] = m;
    g_pl[pidx] = l;
    float* pa = &g_pa[pidx * Dq];
#pragma unroll
    for (int d = 0; d < Dq; d += 4)
        *(float4*)&pa[d] = make_float4(acc[d], acc[d + 1], acc[d + 2], acc[d + 3]);
}

// ---------------- attention split-K: merge pass ----------------
// one warp per (b,h,q); lane = d
__global__ void k_attn_merge(__nv_bfloat16* __restrict__ ohi, __nv_bfloat16* __restrict__ olo) {
    int gw = blockIdx.x * 8 + (threadIdx.x >> 5);  // 0 .. Bq*Hq*Tq-1
    int lane = threadIdx.x & 31;
    int q = gw & (Tq - 1);
    int bh = gw >> 10;          // Tq = 1024
    int h = bh & (Hq - 1);
    int b = bh >> 3;            // Hq = 8
    size_t base = (size_t)gw * NC;
    float m0 = g_pm[base], m1 = g_pm[base + 1], m2 = g_pm[base + 2], m3 = g_pm[base + 3];
    float ms = fmaxf(fmaxf(m0, m1), fmaxf(m2, m3));   // m0 finite always
    float w0 = __expf(m0 - ms), w1 = __expf(m1 - ms);
    float w2 = __expf(m2 - ms), w3 = __expf(m3 - ms);
    float ls = g_pl[base] * w0 + g_pl[base + 1] * w1 + g_pl[base + 2] * w2 + g_pl[base + 3] * w3;
    float a = g_pa[(base + 0) * Dq + lane] * w0 + g_pa[(base + 1) * Dq + lane] * w1
            + g_pa[(base + 2) * Dq + lane] * w2 + g_pa[(base + 3) * Dq + lane] * w3;
    float o = a / ls;
    uint16_t hh, ll;
    split_bf16(o, hh, ll);
    size_t ob = ((size_t)(b * Tq + q)) * Cq + h * Dq + lane;
    ((uint16_t*)ohi)[ob] = hh;
    ((uint16_t*)olo)[ob] = ll;
}

// ---------------- normalize sim_matrix columns ----------------
__global__ void k_simnorm(const float* __restrict__ sim, float* __restrict__ sn) {
    __shared__ float ps[8][32];
    __shared__ float inv[32];
    int tid = threadIdx.x;
    int e = tid & 31, part = tid >> 5;
    float s = 0.f;
    for (int c = part * 32; c < part * 32 + 32; c++) {
        float vv = sim[(size_t)c * Eq + e];
        s += vv * vv;
    }
    ps[part][e] = s;
    __syncthreads();
    if (tid < 32) {
        float tot = 0.f;
#pragma unroll
        for (int p = 0; p < 8; p++) tot += ps[p][tid];
        inv[tid] = 1.f / fmaxf(sqrtf(tot), 1e-12f);
    }
    __syncthreads();
    for (int i = tid; i < Cq * Eq; i += 256) sn[i] = sim[i] * inv[i & 31];
}

// ---------------- fused gate: logits + decision + softmax + dispatch ----------------
__global__ void k_gate_fused(const float* __restrict__ xt, const float* __restrict__ sn,
                             const float* __restrict__ gates,
                             float* __restrict__ pre_o, float* __restrict__ am_o,
                             float* __restrict__ rw) {
    __shared__ float xs[8 * Cq];
    int tid = threadIdx.x;
    int t0 = blockIdx.x * 8;
    for (int i = tid; i < 8 * Cq; i += 256) xs[i] = xt[(size_t)t0 * Cq + i];
    __syncthreads();
    int w = tid >> 5, lane = tid & 31;
    int t = t0 + w;
    float s = 0.f;
    for (int c = lane; c < Cq; c += 32) {
        float vv = xs[w * Cq + c];
        s += vv * vv;
    }
#pragma unroll
    for (int o = 16; o; o >>= 1) s += __shfl_xor_sync(0xffffffffu, s, o);
    float inv = 1.f / fmaxf(sqrtf(s), 1e-12f);
    float acc = 0.f;
    for (int c = 0; c < Cq; c++) acc += xs[w * Cq + c] * sn[c * Eq + lane];
    float lg = acc * inv;

    float pre = lg - 1.f / (1.f + __expf(-gates[lane]));
    float gated = fmaxf(pre, 0.f);
    unsigned act = __ballot_sync(0xffffffffu, pre > 0.f);
    float am;
    if (act == 0u) {
        int rank = 0;
#pragma unroll
        for (int j = 0; j < 32; j++) {
            float lj = __shfl_sync(0xffffffffu, lg, j);
            rank += (lj > lg) || (lj == lg && j < lane);
        }
        am = (rank < 16) ? 1.f : 0.f;
    } else {
        am = (pre > 0.f) ? 1.f : 0.f;
    }
    float g2 = (am > 0.f) ? gated : -INFINITY;
    float mx = g2;
#pragma unroll
    for (int o = 16; o; o >>= 1) mx = fmaxf(mx, __shfl_xor_sync(0xffffffffu, mx, o));
    float p = (am > 0.f) ? __expf(gated - mx) : 0.f;
    float sum = p;
#pragma unroll
    for (int o = 16; o; o >>= 1) sum += __shfl_xor_sync(0xffffffffu, sum, o);
    rw[(size_t)t * Eq + lane] = p / sum;
    pre_o[(size_t)t * Eq + lane] = pre;
    am_o[(size_t)t * Eq + lane] = am;
    if (am > 0.f) {
        int slot = atomicAdd(&g_cnt[lane], 1);
        g_tok[lane * Nq + slot] = t;
    }
}

// ---------------- combine + zero-inactive-feo + bf16 split ----------------
__global__ void k_combine_zero(const float* __restrict__ rw, const float* __restrict__ am,
                               float* __restrict__ feo, const float* __restrict__ hs,
                               __nv_bfloat16* __restrict__ hi, __nv_bfloat16* __restrict__ lo) {
    int t = blockIdx.x, c = threadIdx.x;
    __shared__ float rws[Eq];
    __shared__ float ams[Eq];
    if (c < Eq) {
        rws[c] = rw[(size_t)t * Eq + c];
        ams[c] = am[(size_t)t * Eq + c];
    }
    __syncthreads();
    float s = hs[(size_t)t * Cq + c];
#pragma unroll
    for (int e = 0; e < Eq; e++) {
        float* fp = &feo[((size_t)t * Eq + e) * Cq + c];
        if (ams[e] == 0.f) *fp = 0.f;
        else s += rws[e] * (*fp);
    }
    uint16_t h, l;
    split_bf16(s, h, l);
    ((uint16_t*)hi)[(size_t)t * Cq + c] = h;
    ((uint16_t*)lo)[(size_t)t * Cq + c] = l;
}

// ---------------- host ----------------
extern "C" void kernel_launch(void* const* d_in, const int* in_sizes, int n_in,
                              void* d_out, int out_size) {
    const int*   ids   = (const int*)d_in[0];
    const float* emb   = (const float*)d_in[1];
    const float* wq    = (const float*)d_in[2];
    const float* wk    = (const float*)d_in[3];
    const float* wv    = (const float*)d_in[4];
    const float* wo    = (const float*)d_in[5];
    const float* ln1w  = (const float*)d_in[6];
    const float* ln1b  = (const float*)d_in[7];
    const float* ln2w  = (const float*)d_in[8];
    const float* ln2b  = (const float*)d_in[9];
    const float* sim   = (const float*)d_in[10];
    const float* gates = (const float*)d_in[11];
    const float* w1    = (const float*)d_in[12];
    const float* w2    = (const float*)d_in[13];
    const float* lmh   = (const float*)d_in[14];

    float *hs, *qkv, *xt, *sn, *rw, *feo_s, *pre_s, *am_s;
    int *cnt, *tok;
    __nv_bfloat16 *ahi, *alo, *bhi, *blo, *xhi, *xlo, *w1h, *w1l, *w2h, *w2l;
    __nv_bfloat16 *w3h, *w3l, *wph, *wpl, *hh, *hl;
    cudaGetSymbolAddress((void**)&hs, g_hs);
    cudaGetSymbolAddress((void**)&qkv, g_qkv);
    cudaGetSymbolAddress((void**)&xt, g_xt);
    cudaGetSymbolAddress((void**)&sn, g_sn);
    cudaGetSymbolAddress((void**)&rw, g_rw);
    cudaGetSymbolAddress((void**)&feo_s, g_feo);
    cudaGetSymbolAddress((void**)&pre_s, g_pre);
    cudaGetSymbolAddress((void**)&am_s, g_am);
    cudaGetSymbolAddress((void**)&cnt, g_cnt);
    cudaGetSymbolAddress((void**)&tok, g_tok);
    cudaGetSymbolAddress((void**)&ahi, g_ahi);
    cudaGetSymbolAddress((void**)&alo, g_alo);
    cudaGetSymbolAddress((void**)&bhi, g_bhi);
    cudaGetSymbolAddress((void**)&blo, g_blo);
    cudaGetSymbolAddress((void**)&xhi, g_xhi);
    cudaGetSymbolAddress((void**)&xlo, g_xlo);
    cudaGetSymbolAddress((void**)&w1h, g_w1h);
    cudaGetSymbolAddress((void**)&w1l, g_w1l);
    cudaGetSymbolAddress((void**)&w2h, g_w2h);
    cudaGetSymbolAddress((void**)&w2l, g_w2l);
    cudaGetSymbolAddress((void**)&w3h, g_w3h);
    cudaGetSymbolAddress((void**)&w3l, g_w3l);
    cudaGetSymbolAddress((void**)&wph, g_wph);
    cudaGetSymbolAddress((void**)&wpl, g_wpl);
    cudaGetSymbolAddress((void**)&hh, g_hh);
    cudaGetSymbolAddress((void**)&hl, g_hl);

    float* out = (float*)d_out;
    const size_t NV  = (size_t)Nq * Vq;
    const size_t FEO = (size_t)Nq * Eq * Cq;
    const size_t NE  = (size_t)Nq * Eq;
    float *feo, *pre_o, *am_o;
    if ((size_t)out_size >= NV + FEO + 2 * NE) {
        feo = out + NV;
        pre_o = out + NV + FEO;
        am_o = pre_o + NE;
    } else {
        feo = feo_s; pre_o = pre_s; am_o = am_s;
    }

    cudaFuncSetAttribute(k_gemm_mma, cudaFuncAttributeMaxDynamicSharedMemorySize, MM_SMEM);
    cudaFuncSetAttribute(k_lmhead_mma, cudaFuncAttributeMaxDynamicSharedMemorySize, LM_SMEM);

    cudaMemsetAsync(cnt, 0, Eq * sizeof(int));
    // all constant-weight splits in ONE kernel
    k_split_all<<<(int)(P_LM / 256), 256>>>(w1, w2, wq, wk, wv, wo, lmh,
                                            w1h, w1l, w2h, w2l, w3h, w3l, wph, wpl, bhi, blo);

    // embed + ln1 + split
    k_embed_ln<<<Nq, Cq>>>(ids, emb, ln1w, ln1b, hs, ahi, alo);

    // fused QKV GEMM -> packed qkv [t][768]
    k_gemm_mma<<<dim3(C3 / 128, Nq / 128), 256, MM_SMEM>>>(
        ahi, alo, w3h, w3l, nullptr, nullptr, qkv, nullptr, nullptr, nullptr,
        Cq, Cq, C3, C3, 0, 2);

    // split-K attention -> bf16 split output (reuses ahi/alo)
    k_attn_part<<<dim3(Tq / 128, Hq, Bq * NC), 128>>>(qkv);
    k_attn_merge<<<Bq * Hq * Tq / 8, 256>>>(ahi, alo);

    // hs = hs + attn_out @ wo
    k_gemm_mma<<<dim3(Cq / 128, Nq / 128), 256, MM_SMEM>>>(
        ahi, alo, wph, wpl, nullptr, nullptr, hs, hs, nullptr, nullptr,
        Cq, Cq, Cq, Cq, 0, 2);

    // ln2 -> fp32 xt (for gating) + bf16 split (for MoE)
    k_layernorm_split<<<Nq, Cq>>>(hs, ln2w, ln2b, xt, xhi, xlo);
    k_simnorm<<<1, 256>>>(sim, sn);
    k_gate_fused<<<Nq / 8, 256>>>(xt, sn, gates, pre_o, am_o, rw);

    // sparse MoE: up-proj gathers active tokens per expert, down-proj scatters
    k_gemm_mma<<<dim3(Fq / 128, Nq / 128, Eq), 256, MM_SMEM>>>(
        xhi, xlo, w1h, w1l, hh, hl, nullptr, nullptr, tok, cnt,
        Cq, Cq, Fq, 0, 0, 0);
    k_gemm_mma<<<dim3(Cq / 128, Nq / 128, Eq), 256, MM_SMEM>>>(
        hh, hl, w2h, w2l, nullptr, nullptr, feo, nullptr, tok, cnt,
        Fq, Fq, Cq, 0, Nq * Fq, 1);

    // combine + zero inactive feo + split for lm_head input
    k_combine_zero<<<Nq, Cq>>>(rw, am_o, feo, hs, ahi, alo);

    // lm_head
    k_lmhead_mma<<<VP / 128, 256, LM_SMEM>>>(ahi, alo, bhi, blo, out);
}